// round 1
// baseline (speedup 1.0000x reference)
#include <cuda_runtime.h>
#include <math.h>

// ---------------- constants ----------------
constexpr int Bc = 2, Tc = 8, Hc = 20, Wc = 36, Cch = 512, NHc = 4, HDc = 128;
constexpr int NWHc = 4, NWWc = 4;
constexpr int NWIN = 32;          // B*NWH*NWW
constexpr int NQ = 360;           // T * 45
constexpr int NROLLK = 960;       // T * 120
constexpr int NPOOLK = 360;       // T * 45
constexpr int NK = 1680;          // 360 + 960 + 360
constexpr int TOK = 11520;        // B*T*H*W
constexpr int FFN = 1960;
constexpr float QSCALE = 0.08838834764831845f; // 128^-0.5

// ---------------- scratch (device globals; no allocs) ----------------
__device__ float g_xn[TOK * Cch];            // LN1 out, reused as LN2 out
__device__ float g_qkv[TOK * 3 * Cch];
__device__ float g_pooled[256 * Cch];
__device__ float g_qkvp[256 * 3 * Cch];
__device__ float g_Q[NWIN * NQ * Cch];
__device__ float g_K[NWIN * NK * Cch];
__device__ float g_V[NWIN * NK * Cch];
__device__ float g_S[NWIN * NHc * NQ * NK];  // scores; later reused as h2 (22.6M <= 77.4M)
__device__ float g_Aw[TOK * Cch];            // attention out, window order
__device__ float g_Pw[TOK * Cch];            // proj out, window order
__device__ float g_xres[TOK * Cch];
__device__ float g_h1[TOK * FFN];
__device__ float g_I[16 * 40 * 60 * 108];
__device__ int   g_valid[120];

// ---------------- init valid-rolled table ----------------
__global__ void initvalid_k() {
    if (threadIdx.x == 0 && blockIdx.x == 0) {
        int n = 0;
        for (int s = 0; s < 4; s++)
            for (int ih = 0; ih < 5; ih++)
                for (int iw = 0; iw < 9; iw++) {
                    bool zero;
                    if (s == 0) zero = (ih < 3 && iw < 5);
                    else if (s == 1) zero = (ih < 3 && iw >= 4);
                    else if (s == 2) zero = (ih >= 2 && iw < 5);
                    else zero = (ih >= 2 && iw >= 4);
                    if (!zero) g_valid[n++] = s * 45 + ih * 9 + iw;
                }
    }
}

// ---------------- LayerNorm: one block per token (128 threads x float4) ----------------
__global__ __launch_bounds__(128) void ln_k(const float* __restrict__ in,
                                            const float* __restrict__ g,
                                            const float* __restrict__ b,
                                            float* __restrict__ out) {
    int row = blockIdx.x;
    const float4* xp = (const float4*)(in + (long long)row * 512);
    float4 v = xp[threadIdx.x];
    float s = v.x + v.y + v.z + v.w;
    __shared__ float red[4], red2[4];
    #pragma unroll
    for (int o = 16; o; o >>= 1) s += __shfl_xor_sync(0xffffffffu, s, o);
    int wid = threadIdx.x >> 5, lane = threadIdx.x & 31;
    if (lane == 0) red[wid] = s;
    __syncthreads();
    float mu = (red[0] + red[1] + red[2] + red[3]) * (1.f / 512.f);
    float dx = v.x - mu, dy = v.y - mu, dz = v.z - mu, dw = v.w - mu;
    float sq = dx * dx + dy * dy + dz * dz + dw * dw;
    #pragma unroll
    for (int o = 16; o; o >>= 1) sq += __shfl_xor_sync(0xffffffffu, sq, o);
    if (lane == 0) red2[wid] = sq;
    __syncthreads();
    float var = (red2[0] + red2[1] + red2[2] + red2[3]) * (1.f / 512.f);
    float inv = rsqrtf(var + 1e-5f);
    float4 gg = ((const float4*)g)[threadIdx.x];
    float4 bb = ((const float4*)b)[threadIdx.x];
    float4 o4;
    o4.x = dx * inv * gg.x + bb.x;
    o4.y = dy * inv * gg.y + bb.y;
    o4.z = dz * inv * gg.z + bb.z;
    o4.w = dw * inv * gg.w + bb.w;
    ((float4*)(out + (long long)row * 512))[threadIdx.x] = o4;
}

// ---------------- window pooling: block = (b*T+t, wh, ww) ----------------
__global__ __launch_bounds__(128) void pool_k(const float* __restrict__ xn,
                                              const float* __restrict__ wpool,
                                              const float* __restrict__ bpool,
                                              float* __restrict__ pooled) {
    int blk = blockIdx.x;                 // bt*16 + wh*4 + ww
    int ww = blk & 3, wh = (blk >> 2) & 3, bt = blk >> 4;
    float bp = bpool[0];
    for (int c = threadIdx.x; c < 512; c += 128) {
        float s = 0.f;
        #pragma unroll
        for (int a = 0; a < 45; a++) {
            int ih = a / 9, iw = a % 9;
            long long tok = ((long long)bt * 20 + wh * 5 + ih) * 36 + ww * 9 + iw;
            s += xn[tok * 512 + c] * wpool[a];
        }
        pooled[(long long)blk * 512 + c] = s + bp;
    }
}

// ---------------- gather Q (scaled) ----------------
__global__ __launch_bounds__(128) void gatherq_k(const float* __restrict__ qkv,
                                                 float* __restrict__ Q) {
    int r = blockIdx.x;                   // 0..11519 : win*360 + q
    int win = r / 360, q = r - win * 360;
    int b = win >> 4, wh = (win >> 2) & 3, ww = win & 3;
    int t = q / 45, a = q - t * 45, ih = a / 9, iw = a % 9;
    long long tok = ((long long)(b * 8 + t) * 20 + wh * 5 + ih) * 36 + ww * 9 + iw;
    const float4* src = (const float4*)(qkv + tok * 1536);
    float4* dst = (float4*)(Q + (long long)r * 512);
    float4 v = src[threadIdx.x];
    v.x *= QSCALE; v.y *= QSCALE; v.z *= QSCALE; v.w *= QSCALE;
    dst[threadIdx.x] = v;
}

// ---------------- gather K/V (window + rolled + pooled-unfold) ----------------
__global__ __launch_bounds__(128) void gatherkv_k(const float* __restrict__ qkv,
                                                  const float* __restrict__ qkvp,
                                                  float* __restrict__ Kall,
                                                  float* __restrict__ Vall) {
    int r = blockIdx.x;                   // 0..32*1680-1
    int win = r / 1680, j = r - win * 1680;
    int b = win >> 4, wh = (win >> 2) & 3, ww = win & 3;
    const float* pK = nullptr;
    const float* pV = nullptr;
    if (j < 360) {
        int t = j / 45, a = j - t * 45, ih = a / 9, iw = a % 9;
        long long tok = ((long long)(b * 8 + t) * 20 + wh * 5 + ih) * 36 + ww * 9 + iw;
        pK = qkv + tok * 1536 + 512;
        pV = qkv + tok * 1536 + 1024;
    } else if (j < 1320) {
        int jj = j - 360;
        int t = jj / 120, vi = jj - t * 120;
        int f = g_valid[vi];
        int s = f / 45, a = f - s * 45, ih = a / 9, iw = a % 9;
        int sh = (s < 2) ? -2 : 2;
        int sw = (s & 1) ? 4 : -4;
        int hh = wh * 5 + ih - sh; hh %= 20; if (hh < 0) hh += 20;
        int wp = ww * 9 + iw - sw; wp %= 36; if (wp < 0) wp += 36;
        long long tok = ((long long)(b * 8 + t) * 20 + hh) * 36 + wp;
        pK = qkv + tok * 1536 + 512;
        pV = qkv + tok * 1536 + 1024;
    } else {
        int jj = j - 1320;
        int t = jj / 45, a = jj - t * 45, i = a / 9, jx = a % 9;
        int gi = wh + i - 2, gj = ww + jx - 4;
        if (gi >= 0 && gi < 4 && gj >= 0 && gj < 4) {
            long long ptok = (long long)(b * 8 + t) * 16 + gi * 4 + gj;
            pK = qkvp + ptok * 1536 + 512;
            pV = qkvp + ptok * 1536 + 1024;
        }
    }
    int c = threadIdx.x;
    float4 vk = pK ? ((const float4*)pK)[c] : make_float4(0.f, 0.f, 0.f, 0.f);
    float4 vv = pV ? ((const float4*)pV)[c] : make_float4(0.f, 0.f, 0.f, 0.f);
    ((float4*)(Kall + (long long)r * 512))[c] = vk;
    ((float4*)(Vall + (long long)r * 512))[c] = vv;
}

// ---------------- generic tiled fp32 GEMM: C = A*B (+bias)(+res) ----------------
template <bool TRANSB>
__global__ __launch_bounds__(256) void gemm_k(
    const float* __restrict__ A, const float* __restrict__ Bm,
    const float* __restrict__ bias, const float* __restrict__ res,
    float* __restrict__ Cm,
    int M, int N, int K, int lda, int ldb, int ldc,
    long long sAo, long long sAi, long long sBo, long long sBi,
    long long sCo, long long sCi, int inner) {
    int z = blockIdx.z;
    int zo = z / inner, zi = z - zo * inner;
    A += zo * sAo + zi * sAi;
    Bm += zo * sBo + zi * sBi;
    long long coff = zo * sCo + zi * sCi;
    Cm += coff;
    if (res) res += coff;

    __shared__ float As[16][64];
    __shared__ float Bs[16][64];
    int tid = threadIdx.x;
    int row0 = blockIdx.y * 64, col0 = blockIdx.x * 64;
    int ty = tid >> 4, tx = tid & 15;
    float acc[4][4];
    #pragma unroll
    for (int i = 0; i < 4; i++)
        #pragma unroll
        for (int j = 0; j < 4; j++) acc[i][j] = 0.f;

    for (int k0 = 0; k0 < K; k0 += 16) {
        #pragma unroll
        for (int i = 0; i < 4; i++) {
            int li = tid + i * 256;
            int kk = li & 15, m = li >> 4;
            int gr = row0 + m, gk = k0 + kk;
            As[kk][m] = (gr < M && gk < K) ? A[(long long)gr * lda + gk] : 0.f;
        }
        #pragma unroll
        for (int i = 0; i < 4; i++) {
            int li = tid + i * 256;
            int kk, n;
            if (TRANSB) { kk = li & 15; n = li >> 4; }
            else        { n = li & 63;  kk = li >> 6; }
            int gn = col0 + n, gk = k0 + kk;
            float v = 0.f;
            if (gn < N && gk < K)
                v = TRANSB ? Bm[(long long)gn * ldb + gk] : Bm[(long long)gk * ldb + gn];
            Bs[kk][n] = v;
        }
        __syncthreads();
        #pragma unroll
        for (int kk = 0; kk < 16; kk++) {
            float4 a4 = *(const float4*)&As[kk][ty * 4];
            float4 b4 = *(const float4*)&Bs[kk][tx * 4];
            float av[4] = {a4.x, a4.y, a4.z, a4.w};
            float bv[4] = {b4.x, b4.y, b4.z, b4.w};
            #pragma unroll
            for (int i = 0; i < 4; i++)
                #pragma unroll
                for (int j = 0; j < 4; j++) acc[i][j] += av[i] * bv[j];
        }
        __syncthreads();
    }
    #pragma unroll
    for (int i = 0; i < 4; i++) {
        int gr = row0 + ty * 4 + i;
        if (gr >= M) continue;
        #pragma unroll
        for (int j = 0; j < 4; j++) {
            int gn = col0 + tx * 4 + j;
            if (gn >= N) continue;
            float v = acc[i][j];
            if (bias) v += bias[gn];
            long long ci = (long long)gr * ldc + gn;
            if (res) v += res[ci];
            Cm[ci] = v;
        }
    }
}

// ---------------- softmax with inline pooled-key mask ----------------
__global__ __launch_bounds__(256) void softmax_k(float* __restrict__ S) {
    int row = blockIdx.x;                 // 0..46079 = win*1440 + head*360 + q
    int win = row / 1440;
    int l = win & 15, wh = l >> 2, ww = l & 3;
    float* p = S + (long long)row * 1680;
    float vals[7];
    float mx = -1e30f;
    #pragma unroll
    for (int i = 0; i < 7; i++) {
        int j = threadIdx.x + i * 256;
        float v = -1e30f;
        if (j < 1680) {
            v = p[j];
            if (j >= 1320) {
                int jj = j - 1320;
                int a = jj % 45;
                int ii = a / 9, jx = a % 9;
                int gi = wh + ii - 2, gj = ww + jx - 4;
                if (gi < 0 || gi >= 4 || gj < 0 || gj >= 4) v -= 100.f;
            }
        }
        vals[i] = v;
        mx = fmaxf(mx, v);
    }
    __shared__ float red[8], red2[8];
    #pragma unroll
    for (int o = 16; o; o >>= 1) mx = fmaxf(mx, __shfl_xor_sync(0xffffffffu, mx, o));
    int wid = threadIdx.x >> 5, lane = threadIdx.x & 31;
    if (lane == 0) red[wid] = mx;
    __syncthreads();
    mx = fmaxf(fmaxf(fmaxf(red[0], red[1]), fmaxf(red[2], red[3])),
               fmaxf(fmaxf(red[4], red[5]), fmaxf(red[6], red[7])));
    float sum = 0.f;
    #pragma unroll
    for (int i = 0; i < 7; i++) {
        int j = threadIdx.x + i * 256;
        if (j < 1680) { vals[i] = expf(vals[i] - mx); sum += vals[i]; }
        else vals[i] = 0.f;
    }
    #pragma unroll
    for (int o = 16; o; o >>= 1) sum += __shfl_xor_sync(0xffffffffu, sum, o);
    if (lane == 0) red2[wid] = sum;
    __syncthreads();
    sum = red2[0] + red2[1] + red2[2] + red2[3] + red2[4] + red2[5] + red2[6] + red2[7];
    float inv = 1.f / sum;
    #pragma unroll
    for (int i = 0; i < 7; i++) {
        int j = threadIdx.x + i * 256;
        if (j < 1680) p[j] = vals[i] * inv;
    }
}

// ---------------- scatter window->spatial + residual ----------------
__global__ __launch_bounds__(256) void addres_k(const float* __restrict__ x,
                                                const float* __restrict__ Pw,
                                                float* __restrict__ xres) {
    int idx = blockIdx.x * 256 + threadIdx.x;     // over TOK*128 float4s
    int n = idx >> 7, c4 = idx & 127;
    int w = n % 36;
    int h = (n / 36) % 20;
    int bt = n / 720;
    int b = bt >> 3, t = bt & 7;
    int wh = h / 5, ih = h - wh * 5, ww = w / 9, iw = w - ww * 9;
    int win = b * 16 + wh * 4 + ww;
    int q = t * 45 + ih * 9 + iw;
    long long r = (long long)win * 360 + q;
    float4 xv = ((const float4*)x)[idx];
    float4 pv = ((const float4*)Pw)[r * 128 + c4];
    xv.x += pv.x; xv.y += pv.y; xv.z += pv.z; xv.w += pv.w;
    ((float4*)xres)[idx] = xv;
}

// ---------------- T2T fold (gather form) + normalize ----------------
__global__ __launch_bounds__(256) void t2tfold_k(const float* __restrict__ h1,
                                                 float* __restrict__ I) {
    int idx = blockIdx.x * 256 + threadIdx.x;
    if (idx >= 16 * 40 * 60 * 108) return;
    int x = idx % 108;
    int y = (idx / 108) % 60;
    int c40 = (idx / (108 * 60)) % 40;
    int g = idx / (108 * 60 * 40);
    int pys[3], kis[3], pxs[3], kjs[3];
    int cy = 0, cx = 0;
    #pragma unroll
    for (int dp = 0; dp < 3; dp++) {
        int py = (y + 3) / 3 - dp;
        int ki = y + 3 - 3 * py;
        if (py >= 0 && py < 20 && ki < 7) { pys[cy] = py; kis[cy] = ki; cy++; }
        int px = (x + 3) / 3 - dp;
        int kj = x + 3 - 3 * px;
        if (px >= 0 && px < 36 && kj < 7) { pxs[cx] = px; kjs[cx] = kj; cx++; }
    }
    float s = 0.f;
    for (int a = 0; a < cy; a++)
        for (int bb = 0; bb < cx; bb++) {
            long long r = (long long)g * 720 + pys[a] * 36 + pxs[bb];
            s += h1[r * 1960 + c40 * 49 + kis[a] * 7 + kjs[bb]];
        }
    I[idx] = s / (float)(cy * cx);
}

// ---------------- T2T unfold + exact GELU ----------------
__global__ __launch_bounds__(256) void t2tunf_k(const float* __restrict__ I,
                                                float* __restrict__ h2) {
    int idx = blockIdx.x * 256 + threadIdx.x;
    if (idx >= TOK * FFN) return;
    int c = idx % 1960;
    int r = idx / 1960;
    int g = r / 720;
    int p = r - g * 720;
    int py = p / 36, px = p - py * 36;
    int c40 = c / 49;
    int kk = c - c40 * 49;
    int ki = kk / 7, kj = kk - ki * 7;
    int y = py * 3 + ki - 3, x = px * 3 + kj - 3;
    float v = 0.f;
    if (y >= 0 && y < 60 && x >= 0 && x < 108)
        v = I[(((long long)g * 40 + c40) * 60 + y) * 108 + x];
    h2[idx] = 0.5f * v * (1.f + erff(v * 0.7071067811865475f));
}

// ---------------- host launch ----------------
#define SYM(p, s) do { void* _t = nullptr; cudaGetSymbolAddress(&_t, s); (p) = (float*)_t; } while (0)

static void run_gemm(bool transB, const float* A, const float* Bm, const float* bias,
                     const float* res, float* C, int M, int N, int K,
                     int lda, int ldb, int ldc,
                     long long sAo, long long sAi, long long sBo, long long sBi,
                     long long sCo, long long sCi, int inner, int batch) {
    dim3 grid((N + 63) / 64, (M + 63) / 64, batch);
    if (transB)
        gemm_k<true><<<grid, 256>>>(A, Bm, bias, res, C, M, N, K, lda, ldb, ldc,
                                    sAo, sAi, sBo, sBi, sCo, sCi, inner);
    else
        gemm_k<false><<<grid, 256>>>(A, Bm, bias, res, C, M, N, K, lda, ldb, ldc,
                                     sAo, sAi, sBo, sBi, sCo, sCi, inner);
}

extern "C" void kernel_launch(void* const* d_in, const int* in_sizes, int n_in,
                              void* d_out, int out_size) {
    const float* x     = (const float*)d_in[0];
    const float* g1    = (const float*)d_in[1];
    const float* be1   = (const float*)d_in[2];
    const float* wqkv  = (const float*)d_in[3];
    const float* bqkv  = (const float*)d_in[4];
    const float* wproj = (const float*)d_in[5];
    const float* bproj = (const float*)d_in[6];
    const float* wpool = (const float*)d_in[7];
    const float* bpool = (const float*)d_in[8];
    const float* g2    = (const float*)d_in[9];
    const float* be2   = (const float*)d_in[10];
    const float* w1    = (const float*)d_in[11];
    const float* bf1   = (const float*)d_in[12];
    const float* w2    = (const float*)d_in[13];
    const float* bf2   = (const float*)d_in[14];
    float* out = (float*)d_out;

    float *xn, *qkv, *pooled, *qkvp, *Q, *K, *V, *S, *Aw, *Pw, *xres, *h1, *I;
    SYM(xn, g_xn); SYM(qkv, g_qkv); SYM(pooled, g_pooled); SYM(qkvp, g_qkvp);
    SYM(Q, g_Q); SYM(K, g_K); SYM(V, g_V); SYM(S, g_S); SYM(Aw, g_Aw);
    SYM(Pw, g_Pw); SYM(xres, g_xres); SYM(h1, g_h1); SYM(I, g_I);
    float* h2 = S;  // reuse scores buffer

    initvalid_k<<<1, 32>>>();
    ln_k<<<TOK, 128>>>(x, g1, be1, xn);
    // QKV GEMM
    run_gemm(false, xn, wqkv, bqkv, nullptr, qkv, TOK, 1536, 512, 512, 1536, 1536,
             0, 0, 0, 0, 0, 0, 1, 1);
    pool_k<<<256, 128>>>(xn, wpool, bpool, pooled);
    // pooled QKV GEMM
    run_gemm(false, pooled, wqkv, bqkv, nullptr, qkvp, 256, 1536, 512, 512, 1536, 1536,
             0, 0, 0, 0, 0, 0, 1, 1);
    gatherq_k<<<TOK, 128>>>(qkv, Q);
    gatherkv_k<<<NWIN * NK, 128>>>(qkv, qkvp, K, V);
    // scores: per (win, head): Q(360x128) @ K^T(1680x128)
    run_gemm(true, Q, K, nullptr, nullptr, S, NQ, NK, HDc, 512, 512, NK,
             (long long)NQ * 512, 128, (long long)NK * 512, 128,
             (long long)NHc * NQ * NK, (long long)NQ * NK, NHc, NWIN * NHc);
    softmax_k<<<NWIN * NHc * NQ, 256>>>(S);
    // out: per (win, head): P(360x1680) @ V(1680x128)
    run_gemm(false, S, V, nullptr, nullptr, Aw, NQ, HDc, NK, NK, 512, 512,
             (long long)NHc * NQ * NK, (long long)NQ * NK,
             (long long)NK * 512, 128,
             (long long)NQ * 512, 128, NHc, NWIN * NHc);
    // proj
    run_gemm(false, Aw, wproj, bproj, nullptr, Pw, TOK, 512, 512, 512, 512, 512,
             0, 0, 0, 0, 0, 0, 1, 1);
    addres_k<<<TOK * 128 / 256, 256>>>(x, Pw, xres);
    ln_k<<<TOK, 128>>>(xres, g2, be2, xn);
    // FFN1
    run_gemm(false, xn, w1, bf1, nullptr, h1, TOK, FFN, 512, 512, FFN, FFN,
             0, 0, 0, 0, 0, 0, 1, 1);
    t2tfold_k<<<(16 * 40 * 60 * 108 + 255) / 256, 256>>>(h1, I);
    t2tunf_k<<<(TOK * FFN + 255) / 256, 256>>>(I, h2);
    // FFN2 + residual -> out
    run_gemm(false, h2, w2, bf2, xres, out, TOK, 512, FFN, FFN, 512, 512,
             0, 0, 0, 0, 0, 0, 1, 1);
}

// round 3
// speedup vs baseline: 3.7160x; 3.7160x over previous
#include <cuda_runtime.h>
#include <math.h>
#include <stdint.h>

// ---------------- constants ----------------
constexpr int NWIN = 32;          // B*NWH*NWW
constexpr int NQ = 360;           // T * 45
constexpr int NK = 1680;          // 360 + 960 + 360
constexpr int TOK = 11520;        // B*T*H*W
constexpr int FFN = 1960;
constexpr int Cch = 512, NHc = 4, HDc = 128;
constexpr float QSCALE = 0.08838834764831845f; // 128^-0.5

// ---------------- scratch (device globals; no allocs) ----------------
__device__ float g_xn[TOK * Cch];
__device__ float g_qkv[TOK * 3 * Cch];
__device__ float g_pooled[256 * Cch];
__device__ float g_qkvp[256 * 3 * Cch];
__device__ float g_Q[NWIN * NQ * Cch];
__device__ float g_K[NWIN * NK * Cch];
__device__ float g_V[NWIN * NK * Cch];
__device__ float g_S[NWIN * NHc * NQ * NK];  // scores; later reused as h2
__device__ float g_Aw[TOK * Cch];
__device__ float g_Pw[TOK * Cch];
__device__ float g_xres[TOK * Cch];
__device__ float g_h1[TOK * FFN];
__device__ float g_I[16 * 40 * 60 * 108];
__device__ int   g_valid[120];

// ---------------- init valid-rolled table ----------------
__global__ void initvalid_k() {
    if (threadIdx.x == 0 && blockIdx.x == 0) {
        int n = 0;
        for (int s = 0; s < 4; s++)
            for (int ih = 0; ih < 5; ih++)
                for (int iw = 0; iw < 9; iw++) {
                    bool zero;
                    if (s == 0) zero = (ih < 3 && iw < 5);
                    else if (s == 1) zero = (ih < 3 && iw >= 4);
                    else if (s == 2) zero = (ih >= 2 && iw < 5);
                    else zero = (ih >= 2 && iw >= 4);
                    if (!zero) g_valid[n++] = s * 45 + ih * 9 + iw;
                }
    }
}

// ---------------- LayerNorm ----------------
__global__ __launch_bounds__(128) void ln_k(const float* __restrict__ in,
                                            const float* __restrict__ g,
                                            const float* __restrict__ b,
                                            float* __restrict__ out) {
    int row = blockIdx.x;
    const float4* xp = (const float4*)(in + (long long)row * 512);
    float4 v = xp[threadIdx.x];
    float s = v.x + v.y + v.z + v.w;
    __shared__ float red[4], red2[4];
    #pragma unroll
    for (int o = 16; o; o >>= 1) s += __shfl_xor_sync(0xffffffffu, s, o);
    int wid = threadIdx.x >> 5, lane = threadIdx.x & 31;
    if (lane == 0) red[wid] = s;
    __syncthreads();
    float mu = (red[0] + red[1] + red[2] + red[3]) * (1.f / 512.f);
    float dx = v.x - mu, dy = v.y - mu, dz = v.z - mu, dw = v.w - mu;
    float sq = dx * dx + dy * dy + dz * dz + dw * dw;
    #pragma unroll
    for (int o = 16; o; o >>= 1) sq += __shfl_xor_sync(0xffffffffu, sq, o);
    if (lane == 0) red2[wid] = sq;
    __syncthreads();
    float var = (red2[0] + red2[1] + red2[2] + red2[3]) * (1.f / 512.f);
    float inv = rsqrtf(var + 1e-5f);
    float4 gg = ((const float4*)g)[threadIdx.x];
    float4 bb = ((const float4*)b)[threadIdx.x];
    float4 o4;
    o4.x = dx * inv * gg.x + bb.x;
    o4.y = dy * inv * gg.y + bb.y;
    o4.z = dz * inv * gg.z + bb.z;
    o4.w = dw * inv * gg.w + bb.w;
    ((float4*)(out + (long long)row * 512))[threadIdx.x] = o4;
}

// ---------------- window pooling ----------------
__global__ __launch_bounds__(128) void pool_k(const float* __restrict__ xn,
                                              const float* __restrict__ wpool,
                                              const float* __restrict__ bpool,
                                              float* __restrict__ pooled) {
    int blk = blockIdx.x;
    int ww = blk & 3, wh = (blk >> 2) & 3, bt = blk >> 4;
    float bp = bpool[0];
    for (int c = threadIdx.x; c < 512; c += 128) {
        float s = 0.f;
        #pragma unroll
        for (int a = 0; a < 45; a++) {
            int ih = a / 9, iw = a % 9;
            long long tok = ((long long)bt * 20 + wh * 5 + ih) * 36 + ww * 9 + iw;
            s += xn[tok * 512 + c] * wpool[a];
        }
        pooled[(long long)blk * 512 + c] = s + bp;
    }
}

// ---------------- gather Q (scaled) ----------------
__global__ __launch_bounds__(128) void gatherq_k(const float* __restrict__ qkv,
                                                 float* __restrict__ Q) {
    int r = blockIdx.x;
    int win = r / 360, q = r - win * 360;
    int b = win >> 4, wh = (win >> 2) & 3, ww = win & 3;
    int t = q / 45, a = q - t * 45, ih = a / 9, iw = a % 9;
    long long tok = ((long long)(b * 8 + t) * 20 + wh * 5 + ih) * 36 + ww * 9 + iw;
    const float4* src = (const float4*)(qkv + tok * 1536);
    float4* dst = (float4*)(Q + (long long)r * 512);
    float4 v = src[threadIdx.x];
    v.x *= QSCALE; v.y *= QSCALE; v.z *= QSCALE; v.w *= QSCALE;
    dst[threadIdx.x] = v;
}

// ---------------- gather K/V ----------------
__global__ __launch_bounds__(128) void gatherkv_k(const float* __restrict__ qkv,
                                                  const float* __restrict__ qkvp,
                                                  float* __restrict__ Kall,
                                                  float* __restrict__ Vall) {
    int r = blockIdx.x;
    int win = r / 1680, j = r - win * 1680;
    int b = win >> 4, wh = (win >> 2) & 3, ww = win & 3;
    const float* pK = nullptr;
    const float* pV = nullptr;
    if (j < 360) {
        int t = j / 45, a = j - t * 45, ih = a / 9, iw = a % 9;
        long long tok = ((long long)(b * 8 + t) * 20 + wh * 5 + ih) * 36 + ww * 9 + iw;
        pK = qkv + tok * 1536 + 512;
        pV = qkv + tok * 1536 + 1024;
    } else if (j < 1320) {
        int jj = j - 360;
        int t = jj / 120, vi = jj - t * 120;
        int f = g_valid[vi];
        int s = f / 45, a = f - s * 45, ih = a / 9, iw = a % 9;
        int sh = (s < 2) ? -2 : 2;
        int sw = (s & 1) ? 4 : -4;
        int hh = wh * 5 + ih - sh; hh %= 20; if (hh < 0) hh += 20;
        int wp = ww * 9 + iw - sw; wp %= 36; if (wp < 0) wp += 36;
        long long tok = ((long long)(b * 8 + t) * 20 + hh) * 36 + wp;
        pK = qkv + tok * 1536 + 512;
        pV = qkv + tok * 1536 + 1024;
    } else {
        int jj = j - 1320;
        int t = jj / 45, a = jj - t * 45, i = a / 9, jx = a % 9;
        int gi = wh + i - 2, gj = ww + jx - 4;
        if (gi >= 0 && gi < 4 && gj >= 0 && gj < 4) {
            long long ptok = (long long)(b * 8 + t) * 16 + gi * 4 + gj;
            pK = qkvp + ptok * 1536 + 512;
            pV = qkvp + ptok * 1536 + 1024;
        }
    }
    int c = threadIdx.x;
    float4 vk = pK ? ((const float4*)pK)[c] : make_float4(0.f, 0.f, 0.f, 0.f);
    float4 vv = pV ? ((const float4*)pV)[c] : make_float4(0.f, 0.f, 0.f, 0.f);
    ((float4*)(Kall + (long long)r * 512))[c] = vk;
    ((float4*)(Vall + (long long)r * 512))[c] = vv;
}

// ---------------- tf32 tensor-core GEMM ----------------
__device__ __forceinline__ uint32_t f2tf(float x) {
    uint32_t r;
    asm("cvt.rna.tf32.f32 %0, %1;" : "=r"(r) : "f"(x));
    return r;
}
__device__ __forceinline__ void cpasync16(uint32_t saddr, const void* gaddr, bool pred) {
    int sz = pred ? 16 : 0;
    asm volatile("cp.async.cg.shared.global [%0], [%1], 16, %2;\n"
                 :: "r"(saddr), "l"(gaddr), "r"(sz));
}

// BM=128, BN=64, BK=32, 256 threads, warp grid 4(M) x 2(N), warp tile 32x32
template <bool TRANSB>
__global__ __launch_bounds__(256) void tgemm_k(
    const float* __restrict__ A, const float* __restrict__ Bm,
    const float* __restrict__ bias, const float* __restrict__ res,
    float* __restrict__ Cm,
    int M, int N, int K, int lda, int ldb, int ldc,
    long long sAo, long long sAi, long long sBo, long long sBi,
    long long sCo, long long sCi, int inner) {
    constexpr int BM = 128, BN = 64, BK = 32;
    constexpr int AST = BK + 4;                    // 36 floats/row
    constexpr int BST = TRANSB ? (BK + 4) : (BN + 4); // 36 or 68
    constexpr int ASTAGE = BM * AST;               // floats
    constexpr int BSTAGE = TRANSB ? (BN * BST) : (BK * BST);

    extern __shared__ float smem[];
    float* As = smem;                 // [2][ASTAGE]
    float* Bs = smem + 2 * ASTAGE;    // [2][BSTAGE]

    int z = blockIdx.z;
    int zo = z / inner, zi = z - zo * inner;
    A += zo * sAo + zi * sAi;
    Bm += zo * sBo + zi * sBi;
    long long coff = zo * sCo + zi * sCi;
    Cm += coff;
    if (res) res += coff;

    int tid = threadIdx.x;
    int row0 = blockIdx.y * BM, col0 = blockIdx.x * BN;
    int wid = tid >> 5, lane = tid & 31;
    int wm = wid & 3, wn = wid >> 2;
    int g = lane >> 2, t = lane & 3;

    uint32_t sA0 = (uint32_t)__cvta_generic_to_shared(As);
    uint32_t sB0 = (uint32_t)__cvta_generic_to_shared(Bs);

    int ktiles = (K + BK - 1) / BK;

    auto load_tile = [&](int stage, int k0) {
        // A tile: 128 x 32 -> 1024 float4s; idx = tid + i*256
        #pragma unroll
        for (int i = 0; i < 4; i++) {
            int idx = tid + i * 256;
            int r = idx >> 3, kc = (idx & 7) << 2;
            int gr = row0 + r, gk = k0 + kc;
            bool ok = (gr < M) && (gk < K);
            uint32_t sa = sA0 + (uint32_t)((stage * ASTAGE + r * AST + kc) * 4);
            cpasync16(sa, A + (long long)gr * lda + gk, ok);
        }
        if (TRANSB) {
            // B tile: 64 n-rows x 32 k -> 512 float4s; idx = tid + i*256
            #pragma unroll
            for (int i = 0; i < 2; i++) {
                int idx = tid + i * 256;
                int n = idx >> 3, kc = (idx & 7) << 2;
                int gn = col0 + n, gk = k0 + kc;
                bool ok = (gn < N) && (gk < K);
                uint32_t sb = sB0 + (uint32_t)((stage * BSTAGE + n * BST + kc) * 4);
                cpasync16(sb, Bm + (long long)gn * ldb + gk, ok);
            }
        } else {
            // B tile: 32 k-rows x 64 n
            #pragma unroll
            for (int i = 0; i < 2; i++) {
                int idx = tid + i * 256;
                int kk = idx >> 4, nc = (idx & 15) << 2;
                int gk = k0 + kk, gn = col0 + nc;
                bool ok = (gk < K) && (gn < N);
                uint32_t sb = sB0 + (uint32_t)((stage * BSTAGE + kk * BST + nc) * 4);
                cpasync16(sb, Bm + (long long)gk * ldb + gn, ok);
            }
        }
    };

    float acc[2][4][4];
    #pragma unroll
    for (int mi = 0; mi < 2; mi++)
        #pragma unroll
        for (int ni = 0; ni < 4; ni++)
            #pragma unroll
            for (int q = 0; q < 4; q++) acc[mi][ni][q] = 0.f;

    load_tile(0, 0);
    asm volatile("cp.async.commit_group;\n");

    for (int kt = 0; kt < ktiles; kt++) {
        if (kt + 1 < ktiles) load_tile((kt + 1) & 1, (kt + 1) * BK);
        asm volatile("cp.async.commit_group;\n");
        asm volatile("cp.async.wait_group %0;\n" :: "n"(1));
        __syncthreads();

        const float* Asb = As + (kt & 1) * ASTAGE;
        const float* Bsb = Bs + (kt & 1) * BSTAGE;

        #pragma unroll
        for (int ks = 0; ks < 4; ks++) {
            int kk = ks * 8 + t;
            uint32_t af[2][4], bf[4][2];
            #pragma unroll
            for (int mi = 0; mi < 2; mi++) {
                const float* ap = Asb + (wm * 32 + mi * 16 + g) * AST + kk;
                af[mi][0] = f2tf(ap[0]);
                af[mi][1] = f2tf(ap[8 * AST]);
                af[mi][2] = f2tf(ap[4]);
                af[mi][3] = f2tf(ap[8 * AST + 4]);
            }
            #pragma unroll
            for (int ni = 0; ni < 4; ni++) {
                int c = wn * 32 + ni * 8 + g;
                if (TRANSB) {
                    const float* bp = Bsb + c * BST + kk;
                    bf[ni][0] = f2tf(bp[0]);
                    bf[ni][1] = f2tf(bp[4]);
                } else {
                    const float* bp = Bsb + kk * BST + c;
                    bf[ni][0] = f2tf(bp[0]);
                    bf[ni][1] = f2tf(bp[4 * BST]);
                }
            }
            #pragma unroll
            for (int mi = 0; mi < 2; mi++)
                #pragma unroll
                for (int ni = 0; ni < 4; ni++) {
                    asm volatile(
                        "mma.sync.aligned.m16n8k8.row.col.f32.tf32.tf32.f32 "
                        "{%0,%1,%2,%3}, {%4,%5,%6,%7}, {%8,%9}, {%0,%1,%2,%3};\n"
                        : "+f"(acc[mi][ni][0]), "+f"(acc[mi][ni][1]),
                          "+f"(acc[mi][ni][2]), "+f"(acc[mi][ni][3])
                        : "r"(af[mi][0]), "r"(af[mi][1]), "r"(af[mi][2]), "r"(af[mi][3]),
                          "r"(bf[ni][0]), "r"(bf[ni][1]));
                }
        }
        __syncthreads();
    }

    // epilogue
    #pragma unroll
    for (int mi = 0; mi < 2; mi++) {
        int r = row0 + wm * 32 + mi * 16 + g;
        #pragma unroll
        for (int ni = 0; ni < 4; ni++) {
            int c = col0 + wn * 32 + ni * 8 + 2 * t;
            #pragma unroll
            for (int q = 0; q < 4; q++) {
                int rr = r + (q >> 1) * 8;
                int cc = c + (q & 1);
                if (rr < M && cc < N) {
                    float v = acc[mi][ni][q];
                    if (bias) v += bias[cc];
                    long long ci = (long long)rr * ldc + cc;
                    if (res) v += res[ci];
                    Cm[ci] = v;
                }
            }
        }
    }
}

// ---------------- softmax with inline pooled-key mask ----------------
__global__ __launch_bounds__(256) void softmax_k(float* __restrict__ S) {
    int row = blockIdx.x;
    int win = row / 1440;
    int l = win & 15, wh = l >> 2, ww = l & 3;
    float* p = S + (long long)row * 1680;
    float vals[7];
    float mx = -1e30f;
    #pragma unroll
    for (int i = 0; i < 7; i++) {
        int j = threadIdx.x + i * 256;
        float v = -1e30f;
        if (j < 1680) {
            v = p[j];
            if (j >= 1320) {
                int jj = j - 1320;
                int a = jj % 45;
                int ii = a / 9, jx = a % 9;
                int gi = wh + ii - 2, gj = ww + jx - 4;
                if (gi < 0 || gi >= 4 || gj < 0 || gj >= 4) v -= 100.f;
            }
        }
        vals[i] = v;
        mx = fmaxf(mx, v);
    }
    __shared__ float red[8], red2[8];
    #pragma unroll
    for (int o = 16; o; o >>= 1) mx = fmaxf(mx, __shfl_xor_sync(0xffffffffu, mx, o));
    int wid = threadIdx.x >> 5, lane = threadIdx.x & 31;
    if (lane == 0) red[wid] = mx;
    __syncthreads();
    mx = fmaxf(fmaxf(fmaxf(red[0], red[1]), fmaxf(red[2], red[3])),
               fmaxf(fmaxf(red[4], red[5]), fmaxf(red[6], red[7])));
    float sum = 0.f;
    #pragma unroll
    for (int i = 0; i < 7; i++) {
        int j = threadIdx.x + i * 256;
        if (j < 1680) { vals[i] = expf(vals[i] - mx); sum += vals[i]; }
        else vals[i] = 0.f;
    }
    #pragma unroll
    for (int o = 16; o; o >>= 1) sum += __shfl_xor_sync(0xffffffffu, sum, o);
    if (lane == 0) red2[wid] = sum;
    __syncthreads();
    sum = red2[0] + red2[1] + red2[2] + red2[3] + red2[4] + red2[5] + red2[6] + red2[7];
    float inv = 1.f / sum;
    #pragma unroll
    for (int i = 0; i < 7; i++) {
        int j = threadIdx.x + i * 256;
        if (j < 1680) p[j] = vals[i] * inv;
    }
}

// ---------------- scatter window->spatial + residual ----------------
__global__ __launch_bounds__(256) void addres_k(const float* __restrict__ x,
                                                const float* __restrict__ Pw,
                                                float* __restrict__ xres) {
    int idx = blockIdx.x * 256 + threadIdx.x;
    int n = idx >> 7, c4 = idx & 127;
    int w = n % 36;
    int h = (n / 36) % 20;
    int bt = n / 720;
    int b = bt >> 3, t = bt & 7;
    int wh = h / 5, ih = h - wh * 5, ww = w / 9, iw = w - ww * 9;
    int win = b * 16 + wh * 4 + ww;
    int q = t * 45 + ih * 9 + iw;
    long long r = (long long)win * 360 + q;
    float4 xv = ((const float4*)x)[idx];
    float4 pv = ((const float4*)Pw)[r * 128 + c4];
    xv.x += pv.x; xv.y += pv.y; xv.z += pv.z; xv.w += pv.w;
    ((float4*)xres)[idx] = xv;
}

// ---------------- T2T fold (gather form) + normalize ----------------
__global__ __launch_bounds__(256) void t2tfold_k(const float* __restrict__ h1,
                                                 float* __restrict__ I) {
    int idx = blockIdx.x * 256 + threadIdx.x;
    if (idx >= 16 * 40 * 60 * 108) return;
    int x = idx % 108;
    int y = (idx / 108) % 60;
    int c40 = (idx / (108 * 60)) % 40;
    int g = idx / (108 * 60 * 40);
    int pys[3], kis[3], pxs[3], kjs[3];
    int cy = 0, cx = 0;
    #pragma unroll
    for (int dp = 0; dp < 3; dp++) {
        int py = (y + 3) / 3 - dp;
        int ki = y + 3 - 3 * py;
        if (py >= 0 && py < 20 && ki < 7) { pys[cy] = py; kis[cy] = ki; cy++; }
        int px = (x + 3) / 3 - dp;
        int kj = x + 3 - 3 * px;
        if (px >= 0 && px < 36 && kj < 7) { pxs[cx] = px; kjs[cx] = kj; cx++; }
    }
    float s = 0.f;
    for (int a = 0; a < cy; a++)
        for (int bb = 0; bb < cx; bb++) {
            long long r = (long long)g * 720 + pys[a] * 36 + pxs[bb];
            s += h1[r * 1960 + c40 * 49 + kis[a] * 7 + kjs[bb]];
        }
    I[idx] = s / (float)(cy * cx);
}

// ---------------- T2T unfold + exact GELU ----------------
__global__ __launch_bounds__(256) void t2tunf_k(const float* __restrict__ I,
                                                float* __restrict__ h2) {
    int idx = blockIdx.x * 256 + threadIdx.x;
    if (idx >= TOK * FFN) return;
    int c = idx % 1960;
    int r = idx / 1960;
    int g = r / 720;
    int p = r - g * 720;
    int py = p / 36, px = p - py * 36;
    int c40 = c / 49;
    int kk = c - c40 * 49;
    int ki = kk / 7, kj = kk - ki * 7;
    int y = py * 3 + ki - 3, x = px * 3 + kj - 3;
    float v = 0.f;
    if (y >= 0 && y < 60 && x >= 0 && x < 108)
        v = I[(((long long)g * 40 + c40) * 60 + y) * 108 + x];
    h2[idx] = 0.5f * v * (1.f + erff(v * 0.7071067811865475f));
}

// ---------------- host launch ----------------
#define SYM(p, s) do { void* _t = nullptr; cudaGetSymbolAddress(&_t, s); (p) = (float*)_t; } while (0)

static void run_tgemm(bool transB, const float* A, const float* Bm, const float* bias,
                      const float* res, float* C, int M, int N, int K,
                      int lda, int ldb, int ldc,
                      long long sAo, long long sAi, long long sBo, long long sBi,
                      long long sCo, long long sCi, int inner, int batch) {
    dim3 grid((N + 63) / 64, (M + 127) / 128, batch);
    if (transB) {
        size_t sm = (2 * 128 * 36 + 2 * 64 * 36) * sizeof(float);
        cudaFuncSetAttribute(tgemm_k<true>, cudaFuncAttributeMaxDynamicSharedMemorySize, (int)sm);
        tgemm_k<true><<<grid, 256, sm>>>(A, Bm, bias, res, C, M, N, K, lda, ldb, ldc,
                                         sAo, sAi, sBo, sBi, sCo, sCi, inner);
    } else {
        size_t sm = (2 * 128 * 36 + 2 * 32 * 68) * sizeof(float);
        cudaFuncSetAttribute(tgemm_k<false>, cudaFuncAttributeMaxDynamicSharedMemorySize, (int)sm);
        tgemm_k<false><<<grid, 256, sm>>>(A, Bm, bias, res, C, M, N, K, lda, ldb, ldc,
                                          sAo, sAi, sBo, sBi, sCo, sCi, inner);
    }
}

extern "C" void kernel_launch(void* const* d_in, const int* in_sizes, int n_in,
                              void* d_out, int out_size) {
    const float* x     = (const float*)d_in[0];
    const float* g1    = (const float*)d_in[1];
    const float* be1   = (const float*)d_in[2];
    const float* wqkv  = (const float*)d_in[3];
    const float* bqkv  = (const float*)d_in[4];
    const float* wproj = (const float*)d_in[5];
    const float* bproj = (const float*)d_in[6];
    const float* wpool = (const float*)d_in[7];
    const float* bpool = (const float*)d_in[8];
    const float* g2    = (const float*)d_in[9];
    const float* be2   = (const float*)d_in[10];
    const float* w1    = (const float*)d_in[11];
    const float* bf1   = (const float*)d_in[12];
    const float* w2    = (const float*)d_in[13];
    const float* bf2   = (const float*)d_in[14];
    float* out = (float*)d_out;

    float *xn, *qkv, *pooled, *qkvp, *Q, *K, *V, *S, *Aw, *Pw, *xres, *h1, *I;
    SYM(xn, g_xn); SYM(qkv, g_qkv); SYM(pooled, g_pooled); SYM(qkvp, g_qkvp);
    SYM(Q, g_Q); SYM(K, g_K); SYM(V, g_V); SYM(S, g_S); SYM(Aw, g_Aw);
    SYM(Pw, g_Pw); SYM(xres, g_xres); SYM(h1, g_h1); SYM(I, g_I);
    float* h2 = S;  // reuse scores buffer

    initvalid_k<<<1, 32>>>();
    ln_k<<<TOK, 128>>>(x, g1, be1, xn);
    // QKV GEMM
    run_tgemm(false, xn, wqkv, bqkv, nullptr, qkv, TOK, 1536, 512, 512, 1536, 1536,
              0, 0, 0, 0, 0, 0, 1, 1);
    pool_k<<<256, 128>>>(xn, wpool, bpool, pooled);
    // pooled QKV GEMM
    run_tgemm(false, pooled, wqkv, bqkv, nullptr, qkvp, 256, 1536, 512, 512, 1536, 1536,
              0, 0, 0, 0, 0, 0, 1, 1);
    gatherq_k<<<TOK, 128>>>(qkv, Q);
    gatherkv_k<<<NWIN * NK, 128>>>(qkv, qkvp, K, V);
    // scores: per (win, head): Q(360x128) @ K^T(1680x128)
    run_tgemm(true, Q, K, nullptr, nullptr, S, NQ, NK, HDc, 512, 512, NK,
              (long long)NQ * 512, 128, (long long)NK * 512, 128,
              (long long)NHc * NQ * NK, (long long)NQ * NK, NHc, NWIN * NHc);
    softmax_k<<<NWIN * NHc * NQ, 256>>>(S);
    // out: per (win, head): P(360x1680) @ V(1680x128)
    run_tgemm(false, S, V, nullptr, nullptr, Aw, NQ, HDc, NK, NK, 512, 512,
              (long long)NHc * NQ * NK, (long long)NQ * NK,
              (long long)NK * 512, 128,
              (long long)NQ * 512, 128, NHc, NWIN * NHc);
    // proj
    run_tgemm(false, Aw, wproj, bproj, nullptr, Pw, TOK, 512, 512, 512, 512, 512,
              0, 0, 0, 0, 0, 0, 1, 1);
    addres_k<<<TOK * 128 / 256, 256>>>(x, Pw, xres);
    ln_k<<<TOK, 128>>>(xres, g2, be2, xn);
    // FFN1
    run_tgemm(false, xn, w1, bf1, nullptr, h1, TOK, FFN, 512, 512, FFN, FFN,
              0, 0, 0, 0, 0, 0, 1, 1);
    t2tfold_k<<<(16 * 40 * 60 * 108 + 255) / 256, 256>>>(h1, I);
    t2tunf_k<<<(TOK * FFN + 255) / 256, 256>>>(I, h2);
    // FFN2 + residual -> out
    run_tgemm(false, h2, w2, bf2, xres, out, TOK, 512, FFN, FFN, 512, 512,
              0, 0, 0, 0, 0, 0, 1, 1);
}

// round 4
// speedup vs baseline: 6.0467x; 1.6272x over previous
#include <cuda_runtime.h>
#include <cuda_bf16.h>
#include <math.h>
#include <stdint.h>

// ---------------- constants ----------------
constexpr int NWIN = 32;
constexpr int NQ = 360;
constexpr int NK = 1680;
constexpr int TOK = 11520;
constexpr int FFN = 1960;
constexpr int Cch = 512, NHc = 4, HDc = 128;
constexpr float QSCALE = 0.08838834764831845f;

typedef __nv_bfloat16 bf16;
typedef __nv_bfloat162 bf162;

// ---------------- scratch ----------------
__device__ bf16  g_xn[TOK * Cch];
__device__ bf16  g_qkv[TOK * 3 * Cch];
__device__ bf16  g_pooled[256 * Cch];
__device__ bf16  g_qkvp[256 * 3 * Cch];
__device__ bf16  g_Q[NWIN * NQ * Cch];
__device__ bf16  g_K[NWIN * NK * Cch];
__device__ bf16  g_V[NWIN * NK * Cch];
__device__ float g_S[(long long)NWIN * NHc * NQ * NK]; // scores fp32; P bf16 in place; h2 bf16 reuse
__device__ bf16  g_Aw[TOK * Cch];
__device__ float g_Pw[TOK * Cch];
__device__ float g_xres[TOK * Cch];
__device__ float g_h1[TOK * FFN];
__device__ float g_I[16 * 40 * 60 * 108];
__device__ int   g_valid[120];
__device__ bf16  g_wqkvb[512 * 1536];
__device__ bf16  g_wprojb[512 * 512];
__device__ bf16  g_w1b[512 * 1960];
__device__ bf16  g_w2b[1960 * 512];

// ---------------- init valid-rolled table ----------------
__global__ void initvalid_k() {
    if (threadIdx.x == 0 && blockIdx.x == 0) {
        int n = 0;
        for (int s = 0; s < 4; s++)
            for (int ih = 0; ih < 5; ih++)
                for (int iw = 0; iw < 9; iw++) {
                    bool zero;
                    if (s == 0) zero = (ih < 3 && iw < 5);
                    else if (s == 1) zero = (ih < 3 && iw >= 4);
                    else if (s == 2) zero = (ih >= 2 && iw < 5);
                    else zero = (ih >= 2 && iw >= 4);
                    if (!zero) g_valid[n++] = s * 45 + ih * 9 + iw;
                }
    }
}

// ---------------- weight fp32 -> bf16 ----------------
__global__ __launch_bounds__(256) void convw_k(const float* __restrict__ s,
                                               bf16* __restrict__ d, int n) {
    int i = blockIdx.x * 256 + threadIdx.x;
    if (i < n) d[i] = __float2bfloat16(s[i]);
}

// ---------------- LayerNorm (fp32 in, bf16 out) ----------------
__global__ __launch_bounds__(128) void ln_k(const float* __restrict__ in,
                                            const float* __restrict__ g,
                                            const float* __restrict__ b,
                                            bf16* __restrict__ out) {
    int row = blockIdx.x;
    const float4* xp = (const float4*)(in + (long long)row * 512);
    float4 v = xp[threadIdx.x];
    float s = v.x + v.y + v.z + v.w;
    __shared__ float red[4], red2[4];
    #pragma unroll
    for (int o = 16; o; o >>= 1) s += __shfl_xor_sync(0xffffffffu, s, o);
    int wid = threadIdx.x >> 5, lane = threadIdx.x & 31;
    if (lane == 0) red[wid] = s;
    __syncthreads();
    float mu = (red[0] + red[1] + red[2] + red[3]) * (1.f / 512.f);
    float dx = v.x - mu, dy = v.y - mu, dz = v.z - mu, dw = v.w - mu;
    float sq = dx * dx + dy * dy + dz * dz + dw * dw;
    #pragma unroll
    for (int o = 16; o; o >>= 1) sq += __shfl_xor_sync(0xffffffffu, sq, o);
    if (lane == 0) red2[wid] = sq;
    __syncthreads();
    float var = (red2[0] + red2[1] + red2[2] + red2[3]) * (1.f / 512.f);
    float inv = rsqrtf(var + 1e-5f);
    float4 gg = ((const float4*)g)[threadIdx.x];
    float4 bb = ((const float4*)b)[threadIdx.x];
    bf162 o0 = __floats2bfloat162_rn(dx * inv * gg.x + bb.x, dy * inv * gg.y + bb.y);
    bf162 o1 = __floats2bfloat162_rn(dz * inv * gg.z + bb.z, dw * inv * gg.w + bb.w);
    bf162* op = (bf162*)(out + (long long)row * 512);
    op[2 * threadIdx.x] = o0;
    op[2 * threadIdx.x + 1] = o1;
}

// ---------------- window pooling (bf16 in/out) ----------------
__global__ __launch_bounds__(128) void pool_k(const bf16* __restrict__ xn,
                                              const float* __restrict__ wpool,
                                              const float* __restrict__ bpool,
                                              bf16* __restrict__ pooled) {
    int widx = blockIdx.x >> 2;
    int c = ((blockIdx.x & 3) << 7) + threadIdx.x;
    int ww = widx & 3, wh = (widx >> 2) & 3, bt = widx >> 4;
    float s = 0.f;
    #pragma unroll
    for (int a = 0; a < 45; a++) {
        int ih = a / 9, iw = a % 9;
        long long tok = ((long long)bt * 20 + wh * 5 + ih) * 36 + ww * 9 + iw;
        s += __bfloat162float(xn[tok * 512 + c]) * wpool[a];
    }
    pooled[(long long)widx * 512 + c] = __float2bfloat16(s + bpool[0]);
}

// ---------------- gather Q (scaled, bf16) ----------------
__global__ __launch_bounds__(128) void gatherq_k(const bf16* __restrict__ qkv,
                                                 bf16* __restrict__ Q) {
    int r = blockIdx.x;
    int win = r / 360, q = r - win * 360;
    int b = win >> 4, wh = (win >> 2) & 3, ww = win & 3;
    int t = q / 45, a = q - t * 45, ih = a / 9, iw = a % 9;
    long long tok = ((long long)(b * 8 + t) * 20 + wh * 5 + ih) * 36 + ww * 9 + iw;
    const bf162* src = (const bf162*)(qkv + tok * 1536);
    bf162* dst = (bf162*)(Q + (long long)r * 512);
    int c = threadIdx.x;
    #pragma unroll
    for (int i = 0; i < 2; i++) {
        float2 f = __bfloat1622float2(src[2 * c + i]);
        f.x *= QSCALE; f.y *= QSCALE;
        dst[2 * c + i] = __floats2bfloat162_rn(f.x, f.y);
    }
}

// ---------------- gather K/V (bf16 copies) ----------------
__global__ __launch_bounds__(128) void gatherkv_k(const bf16* __restrict__ qkv,
                                                  const bf16* __restrict__ qkvp,
                                                  bf16* __restrict__ Kall,
                                                  bf16* __restrict__ Vall) {
    int r = blockIdx.x;
    int win = r / 1680, j = r - win * 1680;
    int b = win >> 4, wh = (win >> 2) & 3, ww = win & 3;
    const bf16* pK = nullptr;
    const bf16* pV = nullptr;
    if (j < 360) {
        int t = j / 45, a = j - t * 45, ih = a / 9, iw = a % 9;
        long long tok = ((long long)(b * 8 + t) * 20 + wh * 5 + ih) * 36 + ww * 9 + iw;
        pK = qkv + tok * 1536 + 512;
        pV = qkv + tok * 1536 + 1024;
    } else if (j < 1320) {
        int jj = j - 360;
        int t = jj / 120, vi = jj - t * 120;
        int f = g_valid[vi];
        int s = f / 45, a = f - s * 45, ih = a / 9, iw = a % 9;
        int sh = (s < 2) ? -2 : 2;
        int sw = (s & 1) ? 4 : -4;
        int hh = wh * 5 + ih - sh; hh %= 20; if (hh < 0) hh += 20;
        int wp = ww * 9 + iw - sw; wp %= 36; if (wp < 0) wp += 36;
        long long tok = ((long long)(b * 8 + t) * 20 + hh) * 36 + wp;
        pK = qkv + tok * 1536 + 512;
        pV = qkv + tok * 1536 + 1024;
    } else {
        int jj = j - 1320;
        int t = jj / 45, a = jj - t * 45, i = a / 9, jx = a % 9;
        int gi = wh + i - 2, gj = ww + jx - 4;
        if (gi >= 0 && gi < 4 && gj >= 0 && gj < 4) {
            long long ptok = (long long)(b * 8 + t) * 16 + gi * 4 + gj;
            pK = qkvp + ptok * 1536 + 512;
            pV = qkvp + ptok * 1536 + 1024;
        }
    }
    int c = threadIdx.x;
    uint2 zk = make_uint2(0, 0), zv = make_uint2(0, 0);
    if (pK) { zk = ((const uint2*)pK)[c]; zv = ((const uint2*)pV)[c]; }
    ((uint2*)(Kall + (long long)r * 512))[c] = zk;
    ((uint2*)(Vall + (long long)r * 512))[c] = zv;
}

// ---------------- bf16 tensor-core GEMM ----------------
__device__ __forceinline__ void cpasync16(uint32_t saddr, const void* gaddr, bool pred) {
    int sz = pred ? 16 : 0;
    asm volatile("cp.async.cg.shared.global [%0], [%1], 16, %2;\n"
                 :: "r"(saddr), "l"(gaddr), "r"(sz));
}
__device__ __forceinline__ void ldsm4(uint32_t& r0, uint32_t& r1, uint32_t& r2, uint32_t& r3,
                                      uint32_t a) {
    asm volatile("ldmatrix.sync.aligned.m8n8.x4.shared.b16 {%0,%1,%2,%3}, [%4];\n"
                 : "=r"(r0), "=r"(r1), "=r"(r2), "=r"(r3) : "r"(a));
}
__device__ __forceinline__ void ldsm4t(uint32_t& r0, uint32_t& r1, uint32_t& r2, uint32_t& r3,
                                       uint32_t a) {
    asm volatile("ldmatrix.sync.aligned.m8n8.x4.trans.shared.b16 {%0,%1,%2,%3}, [%4];\n"
                 : "=r"(r0), "=r"(r1), "=r"(r2), "=r"(r3) : "r"(a));
}
__device__ __forceinline__ void cstore(float* p, float v) { *p = v; }
__device__ __forceinline__ void cstore(bf16* p, float v) { *p = __float2bfloat16(v); }

// BM=128, BN=64, BK=32, 256 threads, warps 4(M) x 2(N), warp tile 32x32
template <bool TRANSB, typename OutT>
__global__ __launch_bounds__(256) void tgemm_k(
    const bf16* __restrict__ A, const bf16* __restrict__ Bm,
    const float* __restrict__ bias, const float* __restrict__ res,
    OutT* __restrict__ Cm,
    int M, int N, int K, int lda, int ldb, int ldc,
    long long sAo, long long sAi, long long sBo, long long sBi,
    long long sCo, long long sCi, int inner) {
    constexpr int BM = 128, BN = 64, BK = 32;
    constexpr int AST = BK + 8;                       // 40 bf16 per row
    constexpr int BST = TRANSB ? (BK + 8) : (BN + 8); // 40 or 72
    constexpr int ASTAGE = BM * AST;                  // elems
    constexpr int BSTAGE = TRANSB ? (BN * BST) : (BK * BST);

    extern __shared__ bf16 smem[];
    bf16* As = smem;
    bf16* Bs = smem + 2 * ASTAGE;

    int z = blockIdx.z;
    int zo = z / inner, zi = z - zo * inner;
    A += zo * sAo + zi * sAi;
    Bm += zo * sBo + zi * sBi;
    long long coff = zo * sCo + zi * sCi;
    Cm += coff;
    if (res) res += coff;

    int tid = threadIdx.x;
    int row0 = blockIdx.y * BM, col0 = blockIdx.x * BN;
    int wid = tid >> 5, lane = tid & 31;
    int wm = wid & 3, wn = wid >> 2;
    int g = lane >> 2, t = lane & 3;

    uint32_t sA0 = (uint32_t)__cvta_generic_to_shared(As);
    uint32_t sB0 = (uint32_t)__cvta_generic_to_shared(Bs);

    int ktiles = (K + BK - 1) / BK;

    auto load_tile = [&](int stage, int k0) {
        // A: 128 x 32 bf16 = 512 16B-chunks -> 2/thread
        #pragma unroll
        for (int i = 0; i < 2; i++) {
            int idx = tid + i * 256;
            int r = idx >> 2, kc = (idx & 3) << 3;
            int gr = row0 + r, gk = k0 + kc;
            bool ok = (gr < M) && (gk < K);
            uint32_t sa = sA0 + (uint32_t)((stage * ASTAGE + r * AST + kc) * 2);
            cpasync16(sa, A + (long long)gr * lda + gk, ok);
        }
        if (TRANSB) {
            int idx = tid;
            int n = idx >> 2, kc = (idx & 3) << 3;
            int gn = col0 + n, gk = k0 + kc;
            bool ok = (gn < N) && (gk < K);
            uint32_t sb = sB0 + (uint32_t)((stage * BSTAGE + n * BST + kc) * 2);
            cpasync16(sb, Bm + (long long)gn * ldb + gk, ok);
        } else {
            int idx = tid;
            int kk = idx >> 3, nc = (idx & 7) << 3;
            int gk = k0 + kk, gn = col0 + nc;
            bool ok = (gk < K) && (gn < N);
            uint32_t sb = sB0 + (uint32_t)((stage * BSTAGE + kk * BST + nc) * 2);
            cpasync16(sb, Bm + (long long)gk * ldb + gn, ok);
        }
    };

    float acc[2][4][4];
    #pragma unroll
    for (int mi = 0; mi < 2; mi++)
        #pragma unroll
        for (int ni = 0; ni < 4; ni++)
            #pragma unroll
            for (int q = 0; q < 4; q++) acc[mi][ni][q] = 0.f;

    load_tile(0, 0);
    asm volatile("cp.async.commit_group;\n");

    for (int kt = 0; kt < ktiles; kt++) {
        if (kt + 1 < ktiles) load_tile((kt + 1) & 1, (kt + 1) * BK);
        asm volatile("cp.async.commit_group;\n");
        asm volatile("cp.async.wait_group %0;\n" :: "n"(1));
        __syncthreads();

        uint32_t sAb = sA0 + (uint32_t)((kt & 1) * ASTAGE * 2);
        uint32_t sBb = sB0 + (uint32_t)((kt & 1) * BSTAGE * 2);

        #pragma unroll
        for (int ks = 0; ks < 2; ks++) {
            uint32_t a[2][4], b[4][2];
            #pragma unroll
            for (int mi = 0; mi < 2; mi++) {
                int row = wm * 32 + mi * 16 + (lane & 15);
                uint32_t ad = sAb + (uint32_t)((row * AST + ks * 16 + ((lane >> 4) << 3)) * 2);
                ldsm4(a[mi][0], a[mi][1], a[mi][2], a[mi][3], ad);
            }
            #pragma unroll
            for (int h = 0; h < 2; h++) {
                if (TRANSB) {
                    int rown = wn * 32 + h * 16 + (lane & 7) + ((lane >> 4) << 3);
                    uint32_t bd = sBb + (uint32_t)((rown * BST + ks * 16 + (((lane >> 3) & 1) << 3)) * 2);
                    ldsm4(b[2 * h][0], b[2 * h][1], b[2 * h + 1][0], b[2 * h + 1][1], bd);
                } else {
                    int rowk = ks * 16 + (lane & 7) + (((lane >> 3) & 1) << 3);
                    int coln = wn * 32 + h * 16 + ((lane >> 4) << 3);
                    uint32_t bd = sBb + (uint32_t)((rowk * BST + coln) * 2);
                    ldsm4t(b[2 * h][0], b[2 * h][1], b[2 * h + 1][0], b[2 * h + 1][1], bd);
                }
            }
            #pragma unroll
            for (int mi = 0; mi < 2; mi++)
                #pragma unroll
                for (int ni = 0; ni < 4; ni++) {
                    asm volatile(
                        "mma.sync.aligned.m16n8k16.row.col.f32.bf16.bf16.f32 "
                        "{%0,%1,%2,%3}, {%4,%5,%6,%7}, {%8,%9}, {%0,%1,%2,%3};\n"
                        : "+f"(acc[mi][ni][0]), "+f"(acc[mi][ni][1]),
                          "+f"(acc[mi][ni][2]), "+f"(acc[mi][ni][3])
                        : "r"(a[mi][0]), "r"(a[mi][1]), "r"(a[mi][2]), "r"(a[mi][3]),
                          "r"(b[ni][0]), "r"(b[ni][1]));
                }
        }
        __syncthreads();
    }

    #pragma unroll
    for (int mi = 0; mi < 2; mi++) {
        int r = row0 + wm * 32 + mi * 16 + g;
        #pragma unroll
        for (int ni = 0; ni < 4; ni++) {
            int c = col0 + wn * 32 + ni * 8 + 2 * t;
            #pragma unroll
            for (int q = 0; q < 4; q++) {
                int rr = r + (q >> 1) * 8;
                int cc = c + (q & 1);
                if (rr < M && cc < N) {
                    float v = acc[mi][ni][q];
                    if (bias) v += bias[cc];
                    long long ci = (long long)rr * ldc + cc;
                    if (res) v += res[ci];
                    cstore(Cm + ci, v);
                }
            }
        }
    }
}

// ---------------- softmax: fp32 scores in, bf16 probs written in place ----------------
__global__ __launch_bounds__(256) void softmax_k(float* __restrict__ S) {
    int row = blockIdx.x;
    int win = row / 1440;
    int l = win & 15, wh = l >> 2, ww = l & 3;
    float* p = S + (long long)row * 1680;
    float vals[7];
    float mx = -1e30f;
    #pragma unroll
    for (int i = 0; i < 7; i++) {
        int j = threadIdx.x + i * 256;
        float v = -1e30f;
        if (j < 1680) {
            v = p[j];
            if (j >= 1320) {
                int jj = j - 1320;
                int a = jj % 45;
                int ii = a / 9, jx = a % 9;
                int gi = wh + ii - 2, gj = ww + jx - 4;
                if (gi < 0 || gi >= 4 || gj < 0 || gj >= 4) v -= 100.f;
            }
        }
        vals[i] = v;
        mx = fmaxf(mx, v);
    }
    __shared__ float red[8], red2[8];
    #pragma unroll
    for (int o = 16; o; o >>= 1) mx = fmaxf(mx, __shfl_xor_sync(0xffffffffu, mx, o));
    int wid = threadIdx.x >> 5, lane = threadIdx.x & 31;
    if (lane == 0) red[wid] = mx;
    __syncthreads();
    mx = fmaxf(fmaxf(fmaxf(red[0], red[1]), fmaxf(red[2], red[3])),
               fmaxf(fmaxf(red[4], red[5]), fmaxf(red[6], red[7])));
    float sum = 0.f;
    #pragma unroll
    for (int i = 0; i < 7; i++) {
        int j = threadIdx.x + i * 256;
        if (j < 1680) { vals[i] = expf(vals[i] - mx); sum += vals[i]; }
        else vals[i] = 0.f;
    }
    #pragma unroll
    for (int o = 16; o; o >>= 1) sum += __shfl_xor_sync(0xffffffffu, sum, o);
    if (lane == 0) red2[wid] = sum;
    __syncthreads();
    sum = red2[0] + red2[1] + red2[2] + red2[3] + red2[4] + red2[5] + red2[6] + red2[7];
    float inv = 1.f / sum;
    bf16* pb = (bf16*)p;          // in-place: this block's own row only; all reads done
    #pragma unroll
    for (int i = 0; i < 7; i++) {
        int j = threadIdx.x + i * 256;
        if (j < 1680) pb[j] = __float2bfloat16(vals[i] * inv);
    }
}

// ---------------- scatter window->spatial + residual (fp32) ----------------
__global__ __launch_bounds__(256) void addres_k(const float* __restrict__ x,
                                                const float* __restrict__ Pw,
                                                float* __restrict__ xres) {
    int idx = blockIdx.x * 256 + threadIdx.x;
    int n = idx >> 7, c4 = idx & 127;
    int w = n % 36;
    int h = (n / 36) % 20;
    int bt = n / 720;
    int b = bt >> 3, t = bt & 7;
    int wh = h / 5, ih = h - wh * 5, ww = w / 9, iw = w - ww * 9;
    int win = b * 16 + wh * 4 + ww;
    int q = t * 45 + ih * 9 + iw;
    long long r = (long long)win * 360 + q;
    float4 xv = ((const float4*)x)[idx];
    float4 pv = ((const float4*)Pw)[r * 128 + c4];
    xv.x += pv.x; xv.y += pv.y; xv.z += pv.z; xv.w += pv.w;
    ((float4*)xres)[idx] = xv;
}

// ---------------- T2T fold (gather form) + normalize ----------------
__global__ __launch_bounds__(256) void t2tfold_k(const float* __restrict__ h1,
                                                 float* __restrict__ I) {
    int idx = blockIdx.x * 256 + threadIdx.x;
    if (idx >= 16 * 40 * 60 * 108) return;
    int x = idx % 108;
    int y = (idx / 108) % 60;
    int c40 = (idx / (108 * 60)) % 40;
    int g = idx / (108 * 60 * 40);
    int pys[3], kis[3], pxs[3], kjs[3];
    int cy = 0, cx = 0;
    #pragma unroll
    for (int dp = 0; dp < 3; dp++) {
        int py = (y + 3) / 3 - dp;
        int ki = y + 3 - 3 * py;
        if (py >= 0 && py < 20 && ki < 7) { pys[cy] = py; kis[cy] = ki; cy++; }
        int px = (x + 3) / 3 - dp;
        int kj = x + 3 - 3 * px;
        if (px >= 0 && px < 36 && kj < 7) { pxs[cx] = px; kjs[cx] = kj; cx++; }
    }
    float s = 0.f;
    for (int a = 0; a < cy; a++)
        for (int bb = 0; bb < cx; bb++) {
            long long r = (long long)g * 720 + pys[a] * 36 + pxs[bb];
            s += h1[r * 1960 + c40 * 49 + kis[a] * 7 + kjs[bb]];
        }
    I[idx] = s / (float)(cy * cx);
}

// ---------------- T2T unfold + exact GELU (bf16 out) ----------------
__global__ __launch_bounds__(256) void t2tunf_k(const float* __restrict__ I,
                                                bf16* __restrict__ h2) {
    int idx = blockIdx.x * 256 + threadIdx.x;
    if (idx >= TOK * FFN) return;
    int c = idx % 1960;
    int r = idx / 1960;
    int g = r / 720;
    int p = r - g * 720;
    int py = p / 36, px = p - py * 36;
    int c40 = c / 49;
    int kk = c - c40 * 49;
    int ki = kk / 7, kj = kk - ki * 7;
    int y = py * 3 + ki - 3, x = px * 3 + kj - 3;
    float v = 0.f;
    if (y >= 0 && y < 60 && x >= 0 && x < 108)
        v = I[(((long long)g * 40 + c40) * 60 + y) * 108 + x];
    h2[idx] = __float2bfloat16(0.5f * v * (1.f + erff(v * 0.7071067811865475f)));
}

// ---------------- host launch ----------------
#define SYM(T, p, s) T* p; do { void* _t = nullptr; cudaGetSymbolAddress(&_t, s); (p) = (T*)_t; } while (0)

template <bool TRANSB, typename OutT>
static void run_tgemm(const bf16* A, const bf16* Bm, const float* bias,
                      const float* res, OutT* C, int M, int N, int K,
                      int lda, int ldb, int ldc,
                      long long sAo, long long sAi, long long sBo, long long sBi,
                      long long sCo, long long sCi, int inner, int batch) {
    dim3 grid((N + 63) / 64, (M + 127) / 128, batch);
    size_t sm = (2 * 128 * 40 + 2 * (TRANSB ? 64 * 40 : 32 * 72)) * sizeof(bf16);
    cudaFuncSetAttribute(tgemm_k<TRANSB, OutT>, cudaFuncAttributeMaxDynamicSharedMemorySize, (int)sm);
    tgemm_k<TRANSB, OutT><<<grid, 256, sm>>>(A, Bm, bias, res, C, M, N, K, lda, ldb, ldc,
                                             sAo, sAi, sBo, sBi, sCo, sCi, inner);
}

extern "C" void kernel_launch(void* const* d_in, const int* in_sizes, int n_in,
                              void* d_out, int out_size) {
    const float* x     = (const float*)d_in[0];
    const float* g1    = (const float*)d_in[1];
    const float* be1   = (const float*)d_in[2];
    const float* wqkv  = (const float*)d_in[3];
    const float* bqkv  = (const float*)d_in[4];
    const float* wproj = (const float*)d_in[5];
    const float* bproj = (const float*)d_in[6];
    const float* wpool = (const float*)d_in[7];
    const float* bpool = (const float*)d_in[8];
    const float* g2    = (const float*)d_in[9];
    const float* be2   = (const float*)d_in[10];
    const float* w1    = (const float*)d_in[11];
    const float* bf1   = (const float*)d_in[12];
    const float* w2    = (const float*)d_in[13];
    const float* bf2   = (const float*)d_in[14];
    float* out = (float*)d_out;

    SYM(bf16, xn, g_xn); SYM(bf16, qkv, g_qkv); SYM(bf16, pooled, g_pooled);
    SYM(bf16, qkvp, g_qkvp); SYM(bf16, Q, g_Q); SYM(bf16, K, g_K); SYM(bf16, V, g_V);
    SYM(float, S, g_S); SYM(bf16, Aw, g_Aw); SYM(float, Pw, g_Pw);
    SYM(float, xres, g_xres); SYM(float, h1, g_h1); SYM(float, I, g_I);
    SYM(bf16, wqkvb, g_wqkvb); SYM(bf16, wprojb, g_wprojb);
    SYM(bf16, w1b, g_w1b); SYM(bf16, w2b, g_w2b);
    bf16* P  = (bf16*)S;   // softmax writes probs in place (row stride 3360 bf16)
    bf16* h2 = (bf16*)S;   // reused after P consumed

    initvalid_k<<<1, 32>>>();
    convw_k<<<(512 * 1536 + 255) / 256, 256>>>(wqkv, wqkvb, 512 * 1536);
    convw_k<<<(512 * 512 + 255) / 256, 256>>>(wproj, wprojb, 512 * 512);
    convw_k<<<(512 * 1960 + 255) / 256, 256>>>(w1, w1b, 512 * 1960);
    convw_k<<<(1960 * 512 + 255) / 256, 256>>>(w2, w2b, 1960 * 512);

    ln_k<<<TOK, 128>>>(x, g1, be1, xn);
    run_tgemm<false, bf16>(xn, wqkvb, bqkv, nullptr, qkv, TOK, 1536, 512, 512, 1536, 1536,
                           0, 0, 0, 0, 0, 0, 1, 1);
    pool_k<<<1024, 128>>>(xn, wpool, bpool, pooled);
    run_tgemm<false, bf16>(pooled, wqkvb, bqkv, nullptr, qkvp, 256, 1536, 512, 512, 1536, 1536,
                           0, 0, 0, 0, 0, 0, 1, 1);
    gatherq_k<<<TOK, 128>>>(qkv, Q);
    gatherkv_k<<<NWIN * NK, 128>>>(qkv, qkvp, K, V);
    // scores: per (win,head): Q(360x128) @ K^T(1680x128) -> fp32
    run_tgemm<true, float>(Q, K, nullptr, nullptr, S, NQ, NK, HDc, 512, 512, NK,
                           (long long)NQ * 512, 128, (long long)NK * 512, 128,
                           (long long)NHc * NQ * NK, (long long)NQ * NK, NHc, NWIN * NHc);
    softmax_k<<<NWIN * NHc * NQ, 256>>>(S);
    // P(360x1680 bf16, lda 3360) @ V(1680x128) -> Aw bf16
    run_tgemm<false, bf16>(P, V, nullptr, nullptr, Aw, NQ, HDc, NK, 2 * NK, 512, 512,
                           (long long)NHc * NQ * NK * 2, (long long)NQ * NK * 2,
                           (long long)NK * 512, 128,
                           (long long)NQ * 512, 128, NHc, NWIN * NHc);
    run_tgemm<false, float>(Aw, wprojb, bproj, nullptr, Pw, TOK, 512, 512, 512, 512, 512,
                            0, 0, 0, 0, 0, 0, 1, 1);
    addres_k<<<TOK * 128 / 256, 256>>>(x, Pw, xres);
    ln_k<<<TOK, 128>>>(xres, g2, be2, xn);
    run_tgemm<false, float>(xn, w1b, bf1, nullptr, h1, TOK, FFN, 512, 512, FFN, FFN,
                            0, 0, 0, 0, 0, 0, 1, 1);
    t2tfold_k<<<(16 * 40 * 60 * 108 + 255) / 256, 256>>>(h1, I);
    t2tunf_k<<<(TOK * FFN + 255) / 256, 256>>>(I, h2);
    run_tgemm<false, float>(h2, w2b, bf2, xres, out, TOK, 512, FFN, FFN, 512, 512,
                            0, 0, 0, 0, 0, 0, 1, 1);
}

// round 5
// speedup vs baseline: 7.4542x; 1.2328x over previous
#include <cuda_runtime.h>
#include <cuda_bf16.h>
#include <math.h>
#include <stdint.h>

// ---------------- constants ----------------
constexpr int NWIN = 32;
constexpr int NQ = 360;
constexpr int NK = 1680;
constexpr int TOK = 11520;
constexpr int FFN = 1960;
constexpr int Cch = 512, NHc = 4, HDc = 128;
constexpr float QSCALE = 0.08838834764831845f;

typedef __nv_bfloat16 bf16;
typedef __nv_bfloat162 bf162;

// ---------------- scratch ----------------
__device__ bf16  g_xn[TOK * Cch];
__device__ bf16  g_qkv[TOK * 3 * Cch];
__device__ bf16  g_pooled[256 * Cch];
__device__ bf16  g_qkvp[256 * 3 * Cch];
__device__ bf16  g_Q[NWIN * NQ * Cch];
__device__ bf16  g_K[NWIN * NK * Cch];
__device__ bf16  g_V[NWIN * NK * Cch];
__device__ bf16  g_h2[TOK * FFN];
__device__ bf16  g_Aw[TOK * Cch];
__device__ float g_Pw[TOK * Cch];
__device__ float g_xres[TOK * Cch];
__device__ float g_h1[TOK * FFN];
__device__ float g_I[16 * 40 * 60 * 108];
__device__ int   g_valid[120];
__device__ bf16  g_wqkvb[512 * 1536];
__device__ bf16  g_wprojb[512 * 512];
__device__ bf16  g_w1b[512 * 1960];
__device__ bf16  g_w2b[1960 * 512];

// ---------------- init valid-rolled table ----------------
__global__ void initvalid_k() {
    if (threadIdx.x == 0 && blockIdx.x == 0) {
        int n = 0;
        for (int s = 0; s < 4; s++)
            for (int ih = 0; ih < 5; ih++)
                for (int iw = 0; iw < 9; iw++) {
                    bool zero;
                    if (s == 0) zero = (ih < 3 && iw < 5);
                    else if (s == 1) zero = (ih < 3 && iw >= 4);
                    else if (s == 2) zero = (ih >= 2 && iw < 5);
                    else zero = (ih >= 2 && iw >= 4);
                    if (!zero) g_valid[n++] = s * 45 + ih * 9 + iw;
                }
    }
}

// ---------------- weight fp32 -> bf16 ----------------
__global__ __launch_bounds__(256) void convw_k(const float* __restrict__ s,
                                               bf16* __restrict__ d, int n) {
    int i = blockIdx.x * 256 + threadIdx.x;
    if (i < n) d[i] = __float2bfloat16(s[i]);
}

// ---------------- LayerNorm (fp32 in, bf16 out) ----------------
__global__ __launch_bounds__(128) void ln_k(const float* __restrict__ in,
                                            const float* __restrict__ g,
                                            const float* __restrict__ b,
                                            bf16* __restrict__ out) {
    int row = blockIdx.x;
    const float4* xp = (const float4*)(in + (long long)row * 512);
    float4 v = xp[threadIdx.x];
    float s = v.x + v.y + v.z + v.w;
    __shared__ float red[4], red2[4];
    #pragma unroll
    for (int o = 16; o; o >>= 1) s += __shfl_xor_sync(0xffffffffu, s, o);
    int wid = threadIdx.x >> 5, lane = threadIdx.x & 31;
    if (lane == 0) red[wid] = s;
    __syncthreads();
    float mu = (red[0] + red[1] + red[2] + red[3]) * (1.f / 512.f);
    float dx = v.x - mu, dy = v.y - mu, dz = v.z - mu, dw = v.w - mu;
    float sq = dx * dx + dy * dy + dz * dz + dw * dw;
    #pragma unroll
    for (int o = 16; o; o >>= 1) sq += __shfl_xor_sync(0xffffffffu, sq, o);
    if (lane == 0) red2[wid] = sq;
    __syncthreads();
    float var = (red2[0] + red2[1] + red2[2] + red2[3]) * (1.f / 512.f);
    float inv = rsqrtf(var + 1e-5f);
    float4 gg = ((const float4*)g)[threadIdx.x];
    float4 bb = ((const float4*)b)[threadIdx.x];
    bf162 o0 = __floats2bfloat162_rn(dx * inv * gg.x + bb.x, dy * inv * gg.y + bb.y);
    bf162 o1 = __floats2bfloat162_rn(dz * inv * gg.z + bb.z, dw * inv * gg.w + bb.w);
    bf162* op = (bf162*)(out + (long long)row * 512);
    op[2 * threadIdx.x] = o0;
    op[2 * threadIdx.x + 1] = o1;
}

// ---------------- window pooling ----------------
__global__ __launch_bounds__(128) void pool_k(const bf16* __restrict__ xn,
                                              const float* __restrict__ wpool,
                                              const float* __restrict__ bpool,
                                              bf16* __restrict__ pooled) {
    int widx = blockIdx.x >> 2;
    int c = ((blockIdx.x & 3) << 7) + threadIdx.x;
    int ww = widx & 3, wh = (widx >> 2) & 3, bt = widx >> 4;
    float s = 0.f;
    #pragma unroll
    for (int a = 0; a < 45; a++) {
        int ih = a / 9, iw = a % 9;
        long long tok = ((long long)bt * 20 + wh * 5 + ih) * 36 + ww * 9 + iw;
        s += __bfloat162float(xn[tok * 512 + c]) * wpool[a];
    }
    pooled[(long long)widx * 512 + c] = __float2bfloat16(s + bpool[0]);
}

// ---------------- gather Q (scaled, bf16) ----------------
__global__ __launch_bounds__(128) void gatherq_k(const bf16* __restrict__ qkv,
                                                 bf16* __restrict__ Q) {
    int r = blockIdx.x;
    int win = r / 360, q = r - win * 360;
    int b = win >> 4, wh = (win >> 2) & 3, ww = win & 3;
    int t = q / 45, a = q - t * 45, ih = a / 9, iw = a % 9;
    long long tok = ((long long)(b * 8 + t) * 20 + wh * 5 + ih) * 36 + ww * 9 + iw;
    const bf162* src = (const bf162*)(qkv + tok * 1536);
    bf162* dst = (bf162*)(Q + (long long)r * 512);
    int c = threadIdx.x;
    #pragma unroll
    for (int i = 0; i < 2; i++) {
        float2 f = __bfloat1622float2(src[2 * c + i]);
        f.x *= QSCALE; f.y *= QSCALE;
        dst[2 * c + i] = __floats2bfloat162_rn(f.x, f.y);
    }
}

// ---------------- gather K/V ----------------
__global__ __launch_bounds__(128) void gatherkv_k(const bf16* __restrict__ qkv,
                                                  const bf16* __restrict__ qkvp,
                                                  bf16* __restrict__ Kall,
                                                  bf16* __restrict__ Vall) {
    int r = blockIdx.x;
    int win = r / 1680, j = r - win * 1680;
    int b = win >> 4, wh = (win >> 2) & 3, ww = win & 3;
    const bf16* pK = nullptr;
    const bf16* pV = nullptr;
    if (j < 360) {
        int t = j / 45, a = j - t * 45, ih = a / 9, iw = a % 9;
        long long tok = ((long long)(b * 8 + t) * 20 + wh * 5 + ih) * 36 + ww * 9 + iw;
        pK = qkv + tok * 1536 + 512;
        pV = qkv + tok * 1536 + 1024;
    } else if (j < 1320) {
        int jj = j - 360;
        int t = jj / 120, vi = jj - t * 120;
        int f = g_valid[vi];
        int s = f / 45, a = f - s * 45, ih = a / 9, iw = a % 9;
        int sh = (s < 2) ? -2 : 2;
        int sw = (s & 1) ? 4 : -4;
        int hh = wh * 5 + ih - sh; hh %= 20; if (hh < 0) hh += 20;
        int wp = ww * 9 + iw - sw; wp %= 36; if (wp < 0) wp += 36;
        long long tok = ((long long)(b * 8 + t) * 20 + hh) * 36 + wp;
        pK = qkv + tok * 1536 + 512;
        pV = qkv + tok * 1536 + 1024;
    } else {
        int jj = j - 1320;
        int t = jj / 45, a = jj - t * 45, i = a / 9, jx = a % 9;
        int gi = wh + i - 2, gj = ww + jx - 4;
        if (gi >= 0 && gi < 4 && gj >= 0 && gj < 4) {
            long long ptok = (long long)(b * 8 + t) * 16 + gi * 4 + gj;
            pK = qkvp + ptok * 1536 + 512;
            pV = qkvp + ptok * 1536 + 1024;
        }
    }
    int c = threadIdx.x;
    uint2 zk = make_uint2(0, 0), zv = make_uint2(0, 0);
    if (pK) { zk = ((const uint2*)pK)[c]; zv = ((const uint2*)pV)[c]; }
    ((uint2*)(Kall + (long long)r * 512))[c] = zk;
    ((uint2*)(Vall + (long long)r * 512))[c] = zv;
}

// ---------------- common PTX helpers ----------------
__device__ __forceinline__ void cpasync16(uint32_t saddr, const void* gaddr, bool pred) {
    int sz = pred ? 16 : 0;
    asm volatile("cp.async.cg.shared.global [%0], [%1], 16, %2;\n"
                 :: "r"(saddr), "l"(gaddr), "r"(sz));
}
__device__ __forceinline__ void ldsm4(uint32_t& r0, uint32_t& r1, uint32_t& r2, uint32_t& r3,
                                      uint32_t a) {
    asm volatile("ldmatrix.sync.aligned.m8n8.x4.shared.b16 {%0,%1,%2,%3}, [%4];\n"
                 : "=r"(r0), "=r"(r1), "=r"(r2), "=r"(r3) : "r"(a));
}
__device__ __forceinline__ void ldsm4t(uint32_t& r0, uint32_t& r1, uint32_t& r2, uint32_t& r3,
                                       uint32_t a) {
    asm volatile("ldmatrix.sync.aligned.m8n8.x4.trans.shared.b16 {%0,%1,%2,%3}, [%4];\n"
                 : "=r"(r0), "=r"(r1), "=r"(r2), "=r"(r3) : "r"(a));
}
__device__ __forceinline__ void mma16816(float* c, const uint32_t* a, const uint32_t* b) {
    asm volatile(
        "mma.sync.aligned.m16n8k16.row.col.f32.bf16.bf16.f32 "
        "{%0,%1,%2,%3}, {%4,%5,%6,%7}, {%8,%9}, {%0,%1,%2,%3};\n"
        : "+f"(c[0]), "+f"(c[1]), "+f"(c[2]), "+f"(c[3])
        : "r"(a[0]), "r"(a[1]), "r"(a[2]), "r"(a[3]), "r"(b[0]), "r"(b[1]));
}
__device__ __forceinline__ uint32_t packbf(float x, float y) {
    bf162 h = __floats2bfloat162_rn(x, y);
    return *(uint32_t*)&h;
}
__device__ __forceinline__ void cstore(float* p, float v) { *p = v; }
__device__ __forceinline__ void cstore(bf16* p, float v) { *p = __float2bfloat16(v); }

// ---------------- fused flash attention ----------------
// grid (3 mtiles, 128 win*head), 256 threads / 8 warps. MT=128 queries, KT=112 keys.
constexpr int FA_KT = 112;
constexpr int FA_ST = 136;  // row stride (elems), 272B = 17*16B (odd -> ldsm conflict-free)

__global__ __launch_bounds__(256, 1) void fattn_k(const bf16* __restrict__ Qg,
                                                  const bf16* __restrict__ Kg,
                                                  const bf16* __restrict__ Vg,
                                                  bf16* __restrict__ Og) {
    int mtile = blockIdx.x;
    int zy = blockIdx.y;
    int win = zy >> 2, head = zy & 3;
    int wl = win & 15;
    int mwh = wl >> 2, mww = wl & 3;

    extern __shared__ bf16 sm[];
    bf16* Ks = sm;                         // [2][FA_KT*FA_ST]
    bf16* Vs = sm + 2 * FA_KT * FA_ST;     // [2][FA_KT*FA_ST]
    uint32_t sK = (uint32_t)__cvta_generic_to_shared(Ks);
    uint32_t sV = (uint32_t)__cvta_generic_to_shared(Vs);

    int tid = threadIdx.x, wp = tid >> 5, lane = tid & 31;
    int g = lane >> 2, t = lane & 3;

    const bf16* Qbase = Qg + ((long long)win * 360) * 512 + head * 128;
    const bf16* Kbase = Kg + ((long long)win * 1680) * 512 + head * 128;
    const bf16* Vbase = Vg + ((long long)win * 1680) * 512 + head * 128;

    // ---- load Q tile (128 x 128) into Ks area, extract frags, release ----
    #pragma unroll
    for (int i = 0; i < 8; i++) {
        int idx = tid + i * 256;
        int r = idx >> 4, c = (idx & 15) << 3;
        int q = mtile * 128 + r;
        cpasync16(sK + (uint32_t)((r * FA_ST + c) * 2),
                  Qbase + (long long)q * 512 + c, q < 360);
    }
    asm volatile("cp.async.commit_group;\n");
    asm volatile("cp.async.wait_group 0;\n");
    __syncthreads();
    uint32_t qa[8][4];
    #pragma unroll
    for (int ks = 0; ks < 8; ks++) {
        uint32_t ad = sK + (uint32_t)((((wp << 4) + (lane & 15)) * FA_ST
                                       + ks * 16 + ((lane >> 4) << 3)) * 2);
        ldsm4(qa[ks][0], qa[ks][1], qa[ks][2], qa[ks][3], ad);
    }
    __syncthreads();

    auto loadKV = [&](int stage, int kt) {
        #pragma unroll
        for (int i = 0; i < 7; i++) {
            int idx = tid + i * 256;
            int r = idx >> 4, c = (idx & 15) << 3;
            long long j = (long long)kt * FA_KT + r;
            uint32_t off = (uint32_t)((stage * FA_KT * FA_ST + r * FA_ST + c) * 2);
            cpasync16(sK + off, Kbase + j * 512 + c, true);
            cpasync16(sV + off, Vbase + j * 512 + c, true);
        }
    };

    float m0 = -1e30f, m1 = -1e30f, l0 = 0.f, l1 = 0.f;
    float o[16][4];
    #pragma unroll
    for (int i = 0; i < 16; i++)
        #pragma unroll
        for (int q = 0; q < 4; q++) o[i][q] = 0.f;

    loadKV(0, 0);
    asm volatile("cp.async.commit_group;\n");

    for (int kt = 0; kt < 15; kt++) {
        if (kt + 1 < 15) loadKV((kt + 1) & 1, kt + 1);
        asm volatile("cp.async.commit_group;\n");
        asm volatile("cp.async.wait_group %0;\n" :: "n"(1));
        __syncthreads();

        uint32_t bK = sK + (uint32_t)((kt & 1) * FA_KT * FA_ST * 2);
        uint32_t bV = sV + (uint32_t)((kt & 1) * FA_KT * FA_ST * 2);

        // ---- S = Q @ K^T for this warp's 16 rows x 112 keys ----
        float c[14][4];
        #pragma unroll
        for (int n = 0; n < 14; n++)
            #pragma unroll
            for (int q = 0; q < 4; q++) c[n][q] = 0.f;

        #pragma unroll
        for (int ks = 0; ks < 8; ks++) {
            #pragma unroll
            for (int h = 0; h < 7; h++) {
                uint32_t b[4];
                uint32_t bd = bK + (uint32_t)(((h * 16 + (lane & 7) + ((lane >> 4) << 3)) * FA_ST
                                              + ks * 16 + (((lane >> 3) & 1) << 3)) * 2);
                ldsm4(b[0], b[1], b[2], b[3], bd);
                mma16816(c[2 * h], qa[ks], b);
                mma16816(c[2 * h + 1], qa[ks], b + 2);
            }
        }

        // ---- pooled-key mask (keys >= 1320) ----
        if (kt >= 11) {
            #pragma unroll
            for (int n = 0; n < 14; n++) {
                #pragma unroll
                for (int e = 0; e < 2; e++) {
                    int j = kt * FA_KT + n * 8 + 2 * t + e;
                    if (j >= 1320) {
                        int a = (j - 1320) % 45;
                        int gi = mwh + a / 9 - 2, gj = mww + a % 9 - 4;
                        if (gi < 0 || gi > 3 || gj < 0 || gj > 3) {
                            c[n][e] -= 100.f;
                            c[n][e + 2] -= 100.f;
                        }
                    }
                }
            }
        }

        // ---- online softmax ----
        float r0 = -1e30f, r1 = -1e30f;
        #pragma unroll
        for (int n = 0; n < 14; n++) {
            r0 = fmaxf(r0, fmaxf(c[n][0], c[n][1]));
            r1 = fmaxf(r1, fmaxf(c[n][2], c[n][3]));
        }
        r0 = fmaxf(r0, __shfl_xor_sync(0xffffffffu, r0, 1));
        r0 = fmaxf(r0, __shfl_xor_sync(0xffffffffu, r0, 2));
        r1 = fmaxf(r1, __shfl_xor_sync(0xffffffffu, r1, 1));
        r1 = fmaxf(r1, __shfl_xor_sync(0xffffffffu, r1, 2));
        float mn0 = fmaxf(m0, r0), mn1 = fmaxf(m1, r1);
        float sc0 = __expf(m0 - mn0), sc1 = __expf(m1 - mn1);
        m0 = mn0; m1 = mn1;
        float s0 = 0.f, s1 = 0.f;
        #pragma unroll
        for (int n = 0; n < 14; n++) {
            c[n][0] = __expf(c[n][0] - mn0);
            c[n][1] = __expf(c[n][1] - mn0);
            c[n][2] = __expf(c[n][2] - mn1);
            c[n][3] = __expf(c[n][3] - mn1);
            s0 += c[n][0] + c[n][1];
            s1 += c[n][2] + c[n][3];
        }
        s0 += __shfl_xor_sync(0xffffffffu, s0, 1);
        s0 += __shfl_xor_sync(0xffffffffu, s0, 2);
        s1 += __shfl_xor_sync(0xffffffffu, s1, 1);
        s1 += __shfl_xor_sync(0xffffffffu, s1, 2);
        l0 = l0 * sc0 + s0;
        l1 = l1 * sc1 + s1;
        #pragma unroll
        for (int i = 0; i < 16; i++) {
            o[i][0] *= sc0; o[i][1] *= sc0;
            o[i][2] *= sc1; o[i][3] *= sc1;
        }

        // ---- O += P @ V ----
        #pragma unroll
        for (int kk = 0; kk < 7; kk++) {
            uint32_t a[4];
            a[0] = packbf(c[2 * kk][0], c[2 * kk][1]);
            a[1] = packbf(c[2 * kk][2], c[2 * kk][3]);
            a[2] = packbf(c[2 * kk + 1][0], c[2 * kk + 1][1]);
            a[3] = packbf(c[2 * kk + 1][2], c[2 * kk + 1][3]);
            #pragma unroll
            for (int h = 0; h < 8; h++) {
                uint32_t b[4];
                uint32_t bd = bV + (uint32_t)(((kk * 16 + (lane & 7) + (((lane >> 3) & 1) << 3)) * FA_ST
                                              + h * 16 + ((lane >> 4) << 3)) * 2);
                ldsm4t(b[0], b[1], b[2], b[3], bd);
                mma16816(o[2 * h], a, b);
                mma16816(o[2 * h + 1], a, b + 2);
            }
        }
        __syncthreads();
    }

    // ---- normalize + store ----
    float il0 = 1.f / l0, il1 = 1.f / l1;
    int q0 = mtile * 128 + wp * 16 + g;
    #pragma unroll
    for (int h = 0; h < 16; h++) {
        int col = head * 128 + h * 8 + 2 * t;
        if (q0 < 360) {
            bf162 v = __floats2bfloat162_rn(o[h][0] * il0, o[h][1] * il0);
            *(bf162*)(Og + ((long long)win * 360 + q0) * 512 + col) = v;
        }
        if (q0 + 8 < 360) {
            bf162 v = __floats2bfloat162_rn(o[h][2] * il1, o[h][3] * il1);
            *(bf162*)(Og + ((long long)win * 360 + q0 + 8) * 512 + col) = v;
        }
    }
}

// ---------------- bf16 tensor-core GEMM (dense layers) ----------------
template <bool TRANSB, typename OutT>
__global__ __launch_bounds__(256) void tgemm_k(
    const bf16* __restrict__ A, const bf16* __restrict__ Bm,
    const float* __restrict__ bias, const float* __restrict__ res,
    OutT* __restrict__ Cm,
    int M, int N, int K, int lda, int ldb, int ldc,
    long long sAo, long long sAi, long long sBo, long long sBi,
    long long sCo, long long sCi, int inner) {
    constexpr int BM = 128, BN = 64, BK = 32;
    constexpr int AST = BK + 8;
    constexpr int BST = TRANSB ? (BK + 8) : (BN + 8);
    constexpr int ASTAGE = BM * AST;
    constexpr int BSTAGE = TRANSB ? (BN * BST) : (BK * BST);

    extern __shared__ bf16 smem[];
    bf16* As = smem;
    bf16* Bs = smem + 2 * ASTAGE;

    int z = blockIdx.z;
    int zo = z / inner, zi = z - zo * inner;
    A += zo * sAo + zi * sAi;
    Bm += zo * sBo + zi * sBi;
    long long coff = zo * sCo + zi * sCi;
    Cm += coff;
    if (res) res += coff;

    int tid = threadIdx.x;
    int row0 = blockIdx.y * BM, col0 = blockIdx.x * BN;
    int wid = tid >> 5, lane = tid & 31;
    int wm = wid & 3, wn = wid >> 2;
    int g = lane >> 2, t = lane & 3;

    uint32_t sA0 = (uint32_t)__cvta_generic_to_shared(As);
    uint32_t sB0 = (uint32_t)__cvta_generic_to_shared(Bs);

    int ktiles = (K + BK - 1) / BK;

    auto load_tile = [&](int stage, int k0) {
        #pragma unroll
        for (int i = 0; i < 2; i++) {
            int idx = tid + i * 256;
            int r = idx >> 2, kc = (idx & 3) << 3;
            int gr = row0 + r, gk = k0 + kc;
            bool ok = (gr < M) && (gk < K);
            uint32_t sa = sA0 + (uint32_t)((stage * ASTAGE + r * AST + kc) * 2);
            cpasync16(sa, A + (long long)gr * lda + gk, ok);
        }
        if (TRANSB) {
            int idx = tid;
            int n = idx >> 2, kc = (idx & 3) << 3;
            int gn = col0 + n, gk = k0 + kc;
            bool ok = (gn < N) && (gk < K);
            uint32_t sb = sB0 + (uint32_t)((stage * BSTAGE + n * BST + kc) * 2);
            cpasync16(sb, Bm + (long long)gn * ldb + gk, ok);
        } else {
            int idx = tid;
            int kk = idx >> 3, nc = (idx & 7) << 3;
            int gk = k0 + kk, gn = col0 + nc;
            bool ok = (gk < K) && (gn < N);
            uint32_t sb = sB0 + (uint32_t)((stage * BSTAGE + kk * BST + nc) * 2);
            cpasync16(sb, Bm + (long long)gk * ldb + gn, ok);
        }
    };

    float acc[2][4][4];
    #pragma unroll
    for (int mi = 0; mi < 2; mi++)
        #pragma unroll
        for (int ni = 0; ni < 4; ni++)
            #pragma unroll
            for (int q = 0; q < 4; q++) acc[mi][ni][q] = 0.f;

    load_tile(0, 0);
    asm volatile("cp.async.commit_group;\n");

    for (int kt = 0; kt < ktiles; kt++) {
        if (kt + 1 < ktiles) load_tile((kt + 1) & 1, (kt + 1) * BK);
        asm volatile("cp.async.commit_group;\n");
        asm volatile("cp.async.wait_group %0;\n" :: "n"(1));
        __syncthreads();

        uint32_t sAb = sA0 + (uint32_t)((kt & 1) * ASTAGE * 2);
        uint32_t sBb = sB0 + (uint32_t)((kt & 1) * BSTAGE * 2);

        #pragma unroll
        for (int ks = 0; ks < 2; ks++) {
            uint32_t a[2][4], b[4][2];
            #pragma unroll
            for (int mi = 0; mi < 2; mi++) {
                int row = wm * 32 + mi * 16 + (lane & 15);
                uint32_t ad = sAb + (uint32_t)((row * AST + ks * 16 + ((lane >> 4) << 3)) * 2);
                ldsm4(a[mi][0], a[mi][1], a[mi][2], a[mi][3], ad);
            }
            #pragma unroll
            for (int h = 0; h < 2; h++) {
                if (TRANSB) {
                    int rown = wn * 32 + h * 16 + (lane & 7) + ((lane >> 4) << 3);
                    uint32_t bd = sBb + (uint32_t)((rown * BST + ks * 16 + (((lane >> 3) & 1) << 3)) * 2);
                    ldsm4(b[2 * h][0], b[2 * h][1], b[2 * h + 1][0], b[2 * h + 1][1], bd);
                } else {
                    int rowk = ks * 16 + (lane & 7) + (((lane >> 3) & 1) << 3);
                    int coln = wn * 32 + h * 16 + ((lane >> 4) << 3);
                    uint32_t bd = sBb + (uint32_t)((rowk * BST + coln) * 2);
                    ldsm4t(b[2 * h][0], b[2 * h][1], b[2 * h + 1][0], b[2 * h + 1][1], bd);
                }
            }
            #pragma unroll
            for (int mi = 0; mi < 2; mi++)
                #pragma unroll
                for (int ni = 0; ni < 4; ni++)
                    mma16816(acc[mi][ni], a[mi], b[ni]);
        }
        __syncthreads();
    }

    #pragma unroll
    for (int mi = 0; mi < 2; mi++) {
        int r = row0 + wm * 32 + mi * 16 + g;
        #pragma unroll
        for (int ni = 0; ni < 4; ni++) {
            int c = col0 + wn * 32 + ni * 8 + 2 * t;
            #pragma unroll
            for (int q = 0; q < 4; q++) {
                int rr = r + (q >> 1) * 8;
                int cc = c + (q & 1);
                if (rr < M && cc < N) {
                    float v = acc[mi][ni][q];
                    if (bias) v += bias[cc];
                    long long ci = (long long)rr * ldc + cc;
                    if (res) v += res[ci];
                    cstore(Cm + ci, v);
                }
            }
        }
    }
}

// ---------------- scatter window->spatial + residual ----------------
__global__ __launch_bounds__(256) void addres_k(const float* __restrict__ x,
                                                const float* __restrict__ Pw,
                                                float* __restrict__ xres) {
    int idx = blockIdx.x * 256 + threadIdx.x;
    int n = idx >> 7, c4 = idx & 127;
    int w = n % 36;
    int h = (n / 36) % 20;
    int bt = n / 720;
    int b = bt >> 3, t = bt & 7;
    int wh = h / 5, ih = h - wh * 5, ww = w / 9, iw = w - ww * 9;
    int win = b * 16 + wh * 4 + ww;
    int q = t * 45 + ih * 9 + iw;
    long long r = (long long)win * 360 + q;
    float4 xv = ((const float4*)x)[idx];
    float4 pv = ((const float4*)Pw)[r * 128 + c4];
    xv.x += pv.x; xv.y += pv.y; xv.z += pv.z; xv.w += pv.w;
    ((float4*)xres)[idx] = xv;
}

// ---------------- T2T fold (gather form) + normalize ----------------
__global__ __launch_bounds__(256) void t2tfold_k(const float* __restrict__ h1,
                                                 float* __restrict__ I) {
    int idx = blockIdx.x * 256 + threadIdx.x;
    if (idx >= 16 * 40 * 60 * 108) return;
    int x = idx % 108;
    int y = (idx / 108) % 60;
    int c40 = (idx / (108 * 60)) % 40;
    int g = idx / (108 * 60 * 40);
    int pys[3], kis[3], pxs[3], kjs[3];
    int cy = 0, cx = 0;
    #pragma unroll
    for (int dp = 0; dp < 3; dp++) {
        int py = (y + 3) / 3 - dp;
        int ki = y + 3 - 3 * py;
        if (py >= 0 && py < 20 && ki < 7) { pys[cy] = py; kis[cy] = ki; cy++; }
        int px = (x + 3) / 3 - dp;
        int kj = x + 3 - 3 * px;
        if (px >= 0 && px < 36 && kj < 7) { pxs[cx] = px; kjs[cx] = kj; cx++; }
    }
    float s = 0.f;
    for (int a = 0; a < cy; a++)
        for (int bb = 0; bb < cx; bb++) {
            long long r = (long long)g * 720 + pys[a] * 36 + pxs[bb];
            s += h1[r * 1960 + c40 * 49 + kis[a] * 7 + kjs[bb]];
        }
    I[idx] = s / (float)(cy * cx);
}

// ---------------- T2T unfold + exact GELU (bf16 out) ----------------
__global__ __launch_bounds__(256) void t2tunf_k(const float* __restrict__ I,
                                                bf16* __restrict__ h2) {
    int idx = blockIdx.x * 256 + threadIdx.x;
    if (idx >= TOK * FFN) return;
    int c = idx % 1960;
    int r = idx / 1960;
    int g = r / 720;
    int p = r - g * 720;
    int py = p / 36, px = p - py * 36;
    int c40 = c / 49;
    int kk = c - c40 * 49;
    int ki = kk / 7, kj = kk - ki * 7;
    int y = py * 3 + ki - 3, x = px * 3 + kj - 3;
    float v = 0.f;
    if (y >= 0 && y < 60 && x >= 0 && x < 108)
        v = I[(((long long)g * 40 + c40) * 60 + y) * 108 + x];
    h2[idx] = __float2bfloat16(0.5f * v * (1.f + erff(v * 0.7071067811865475f)));
}

// ---------------- host launch ----------------
#define SYM(T, p, s) T* p; do { void* _t = nullptr; cudaGetSymbolAddress(&_t, s); (p) = (T*)_t; } while (0)

template <bool TRANSB, typename OutT>
static void run_tgemm(const bf16* A, const bf16* Bm, const float* bias,
                      const float* res, OutT* C, int M, int N, int K,
                      int lda, int ldb, int ldc,
                      long long sAo, long long sAi, long long sBo, long long sBi,
                      long long sCo, long long sCi, int inner, int batch) {
    dim3 grid((N + 63) / 64, (M + 127) / 128, batch);
    size_t sm = (2 * 128 * 40 + 2 * (TRANSB ? 64 * 40 : 32 * 72)) * sizeof(bf16);
    cudaFuncSetAttribute(tgemm_k<TRANSB, OutT>, cudaFuncAttributeMaxDynamicSharedMemorySize, (int)sm);
    tgemm_k<TRANSB, OutT><<<grid, 256, sm>>>(A, Bm, bias, res, C, M, N, K, lda, ldb, ldc,
                                             sAo, sAi, sBo, sBi, sCo, sCi, inner);
}

extern "C" void kernel_launch(void* const* d_in, const int* in_sizes, int n_in,
                              void* d_out, int out_size) {
    const float* x     = (const float*)d_in[0];
    const float* g1    = (const float*)d_in[1];
    const float* be1   = (const float*)d_in[2];
    const float* wqkv  = (const float*)d_in[3];
    const float* bqkv  = (const float*)d_in[4];
    const float* wproj = (const float*)d_in[5];
    const float* bproj = (const float*)d_in[6];
    const float* wpool = (const float*)d_in[7];
    const float* bpool = (const float*)d_in[8];
    const float* g2    = (const float*)d_in[9];
    const float* be2   = (const float*)d_in[10];
    const float* w1    = (const float*)d_in[11];
    const float* bf1   = (const float*)d_in[12];
    const float* w2    = (const float*)d_in[13];
    const float* bf2   = (const float*)d_in[14];
    float* out = (float*)d_out;

    SYM(bf16, xn, g_xn); SYM(bf16, qkv, g_qkv); SYM(bf16, pooled, g_pooled);
    SYM(bf16, qkvp, g_qkvp); SYM(bf16, Q, g_Q); SYM(bf16, K, g_K); SYM(bf16, V, g_V);
    SYM(bf16, h2, g_h2); SYM(bf16, Aw, g_Aw); SYM(float, Pw, g_Pw);
    SYM(float, xres, g_xres); SYM(float, h1, g_h1); SYM(float, I, g_I);
    SYM(bf16, wqkvb, g_wqkvb); SYM(bf16, wprojb, g_wprojb);
    SYM(bf16, w1b, g_w1b); SYM(bf16, w2b, g_w2b);

    initvalid_k<<<1, 32>>>();
    convw_k<<<(512 * 1536 + 255) / 256, 256>>>(wqkv, wqkvb, 512 * 1536);
    convw_k<<<(512 * 512 + 255) / 256, 256>>>(wproj, wprojb, 512 * 512);
    convw_k<<<(512 * 1960 + 255) / 256, 256>>>(w1, w1b, 512 * 1960);
    convw_k<<<(1960 * 512 + 255) / 256, 256>>>(w2, w2b, 1960 * 512);

    ln_k<<<TOK, 128>>>(x, g1, be1, xn);
    run_tgemm<false, bf16>(xn, wqkvb, bqkv, nullptr, qkv, TOK, 1536, 512, 512, 1536, 1536,
                           0, 0, 0, 0, 0, 0, 1, 1);
    pool_k<<<1024, 128>>>(xn, wpool, bpool, pooled);
    run_tgemm<false, bf16>(pooled, wqkvb, bqkv, nullptr, qkvp, 256, 1536, 512, 512, 1536, 1536,
                           0, 0, 0, 0, 0, 0, 1, 1);
    gatherq_k<<<TOK, 128>>>(qkv, Q);
    gatherkv_k<<<NWIN * NK, 128>>>(qkv, qkvp, K, V);

    // fused flash attention: scores + mask + softmax + PV -> Aw (bf16)
    {
        size_t smfa = (size_t)4 * FA_KT * FA_ST * sizeof(bf16);  // K,V double-buffered
        cudaFuncSetAttribute(fattn_k, cudaFuncAttributeMaxDynamicSharedMemorySize, (int)smfa);
        fattn_k<<<dim3(3, 128), 256, smfa>>>(Q, K, V, Aw);
    }

    run_tgemm<false, float>(Aw, wprojb, bproj, nullptr, Pw, TOK, 512, 512, 512, 512, 512,
                            0, 0, 0, 0, 0, 0, 1, 1);
    addres_k<<<TOK * 128 / 256, 256>>>(x, Pw, xres);
    ln_k<<<TOK, 128>>>(xres, g2, be2, xn);
    run_tgemm<false, float>(xn, w1b, bf1, nullptr, h1, TOK, FFN, 512, 512, FFN, FFN,
                            0, 0, 0, 0, 0, 0, 1, 1);
    t2tfold_k<<<(16 * 40 * 60 * 108 + 255) / 256, 256>>>(h1, I);
    t2tunf_k<<<(TOK * FFN + 255) / 256, 256>>>(I, h2);
    run_tgemm<false, float>(h2, w2b, bf2, xres, out, TOK, 512, FFN, FFN, 512, 512,
                            0, 0, 0, 0, 0, 0, 1, 1);
}

// round 7
// speedup vs baseline: 8.4340x; 1.1314x over previous
#include <cuda_runtime.h>
#include <cuda_bf16.h>
#include <math.h>
#include <stdint.h>

// ---------------- constants ----------------
constexpr int NWIN = 32;
constexpr int NQ = 360;
constexpr int NK = 1680;
constexpr int TOK = 11520;
constexpr int FFN = 1960;
constexpr int Cch = 512;
constexpr float QSCALE = 0.08838834764831845f;

typedef __nv_bfloat16 bf16;
typedef __nv_bfloat162 bf162;

// ---------------- scratch ----------------
__device__ bf16  g_xn[TOK * Cch];
__device__ bf16  g_qkv[TOK * 3 * Cch];
__device__ bf16  g_pooled[256 * Cch];
__device__ bf16  g_qkvp[256 * 3 * Cch];
__device__ bf16  g_Aw[TOK * Cch];
__device__ float g_Pw[TOK * Cch];
__device__ float g_xres[TOK * Cch];
__device__ bf16  g_hb[TOK * FFN];          // h1 (pre-fold) then h2 (post-GELU)
__device__ float g_I[16 * 40 * 60 * 108];
__device__ int   g_valid[120];
__device__ int   g_qidx[NWIN * NQ];
__device__ int   g_kidx[NWIN * NK];
__device__ bf16  g_wqkvb[512 * 1536];
__device__ bf16  g_wprojb[512 * 512];
__device__ bf16  g_w1b[512 * 1960];
__device__ bf16  g_w2b[1960 * 512];

// ---------------- init valid-rolled table ----------------
__global__ void initvalid_k() {
    if (threadIdx.x == 0 && blockIdx.x == 0) {
        int n = 0;
        for (int s = 0; s < 4; s++)
            for (int ih = 0; ih < 5; ih++)
                for (int iw = 0; iw < 9; iw++) {
                    bool zero;
                    if (s == 0) zero = (ih < 3 && iw < 5);
                    else if (s == 1) zero = (ih < 3 && iw >= 4);
                    else if (s == 2) zero = (ih >= 2 && iw < 5);
                    else zero = (ih >= 2 && iw >= 4);
                    if (!zero) g_valid[n++] = s * 45 + ih * 9 + iw;
                }
    }
}

// ---------------- build gather index tables ----------------
__global__ __launch_bounds__(256) void idx_k(int* __restrict__ qidx,
                                             int* __restrict__ kidx) {
    int i = blockIdx.x * 256 + threadIdx.x;
    if (i < NWIN * NQ) {
        int win = i / NQ, q = i - win * NQ;
        int b = win >> 4, wh = (win >> 2) & 3, ww = win & 3;
        int t = q / 45, a = q - t * 45, ih = a / 9, iw = a % 9;
        qidx[i] = ((b * 8 + t) * 20 + wh * 5 + ih) * 36 + ww * 9 + iw;
    }
    if (i < NWIN * NK) {
        int win = i / NK, j = i - win * NK;
        int b = win >> 4, wh = (win >> 2) & 3, ww = win & 3;
        int e = -1;
        if (j < 360) {
            int t = j / 45, a = j - t * 45, ih = a / 9, iw = a % 9;
            e = ((b * 8 + t) * 20 + wh * 5 + ih) * 36 + ww * 9 + iw;
        } else if (j < 1320) {
            int jj = j - 360;
            int t = jj / 120, vi = jj - t * 120;
            int f = g_valid[vi];
            int s = f / 45, a = f - s * 45, ih = a / 9, iw = a % 9;
            int sh = (s < 2) ? -2 : 2;
            int sw = (s & 1) ? 4 : -4;
            int hh = wh * 5 + ih - sh; hh %= 20; if (hh < 0) hh += 20;
            int wp = ww * 9 + iw - sw; wp %= 36; if (wp < 0) wp += 36;
            e = ((b * 8 + t) * 20 + hh) * 36 + wp;
        } else {
            int jj = j - 1320;
            int t = jj / 45, a = jj - t * 45, ii = a / 9, jx = a % 9;
            int gi = wh + ii - 2, gj = ww + jx - 4;
            if (gi >= 0 && gi < 4 && gj >= 0 && gj < 4)
                e = TOK + (b * 8 + t) * 16 + gi * 4 + gj;
        }
        kidx[i] = e;
    }
}

// ---------------- weight fp32 -> bf16 ----------------
__global__ __launch_bounds__(256) void convw_k(const float* __restrict__ s,
                                               bf16* __restrict__ d, int n) {
    int i = blockIdx.x * 256 + threadIdx.x;
    if (i < n) d[i] = __float2bfloat16(s[i]);
}

// ---------------- LayerNorm (fp32 in, bf16 out) ----------------
__global__ __launch_bounds__(128) void ln_k(const float* __restrict__ in,
                                            const float* __restrict__ g,
                                            const float* __restrict__ b,
                                            bf16* __restrict__ out) {
    int row = blockIdx.x;
    const float4* xp = (const float4*)(in + (long long)row * 512);
    float4 v = xp[threadIdx.x];
    float s = v.x + v.y + v.z + v.w;
    __shared__ float red[4], red2[4];
    #pragma unroll
    for (int o = 16; o; o >>= 1) s += __shfl_xor_sync(0xffffffffu, s, o);
    int wid = threadIdx.x >> 5, lane = threadIdx.x & 31;
    if (lane == 0) red[wid] = s;
    __syncthreads();
    float mu = (red[0] + red[1] + red[2] + red[3]) * (1.f / 512.f);
    float dx = v.x - mu, dy = v.y - mu, dz = v.z - mu, dw = v.w - mu;
    float sq = dx * dx + dy * dy + dz * dz + dw * dw;
    #pragma unroll
    for (int o = 16; o; o >>= 1) sq += __shfl_xor_sync(0xffffffffu, sq, o);
    if (lane == 0) red2[wid] = sq;
    __syncthreads();
    float var = (red2[0] + red2[1] + red2[2] + red2[3]) * (1.f / 512.f);
    float inv = rsqrtf(var + 1e-5f);
    float4 gg = ((const float4*)g)[threadIdx.x];
    float4 bb = ((const float4*)b)[threadIdx.x];
    bf162 o0 = __floats2bfloat162_rn(dx * inv * gg.x + bb.x, dy * inv * gg.y + bb.y);
    bf162 o1 = __floats2bfloat162_rn(dz * inv * gg.z + bb.z, dw * inv * gg.w + bb.w);
    bf162* op = (bf162*)(out + (long long)row * 512);
    op[2 * threadIdx.x] = o0;
    op[2 * threadIdx.x + 1] = o1;
}

// ---------------- window pooling ----------------
__global__ __launch_bounds__(128) void pool_k(const bf16* __restrict__ xn,
                                              const float* __restrict__ wpool,
                                              const float* __restrict__ bpool,
                                              bf16* __restrict__ pooled) {
    int widx = blockIdx.x >> 2;
    int c = ((blockIdx.x & 3) << 7) + threadIdx.x;
    int ww = widx & 3, wh = (widx >> 2) & 3, bt = widx >> 4;
    float s = 0.f;
    #pragma unroll
    for (int a = 0; a < 45; a++) {
        int ih = a / 9, iw = a % 9;
        long long tok = ((long long)bt * 20 + wh * 5 + ih) * 36 + ww * 9 + iw;
        s += __bfloat162float(xn[tok * 512 + c]) * wpool[a];
    }
    pooled[(long long)widx * 512 + c] = __float2bfloat16(s + bpool[0]);
}

// ---------------- common PTX helpers ----------------
__device__ __forceinline__ void cpasync16(uint32_t saddr, const void* gaddr, bool pred) {
    int sz = pred ? 16 : 0;
    asm volatile("cp.async.cg.shared.global [%0], [%1], 16, %2;\n"
                 :: "r"(saddr), "l"(gaddr), "r"(sz));
}
__device__ __forceinline__ void ldsm4(uint32_t& r0, uint32_t& r1, uint32_t& r2, uint32_t& r3,
                                      uint32_t a) {
    asm volatile("ldmatrix.sync.aligned.m8n8.x4.shared.b16 {%0,%1,%2,%3}, [%4];\n"
                 : "=r"(r0), "=r"(r1), "=r"(r2), "=r"(r3) : "r"(a));
}
__device__ __forceinline__ void ldsm4t(uint32_t& r0, uint32_t& r1, uint32_t& r2, uint32_t& r3,
                                       uint32_t a) {
    asm volatile("ldmatrix.sync.aligned.m8n8.x4.trans.shared.b16 {%0,%1,%2,%3}, [%4];\n"
                 : "=r"(r0), "=r"(r1), "=r"(r2), "=r"(r3) : "r"(a));
}
__device__ __forceinline__ void mma16816(float* c, const uint32_t* a, const uint32_t* b) {
    asm volatile(
        "mma.sync.aligned.m16n8k16.row.col.f32.bf16.bf16.f32 "
        "{%0,%1,%2,%3}, {%4,%5,%6,%7}, {%8,%9}, {%0,%1,%2,%3};\n"
        : "+f"(c[0]), "+f"(c[1]), "+f"(c[2]), "+f"(c[3])
        : "r"(a[0]), "r"(a[1]), "r"(a[2]), "r"(a[3]), "r"(b[0]), "r"(b[1]));
}
__device__ __forceinline__ uint32_t packbf(float x, float y) {
    bf162 h = __floats2bfloat162_rn(x, y);
    return *(uint32_t*)&h;
}
__device__ __forceinline__ void store2(float* p, float x, float y) {
    *(float2*)p = make_float2(x, y);
}
__device__ __forceinline__ void store2(bf16* p, float x, float y) {
    *(bf162*)p = __floats2bfloat162_rn(x, y);
}

// ---------------- fused flash attention (indirect K/V/Q loads) ----------------
constexpr int FA_KT = 112;
constexpr int FA_ST = 136;

__global__ __launch_bounds__(256, 1) void fattn_k(const bf16* __restrict__ qkv,
                                                  const bf16* __restrict__ qkvp,
                                                  const int* __restrict__ qidx,
                                                  const int* __restrict__ kidx,
                                                  bf16* __restrict__ Og) {
    int mtile = blockIdx.x;
    int zy = blockIdx.y;
    int win = zy >> 2, head = zy & 3;
    int wl = win & 15;
    int mwh = wl >> 2, mww = wl & 3;

    extern __shared__ bf16 sm[];
    bf16* Ks = sm;
    bf16* Vs = sm + 2 * FA_KT * FA_ST;
    uint32_t sK = (uint32_t)__cvta_generic_to_shared(Ks);
    uint32_t sV = (uint32_t)__cvta_generic_to_shared(Vs);

    int tid = threadIdx.x, wp = tid >> 5, lane = tid & 31;
    int g = lane >> 2, t = lane & 3;
    int hoff = head * 128;

    // ---- load Q tile (direct from qkv via index table) ----
    #pragma unroll
    for (int i = 0; i < 8; i++) {
        int idx = tid + i * 256;
        int r = idx >> 4, c = (idx & 15) << 3;
        int q = mtile * 128 + r;
        bool ok = q < 360;
        int e = ok ? __ldg(qidx + win * 360 + q) : 0;
        cpasync16(sK + (uint32_t)((r * FA_ST + c) * 2),
                  qkv + (long long)e * 1536 + hoff + c, ok);
    }
    asm volatile("cp.async.commit_group;\n");
    asm volatile("cp.async.wait_group 0;\n");
    __syncthreads();
    uint32_t qa[8][4];
    #pragma unroll
    for (int ks = 0; ks < 8; ks++) {
        uint32_t ad = sK + (uint32_t)((((wp << 4) + (lane & 15)) * FA_ST
                                       + ks * 16 + ((lane >> 4) << 3)) * 2);
        ldsm4(qa[ks][0], qa[ks][1], qa[ks][2], qa[ks][3], ad);
    }
    __syncthreads();

    auto loadKV = [&](int stage, int kt) {
        #pragma unroll
        for (int i = 0; i < 7; i++) {
            int idx = tid + i * 256;
            int r = idx >> 4, c = (idx & 15) << 3;
            int e = __ldg(kidx + win * 1680 + kt * FA_KT + r);
            bool ok = e >= 0;
            const bf16* p = qkv;
            if (ok) p = (e < TOK) ? qkv + (long long)e * 1536
                                  : qkvp + (long long)(e - TOK) * 1536;
            uint32_t off = (uint32_t)((stage * FA_KT * FA_ST + r * FA_ST + c) * 2);
            cpasync16(sK + off, p + 512 + hoff + c, ok);
            cpasync16(sV + off, p + 1024 + hoff + c, ok);
        }
    };

    float m0 = -1e30f, m1 = -1e30f, l0 = 0.f, l1 = 0.f;
    float o[16][4];
    #pragma unroll
    for (int i = 0; i < 16; i++)
        #pragma unroll
        for (int q = 0; q < 4; q++) o[i][q] = 0.f;

    loadKV(0, 0);
    asm volatile("cp.async.commit_group;\n");

    for (int kt = 0; kt < 15; kt++) {
        if (kt + 1 < 15) loadKV((kt + 1) & 1, kt + 1);
        asm volatile("cp.async.commit_group;\n");
        asm volatile("cp.async.wait_group %0;\n" :: "n"(1));
        __syncthreads();

        uint32_t bK = sK + (uint32_t)((kt & 1) * FA_KT * FA_ST * 2);
        uint32_t bV = sV + (uint32_t)((kt & 1) * FA_KT * FA_ST * 2);

        float c[14][4];
        #pragma unroll
        for (int n = 0; n < 14; n++)
            #pragma unroll
            for (int q = 0; q < 4; q++) c[n][q] = 0.f;

        #pragma unroll
        for (int ks = 0; ks < 8; ks++) {
            #pragma unroll
            for (int h = 0; h < 7; h++) {
                uint32_t b[4];
                uint32_t bd = bK + (uint32_t)(((h * 16 + (lane & 7) + ((lane >> 4) << 3)) * FA_ST
                                              + ks * 16 + (((lane >> 3) & 1) << 3)) * 2);
                ldsm4(b[0], b[1], b[2], b[3], bd);
                mma16816(c[2 * h], qa[ks], b);
                mma16816(c[2 * h + 1], qa[ks], b + 2);
            }
        }

        // scale scores (Q was unscaled), then pooled-key mask
        #pragma unroll
        for (int n = 0; n < 14; n++)
            #pragma unroll
            for (int q = 0; q < 4; q++) c[n][q] *= QSCALE;

        if (kt >= 11) {
            #pragma unroll
            for (int n = 0; n < 14; n++) {
                #pragma unroll
                for (int e = 0; e < 2; e++) {
                    int j = kt * FA_KT + n * 8 + 2 * t + e;
                    if (j >= 1320) {
                        int a = (j - 1320) % 45;
                        int gi = mwh + a / 9 - 2, gj = mww + a % 9 - 4;
                        if (gi < 0 || gi > 3 || gj < 0 || gj > 3) {
                            c[n][e] -= 100.f;
                            c[n][e + 2] -= 100.f;
                        }
                    }
                }
            }
        }

        // ---- online softmax ----
        float r0 = -1e30f, r1 = -1e30f;
        #pragma unroll
        for (int n = 0; n < 14; n++) {
            r0 = fmaxf(r0, fmaxf(c[n][0], c[n][1]));
            r1 = fmaxf(r1, fmaxf(c[n][2], c[n][3]));
        }
        r0 = fmaxf(r0, __shfl_xor_sync(0xffffffffu, r0, 1));
        r0 = fmaxf(r0, __shfl_xor_sync(0xffffffffu, r0, 2));
        r1 = fmaxf(r1, __shfl_xor_sync(0xffffffffu, r1, 1));
        r1 = fmaxf(r1, __shfl_xor_sync(0xffffffffu, r1, 2));
        float mn0 = fmaxf(m0, r0), mn1 = fmaxf(m1, r1);
        float sc0 = __expf(m0 - mn0), sc1 = __expf(m1 - mn1);
        m0 = mn0; m1 = mn1;
        float s0 = 0.f, s1 = 0.f;
        #pragma unroll
        for (int n = 0; n < 14; n++) {
            c[n][0] = __expf(c[n][0] - mn0);
            c[n][1] = __expf(c[n][1] - mn0);
            c[n][2] = __expf(c[n][2] - mn1);
            c[n][3] = __expf(c[n][3] - mn1);
            s0 += c[n][0] + c[n][1];
            s1 += c[n][2] + c[n][3];
        }
        s0 += __shfl_xor_sync(0xffffffffu, s0, 1);
        s0 += __shfl_xor_sync(0xffffffffu, s0, 2);
        s1 += __shfl_xor_sync(0xffffffffu, s1, 1);
        s1 += __shfl_xor_sync(0xffffffffu, s1, 2);
        l0 = l0 * sc0 + s0;
        l1 = l1 * sc1 + s1;
        #pragma unroll
        for (int i = 0; i < 16; i++) {
            o[i][0] *= sc0; o[i][1] *= sc0;
            o[i][2] *= sc1; o[i][3] *= sc1;
        }

        // ---- O += P @ V ----
        #pragma unroll
        for (int kk = 0; kk < 7; kk++) {
            uint32_t a[4];
            a[0] = packbf(c[2 * kk][0], c[2 * kk][1]);
            a[1] = packbf(c[2 * kk][2], c[2 * kk][3]);
            a[2] = packbf(c[2 * kk + 1][0], c[2 * kk + 1][1]);
            a[3] = packbf(c[2 * kk + 1][2], c[2 * kk + 1][3]);
            #pragma unroll
            for (int h = 0; h < 8; h++) {
                uint32_t b[4];
                uint32_t bd = bV + (uint32_t)(((kk * 16 + (lane & 7) + (((lane >> 3) & 1) << 3)) * FA_ST
                                              + h * 16 + ((lane >> 4) << 3)) * 2);
                ldsm4t(b[0], b[1], b[2], b[3], bd);
                mma16816(o[2 * h], a, b);
                mma16816(o[2 * h + 1], a, b + 2);
            }
        }
        __syncthreads();
    }

    float il0 = 1.f / l0, il1 = 1.f / l1;
    int q0 = mtile * 128 + wp * 16 + g;
    #pragma unroll
    for (int h = 0; h < 16; h++) {
        int col = hoff + h * 8 + 2 * t;
        if (q0 < 360) {
            bf162 v = __floats2bfloat162_rn(o[h][0] * il0, o[h][1] * il0);
            *(bf162*)(Og + ((long long)win * 360 + q0) * 512 + col) = v;
        }
        if (q0 + 8 < 360) {
            bf162 v = __floats2bfloat162_rn(o[h][2] * il1, o[h][3] * il1);
            *(bf162*)(Og + ((long long)win * 360 + q0 + 8) * 512 + col) = v;
        }
    }
}

// ---------------- bf16 GEMM: BM=128, BN=128, BK=32, 3-stage, 8 warps (4x2) ----------------
constexpr int GBM = 128, GBN = 128, GBK = 32;
constexpr int GAST = GBK + 8;    // 40
constexpr int GBST = GBN + 8;    // 136
constexpr int GASZ = GBM * GAST; // 5120
constexpr int GBSZ = GBK * GBST; // 4352

template <typename OutT>
__global__ __launch_bounds__(256, 2) void tgemm_k(
    const bf16* __restrict__ A, const bf16* __restrict__ Bm,
    const float* __restrict__ bias, const float* __restrict__ res,
    OutT* __restrict__ Cm, int M, int N, int K) {
    extern __shared__ bf16 smem[];
    bf16* As = smem;
    bf16* Bs = smem + 3 * GASZ;

    int tid = threadIdx.x;
    int row0 = blockIdx.y * GBM, col0 = blockIdx.x * GBN;
    int wid = tid >> 5, lane = tid & 31;
    int wm = wid & 3, wn = wid >> 2;
    int g = lane >> 2, t = lane & 3;

    uint32_t sA0 = (uint32_t)__cvta_generic_to_shared(As);
    uint32_t sB0 = (uint32_t)__cvta_generic_to_shared(Bs);
    int ktiles = (K + GBK - 1) / GBK;

    auto load_tile = [&](int stage, int k0) {
        #pragma unroll
        for (int i = 0; i < 2; i++) {
            int idx = tid + i * 256;
            int r = idx >> 2, kc = (idx & 3) << 3;
            bool ok = (k0 + kc) < K;   // M % 128 == 0 for all calls
            cpasync16(sA0 + (uint32_t)((stage * GASZ + r * GAST + kc) * 2),
                      A + (long long)(row0 + r) * K + k0 + kc, ok);
        }
        #pragma unroll
        for (int i = 0; i < 2; i++) {
            int idx = tid + i * 256;
            int kk = idx >> 4, nc = (idx & 15) << 3;
            int gn = col0 + nc;
            bool ok = ((k0 + kk) < K) && (gn < N);
            cpasync16(sB0 + (uint32_t)((stage * GBSZ + kk * GBST + nc) * 2),
                      Bm + (long long)(k0 + kk) * N + gn, ok);
        }
    };

    float acc[2][8][4];
    #pragma unroll
    for (int mi = 0; mi < 2; mi++)
        #pragma unroll
        for (int ni = 0; ni < 8; ni++)
            #pragma unroll
            for (int q = 0; q < 4; q++) acc[mi][ni][q] = 0.f;

    load_tile(0, 0);
    asm volatile("cp.async.commit_group;\n");
    load_tile(1, GBK);
    asm volatile("cp.async.commit_group;\n");

    for (int kt = 0; kt < ktiles; kt++) {
        asm volatile("cp.async.wait_group %0;\n" :: "n"(1));
        __syncthreads();
        if (kt + 2 < ktiles) load_tile((kt + 2) % 3, (kt + 2) * GBK);
        asm volatile("cp.async.commit_group;\n");

        uint32_t sAb = sA0 + (uint32_t)((kt % 3) * GASZ * 2);
        uint32_t sBb = sB0 + (uint32_t)((kt % 3) * GBSZ * 2);

        #pragma unroll
        for (int ks = 0; ks < 2; ks++) {
            uint32_t a[2][4], b[8][2];
            #pragma unroll
            for (int mi = 0; mi < 2; mi++) {
                int row = wm * 32 + mi * 16 + (lane & 15);
                uint32_t ad = sAb + (uint32_t)((row * GAST + ks * 16 + ((lane >> 4) << 3)) * 2);
                ldsm4(a[mi][0], a[mi][1], a[mi][2], a[mi][3], ad);
            }
            #pragma unroll
            for (int h = 0; h < 4; h++) {
                int rowk = ks * 16 + (lane & 7) + (((lane >> 3) & 1) << 3);
                int coln = wn * 64 + h * 16 + ((lane >> 4) << 3);
                uint32_t bd = sBb + (uint32_t)((rowk * GBST + coln) * 2);
                ldsm4t(b[2 * h][0], b[2 * h][1], b[2 * h + 1][0], b[2 * h + 1][1], bd);
            }
            #pragma unroll
            for (int mi = 0; mi < 2; mi++)
                #pragma unroll
                for (int ni = 0; ni < 8; ni++)
                    mma16816(acc[mi][ni], a[mi], b[ni]);
        }
    }

    #pragma unroll
    for (int mi = 0; mi < 2; mi++) {
        int r = row0 + wm * 32 + mi * 16 + g;
        #pragma unroll
        for (int ni = 0; ni < 8; ni++) {
            int cidx = col0 + wn * 64 + ni * 8 + 2 * t;
            if (cidx < N) {
                float b0 = bias ? bias[cidx] : 0.f;
                float b1 = bias ? bias[cidx + 1] : 0.f;
                float x0 = acc[mi][ni][0] + b0, x1 = acc[mi][ni][1] + b1;
                float x2 = acc[mi][ni][2] + b0, x3 = acc[mi][ni][3] + b1;
                long long i0 = (long long)r * N + cidx;
                long long i1 = (long long)(r + 8) * N + cidx;
                if (res) {
                    float2 r0 = *(const float2*)(res + i0);
                    float2 r1 = *(const float2*)(res + i1);
                    x0 += r0.x; x1 += r0.y; x2 += r1.x; x3 += r1.y;
                }
                store2(Cm + i0, x0, x1);
                store2(Cm + i1, x2, x3);
            }
        }
    }
}

// ---------------- scatter window->spatial + residual ----------------
__global__ __launch_bounds__(256) void addres_k(const float* __restrict__ x,
                                                const float* __restrict__ Pw,
                                                float* __restrict__ xres) {
    int idx = blockIdx.x * 256 + threadIdx.x;
    int n = idx >> 7, c4 = idx & 127;
    int w = n % 36;
    int h = (n / 36) % 20;
    int bt = n / 720;
    int b = bt >> 3, t = bt & 7;
    int wh = h / 5, ih = h - wh * 5, ww = w / 9, iw = w - ww * 9;
    int win = b * 16 + wh * 4 + ww;
    int q = t * 45 + ih * 9 + iw;
    long long r = (long long)win * 360 + q;
    float4 xv = ((const float4*)x)[idx];
    float4 pv = ((const float4*)Pw)[r * 128 + c4];
    xv.x += pv.x; xv.y += pv.y; xv.z += pv.z; xv.w += pv.w;
    ((float4*)xres)[idx] = xv;
}

// ---------------- T2T fold (gather form, bf16 in) + normalize ----------------
__global__ __launch_bounds__(256) void t2tfold_k(const bf16* __restrict__ h1,
                                                 float* __restrict__ I) {
    int idx = blockIdx.x * 256 + threadIdx.x;
    if (idx >= 16 * 40 * 60 * 108) return;
    int x = idx % 108;
    int y = (idx / 108) % 60;
    int c40 = (idx / (108 * 60)) % 40;
    int g = idx / (108 * 60 * 40);
    int pys[3], kis[3], pxs[3], kjs[3];
    int cy = 0, cx = 0;
    #pragma unroll
    for (int dp = 0; dp < 3; dp++) {
        int py = (y + 3) / 3 - dp;
        int ki = y + 3 - 3 * py;
        if (py >= 0 && py < 20 && ki < 7) { pys[cy] = py; kis[cy] = ki; cy++; }
        int px = (x + 3) / 3 - dp;
        int kj = x + 3 - 3 * px;
        if (px >= 0 && px < 36 && kj < 7) { pxs[cx] = px; kjs[cx] = kj; cx++; }
    }
    float s = 0.f;
    for (int a = 0; a < cy; a++)
        for (int bb = 0; bb < cx; bb++) {
            long long r = (long long)g * 720 + pys[a] * 36 + pxs[bb];
            s += __bfloat162float(h1[r * 1960 + c40 * 49 + kis[a] * 7 + kjs[bb]]);
        }
    I[idx] = s / (float)(cy * cx);
}

// ---------------- T2T unfold + exact GELU (bf16 out) ----------------
__global__ __launch_bounds__(256) void t2tunf_k(const float* __restrict__ I,
                                                bf16* __restrict__ h2) {
    int idx = blockIdx.x * 256 + threadIdx.x;
    if (idx >= TOK * FFN) return;
    int c = idx % 1960;
    int r = idx / 1960;
    int g = r / 720;
    int p = r - g * 720;
    int py = p / 36, px = p - py * 36;
    int c40 = c / 49;
    int kk = c - c40 * 49;
    int ki = kk / 7, kj = kk - ki * 7;
    int y = py * 3 + ki - 3, x = px * 3 + kj - 3;
    float v = 0.f;
    if (y >= 0 && y < 60 && x >= 0 && x < 108)
        v = I[(((long long)g * 40 + c40) * 60 + y) * 108 + x];
    h2[idx] = __float2bfloat16(0.5f * v * (1.f + erff(v * 0.7071067811865475f)));
}

// ---------------- host launch ----------------
#define SYM(T, p, s) T* p; do { void* _t = nullptr; cudaGetSymbolAddress(&_t, s); (p) = (T*)_t; } while (0)

template <typename OutT>
static void run_tgemm(const bf16* A, const bf16* Bm, const float* bias,
                      const float* res, OutT* C, int M, int N, int K) {
    dim3 grid((N + GBN - 1) / GBN, M / GBM);
    size_t sm = (size_t)3 * (GASZ + GBSZ) * sizeof(bf16);
    cudaFuncSetAttribute(tgemm_k<OutT>, cudaFuncAttributeMaxDynamicSharedMemorySize, (int)sm);
    tgemm_k<OutT><<<grid, 256, sm>>>(A, Bm, bias, res, C, M, N, K);
}

extern "C" void kernel_launch(void* const* d_in, const int* in_sizes, int n_in,
                              void* d_out, int out_size) {
    const float* x     = (const float*)d_in[0];
    const float* g1    = (const float*)d_in[1];
    const float* be1   = (const float*)d_in[2];
    const float* wqkv  = (const float*)d_in[3];
    const float* bqkv  = (const float*)d_in[4];
    const float* wproj = (const float*)d_in[5];
    const float* bproj = (const float*)d_in[6];
    const float* wpool = (const float*)d_in[7];
    const float* bpool = (const float*)d_in[8];
    const float* g2    = (const float*)d_in[9];
    const float* be2   = (const float*)d_in[10];
    const float* w1    = (const float*)d_in[11];
    const float* bf1   = (const float*)d_in[12];
    const float* w2    = (const float*)d_in[13];
    const float* bf2   = (const float*)d_in[14];
    float* out = (float*)d_out;

    SYM(bf16, xn, g_xn); SYM(bf16, qkv, g_qkv); SYM(bf16, pooled, g_pooled);
    SYM(bf16, qkvp, g_qkvp); SYM(bf16, Aw, g_Aw); SYM(float, Pw, g_Pw);
    SYM(float, xres, g_xres); SYM(bf16, hb, g_hb); SYM(float, I, g_I);
    SYM(int, qidx, g_qidx); SYM(int, kidx, g_kidx);
    SYM(bf16, wqkvb, g_wqkvb); SYM(bf16, wprojb, g_wprojb);
    SYM(bf16, w1b, g_w1b); SYM(bf16, w2b, g_w2b);

    initvalid_k<<<1, 32>>>();
    idx_k<<<(NWIN * NK + 255) / 256, 256>>>(qidx, kidx);
    convw_k<<<(512 * 1536 + 255) / 256, 256>>>(wqkv, wqkvb, 512 * 1536);
    convw_k<<<(512 * 512 + 255) / 256, 256>>>(wproj, wprojb, 512 * 512);
    convw_k<<<(512 * 1960 + 255) / 256, 256>>>(w1, w1b, 512 * 1960);
    convw_k<<<(1960 * 512 + 255) / 256, 256>>>(w2, w2b, 1960 * 512);

    ln_k<<<TOK, 128>>>(x, g1, be1, xn);
    run_tgemm<bf16>(xn, wqkvb, bqkv, nullptr, qkv, TOK, 1536, 512);
    pool_k<<<1024, 128>>>(xn, wpool, bpool, pooled);
    run_tgemm<bf16>(pooled, wqkvb, bqkv, nullptr, qkvp, 256, 1536, 512);

    {
        size_t smfa = (size_t)4 * FA_KT * FA_ST * sizeof(bf16);
        cudaFuncSetAttribute(fattn_k, cudaFuncAttributeMaxDynamicSharedMemorySize, (int)smfa);
        fattn_k<<<dim3(3, 128), 256, smfa>>>(qkv, qkvp, qidx, kidx, Aw);
    }

    run_tgemm<float>(Aw, wprojb, bproj, nullptr, Pw, TOK, 512, 512);
    addres_k<<<TOK * 128 / 256, 256>>>(x, Pw, xres);
    ln_k<<<TOK, 128>>>(xres, g2, be2, xn);
    run_tgemm<bf16>(xn, w1b, bf1, nullptr, hb, TOK, FFN, 512);
    t2tfold_k<<<(16 * 40 * 60 * 108 + 255) / 256, 256>>>(hb, I);
    t2tunf_k<<<(TOK * FFN + 255) / 256, 256>>>(I, hb);
    run_tgemm<float>(hb, w2b, bf2, xres, out, TOK, 512, FFN);
}

// round 8
// speedup vs baseline: 8.9967x; 1.0667x over previous
#include <cuda_runtime.h>
#include <cuda_bf16.h>
#include <math.h>
#include <stdint.h>

// ---------------- constants ----------------
constexpr int NWIN = 32;
constexpr int NQ = 360;
constexpr int NKP = 1456;          // compacted+padded keys = 13 * 112
constexpr int NKT = 13;            // key tiles
constexpr int TOK = 11520;
constexpr int FFN = 1960;
constexpr int Cch = 512;
constexpr float SC2 = 0.08838834764831845f * 1.4426950408889634f; // qscale * log2(e)

typedef __nv_bfloat16 bf16;
typedef __nv_bfloat162 bf162;

// ---------------- scratch ----------------
__device__ bf16  g_xn[TOK * Cch];
__device__ bf16  g_qkv[TOK * 3 * Cch];
__device__ bf16  g_pooled[256 * Cch];
__device__ bf16  g_qkvp[256 * 3 * Cch];
__device__ bf16  g_Aw[TOK * Cch];
__device__ float g_xres[TOK * Cch];
__device__ bf16  g_hb[TOK * FFN];          // h1 (pre-fold) then h2 (post-GELU)
__device__ float g_I[16 * 40 * 60 * 108];
__device__ int   g_valid[120];
__device__ int   g_qidx[NWIN * NQ];
__device__ int   g_kidx[NWIN * NKP];
__device__ bf16  g_wb[3055616];            // qkv | proj | w1 | w2 (bf16)
constexpr int WO_PROJ = 786432;
constexpr int WO_W1   = 1048576;
constexpr int WO_W2   = 2052096;
constexpr int WTOT    = 3055616;

// ---------------- init valid-rolled table ----------------
__global__ void initvalid_k() {
    if (threadIdx.x == 0 && blockIdx.x == 0) {
        int n = 0;
        for (int s = 0; s < 4; s++)
            for (int ih = 0; ih < 5; ih++)
                for (int iw = 0; iw < 9; iw++) {
                    bool zero;
                    if (s == 0) zero = (ih < 3 && iw < 5);
                    else if (s == 1) zero = (ih < 3 && iw >= 4);
                    else if (s == 2) zero = (ih >= 2 && iw < 5);
                    else zero = (ih >= 2 && iw >= 4);
                    if (!zero) g_valid[n++] = s * 45 + ih * 9 + iw;
                }
    }
}

// ---------------- build gather index tables (compacted pooled keys) ----------------
__global__ __launch_bounds__(256) void idx_k(int* __restrict__ qidx,
                                             int* __restrict__ kidx) {
    int i = blockIdx.x * 256 + threadIdx.x;
    if (i < NWIN * NQ) {
        int win = i / NQ, q = i - win * NQ;
        int b = win >> 4, wh = (win >> 2) & 3, ww = win & 3;
        int t = q / 45, a = q - t * 45, ih = a / 9, iw = a % 9;
        qidx[i] = ((b * 8 + t) * 20 + wh * 5 + ih) * 36 + ww * 9 + iw;
    }
    if (i < NWIN * NKP) {
        int win = i / NKP, j = i - win * NKP;
        int b = win >> 4, wh = (win >> 2) & 3, ww = win & 3;
        int e = -1;
        if (j < 360) {
            int t = j / 45, a = j - t * 45, ih = a / 9, iw = a % 9;
            e = ((b * 8 + t) * 20 + wh * 5 + ih) * 36 + ww * 9 + iw;
        } else if (j < 1320) {
            int jj = j - 360;
            int t = jj / 120, vi = jj - t * 120;
            int f = g_valid[vi];
            int s = f / 45, a = f - s * 45, ih = a / 9, iw = a % 9;
            int sh = (s < 2) ? -2 : 2;
            int sw = (s & 1) ? 4 : -4;
            int hh = wh * 5 + ih - sh; hh %= 20; if (hh < 0) hh += 20;
            int wp = ww * 9 + iw - sw; wp %= 36; if (wp < 0) wp += 36;
            e = ((b * 8 + t) * 20 + hh) * 36 + wp;
        } else {
            // compacted valid pooled keys only
            int pos = j - 1320;
            int i0 = (2 - wh) > 0 ? (2 - wh) : 0;
            int iend = (6 - wh) < 5 ? (6 - wh) : 5;
            int rows = iend - i0;
            int nv = rows * 4;
            if (pos < nv * 8) {
                int t = pos / nv, r = pos - t * nv;
                int di = r >> 2, dj = r & 3;
                int gi = wh + (i0 + di) - 2;
                int gj = dj;                 // ww + (4-ww+dj) - 4
                e = TOK + (b * 8 + t) * 16 + gi * 4 + gj;
            }
        }
        kidx[i] = e;
    }
}

// ---------------- all weights fp32 -> bf16 (single launch) ----------------
__global__ __launch_bounds__(256) void convw_all(const float* __restrict__ a,
                                                 const float* __restrict__ b,
                                                 const float* __restrict__ c,
                                                 const float* __restrict__ d,
                                                 bf16* __restrict__ o) {
    int i = blockIdx.x * 256 + threadIdx.x;
    if (i >= WTOT) return;
    float v;
    if (i < WO_PROJ) v = a[i];
    else if (i < WO_W1) v = b[i - WO_PROJ];
    else if (i < WO_W2) v = c[i - WO_W1];
    else v = d[i - WO_W2];
    o[i] = __float2bfloat16(v);
}

// ---------------- LayerNorm (fp32 in, bf16 out) ----------------
__global__ __launch_bounds__(128) void ln_k(const float* __restrict__ in,
                                            const float* __restrict__ g,
                                            const float* __restrict__ b,
                                            bf16* __restrict__ out) {
    int row = blockIdx.x;
    const float4* xp = (const float4*)(in + (long long)row * 512);
    float4 v = xp[threadIdx.x];
    float s = v.x + v.y + v.z + v.w;
    __shared__ float red[4], red2[4];
    #pragma unroll
    for (int o = 16; o; o >>= 1) s += __shfl_xor_sync(0xffffffffu, s, o);
    int wid = threadIdx.x >> 5, lane = threadIdx.x & 31;
    if (lane == 0) red[wid] = s;
    __syncthreads();
    float mu = (red[0] + red[1] + red[2] + red[3]) * (1.f / 512.f);
    float dx = v.x - mu, dy = v.y - mu, dz = v.z - mu, dw = v.w - mu;
    float sq = dx * dx + dy * dy + dz * dz + dw * dw;
    #pragma unroll
    for (int o = 16; o; o >>= 1) sq += __shfl_xor_sync(0xffffffffu, sq, o);
    if (lane == 0) red2[wid] = sq;
    __syncthreads();
    float var = (red2[0] + red2[1] + red2[2] + red2[3]) * (1.f / 512.f);
    float inv = rsqrtf(var + 1e-5f);
    float4 gg = ((const float4*)g)[threadIdx.x];
    float4 bb = ((const float4*)b)[threadIdx.x];
    bf162 o0 = __floats2bfloat162_rn(dx * inv * gg.x + bb.x, dy * inv * gg.y + bb.y);
    bf162 o1 = __floats2bfloat162_rn(dz * inv * gg.z + bb.z, dw * inv * gg.w + bb.w);
    bf162* op = (bf162*)(out + (long long)row * 512);
    op[2 * threadIdx.x] = o0;
    op[2 * threadIdx.x + 1] = o1;
}

// ---------------- window pooling ----------------
__global__ __launch_bounds__(128) void pool_k(const bf16* __restrict__ xn,
                                              const float* __restrict__ wpool,
                                              const float* __restrict__ bpool,
                                              bf16* __restrict__ pooled) {
    int widx = blockIdx.x >> 2;
    int c = ((blockIdx.x & 3) << 7) + threadIdx.x;
    int ww = widx & 3, wh = (widx >> 2) & 3, bt = widx >> 4;
    float s = 0.f;
    #pragma unroll
    for (int a = 0; a < 45; a++) {
        int ih = a / 9, iw = a % 9;
        long long tok = ((long long)bt * 20 + wh * 5 + ih) * 36 + ww * 9 + iw;
        s += __bfloat162float(xn[tok * 512 + c]) * wpool[a];
    }
    pooled[(long long)widx * 512 + c] = __float2bfloat16(s + bpool[0]);
}

// ---------------- common PTX helpers ----------------
__device__ __forceinline__ void cpasync16(uint32_t saddr, const void* gaddr, bool pred) {
    int sz = pred ? 16 : 0;
    asm volatile("cp.async.cg.shared.global [%0], [%1], 16, %2;\n"
                 :: "r"(saddr), "l"(gaddr), "r"(sz));
}
__device__ __forceinline__ void ldsm4(uint32_t& r0, uint32_t& r1, uint32_t& r2, uint32_t& r3,
                                      uint32_t a) {
    asm volatile("ldmatrix.sync.aligned.m8n8.x4.shared.b16 {%0,%1,%2,%3}, [%4];\n"
                 : "=r"(r0), "=r"(r1), "=r"(r2), "=r"(r3) : "r"(a));
}
__device__ __forceinline__ void ldsm4t(uint32_t& r0, uint32_t& r1, uint32_t& r2, uint32_t& r3,
                                       uint32_t a) {
    asm volatile("ldmatrix.sync.aligned.m8n8.x4.trans.shared.b16 {%0,%1,%2,%3}, [%4];\n"
                 : "=r"(r0), "=r"(r1), "=r"(r2), "=r"(r3) : "r"(a));
}
__device__ __forceinline__ void mma16816(float* c, const uint32_t* a, const uint32_t* b) {
    asm volatile(
        "mma.sync.aligned.m16n8k16.row.col.f32.bf16.bf16.f32 "
        "{%0,%1,%2,%3}, {%4,%5,%6,%7}, {%8,%9}, {%0,%1,%2,%3};\n"
        : "+f"(c[0]), "+f"(c[1]), "+f"(c[2]), "+f"(c[3])
        : "r"(a[0]), "r"(a[1]), "r"(a[2]), "r"(a[3]), "r"(b[0]), "r"(b[1]));
}
__device__ __forceinline__ uint32_t packbf(float x, float y) {
    bf162 h = __floats2bfloat162_rn(x, y);
    return *(uint32_t*)&h;
}
__device__ __forceinline__ float ex2f(float x) {
    float r;
    asm("ex2.approx.f32 %0, %1;" : "=f"(r) : "f"(x));
    return r;
}
__device__ __forceinline__ void store2(float* p, float x, float y) {
    *(float2*)p = make_float2(x, y);
}
__device__ __forceinline__ void store2(bf16* p, float x, float y) {
    *(bf162*)p = __floats2bfloat162_rn(x, y);
}

// ---------------- fused flash attention (compacted keys, log2-domain softmax) ----------------
constexpr int FA_KT = 112;
constexpr int FA_ST = 136;

__global__ __launch_bounds__(256, 1) void fattn_k(const bf16* __restrict__ qkv,
                                                  const bf16* __restrict__ qkvp,
                                                  const int* __restrict__ qidx,
                                                  const int* __restrict__ kidx,
                                                  bf16* __restrict__ Og) {
    int mtile = blockIdx.x;
    int zy = blockIdx.y;
    int win = zy >> 2, head = zy & 3;
    int wl = win & 15;
    int mwh = wl >> 2;
    // valid key count for this window (rows: wh 0/3 -> 3, wh 1/2 -> 4; cols always 4)
    int nk = 1320 + (((mwh == 0) || (mwh == 3)) ? 12 : 16) * 8;

    extern __shared__ bf16 sm[];
    bf16* Ks = sm;
    bf16* Vs = sm + 2 * FA_KT * FA_ST;
    uint32_t sK = (uint32_t)__cvta_generic_to_shared(Ks);
    uint32_t sV = (uint32_t)__cvta_generic_to_shared(Vs);

    int tid = threadIdx.x, wp = tid >> 5, lane = tid & 31;
    int g = lane >> 2, t = lane & 3;
    int hoff = head * 128;

    // ---- load Q tile ----
    #pragma unroll
    for (int i = 0; i < 8; i++) {
        int idx = tid + i * 256;
        int r = idx >> 4, c = (idx & 15) << 3;
        int q = mtile * 128 + r;
        bool ok = q < 360;
        int e = ok ? __ldg(qidx + win * 360 + q) : 0;
        cpasync16(sK + (uint32_t)((r * FA_ST + c) * 2),
                  qkv + (long long)e * 1536 + hoff + c, ok);
    }
    asm volatile("cp.async.commit_group;\n");
    asm volatile("cp.async.wait_group 0;\n");
    __syncthreads();
    uint32_t qa[8][4];
    #pragma unroll
    for (int ks = 0; ks < 8; ks++) {
        uint32_t ad = sK + (uint32_t)((((wp << 4) + (lane & 15)) * FA_ST
                                       + ks * 16 + ((lane >> 4) << 3)) * 2);
        ldsm4(qa[ks][0], qa[ks][1], qa[ks][2], qa[ks][3], ad);
    }
    __syncthreads();

    auto loadKV = [&](int stage, int kt) {
        #pragma unroll
        for (int i = 0; i < 7; i++) {
            int idx = tid + i * 256;
            int r = idx >> 4, c = (idx & 15) << 3;
            int e = __ldg(kidx + win * NKP + kt * FA_KT + r);
            bool ok = e >= 0;
            const bf16* p = qkv;
            if (ok) p = (e < TOK) ? qkv + (long long)e * 1536
                                  : qkvp + (long long)(e - TOK) * 1536;
            uint32_t off = (uint32_t)((stage * FA_KT * FA_ST + r * FA_ST + c) * 2);
            cpasync16(sK + off, p + 512 + hoff + c, ok);
            cpasync16(sV + off, p + 1024 + hoff + c, ok);
        }
    };

    float m0 = -1e30f, m1 = -1e30f, l0 = 0.f, l1 = 0.f;
    float o[16][4];
    #pragma unroll
    for (int i = 0; i < 16; i++)
        #pragma unroll
        for (int q = 0; q < 4; q++) o[i][q] = 0.f;

    loadKV(0, 0);
    asm volatile("cp.async.commit_group;\n");

    for (int kt = 0; kt < NKT; kt++) {
        if (kt + 1 < NKT) loadKV((kt + 1) & 1, kt + 1);
        asm volatile("cp.async.commit_group;\n");
        asm volatile("cp.async.wait_group %0;\n" :: "n"(1));
        __syncthreads();

        uint32_t bK = sK + (uint32_t)((kt & 1) * FA_KT * FA_ST * 2);
        uint32_t bV = sV + (uint32_t)((kt & 1) * FA_KT * FA_ST * 2);

        float c[14][4];
        #pragma unroll
        for (int n = 0; n < 14; n++)
            #pragma unroll
            for (int q = 0; q < 4; q++) c[n][q] = 0.f;

        #pragma unroll
        for (int ks = 0; ks < 8; ks++) {
            #pragma unroll
            for (int h = 0; h < 7; h++) {
                uint32_t b[4];
                uint32_t bd = bK + (uint32_t)(((h * 16 + (lane & 7) + ((lane >> 4) << 3)) * FA_ST
                                              + ks * 16 + (((lane >> 3) & 1) << 3)) * 2);
                ldsm4(b[0], b[1], b[2], b[3], bd);
                mma16816(c[2 * h], qa[ks], b);
                mma16816(c[2 * h + 1], qa[ks], b + 2);
            }
        }

        // scale into log2 domain
        #pragma unroll
        for (int n = 0; n < 14; n++)
            #pragma unroll
            for (int q = 0; q < 4; q++) c[n][q] *= SC2;

        // mask padding keys (last tile only)
        if (kt == NKT - 1) {
            #pragma unroll
            for (int n = 0; n < 14; n++) {
                #pragma unroll
                for (int e = 0; e < 2; e++) {
                    int j = (NKT - 1) * FA_KT + n * 8 + 2 * t + e;
                    if (j >= nk) { c[n][e] = -1e30f; c[n][e + 2] = -1e30f; }
                }
            }
        }

        // ---- online softmax (log2 domain) ----
        float r0 = -1e30f, r1 = -1e30f;
        #pragma unroll
        for (int n = 0; n < 14; n++) {
            r0 = fmaxf(r0, fmaxf(c[n][0], c[n][1]));
            r1 = fmaxf(r1, fmaxf(c[n][2], c[n][3]));
        }
        r0 = fmaxf(r0, __shfl_xor_sync(0xffffffffu, r0, 1));
        r0 = fmaxf(r0, __shfl_xor_sync(0xffffffffu, r0, 2));
        r1 = fmaxf(r1, __shfl_xor_sync(0xffffffffu, r1, 1));
        r1 = fmaxf(r1, __shfl_xor_sync(0xffffffffu, r1, 2));
        float mn0 = fmaxf(m0, r0), mn1 = fmaxf(m1, r1);
        float sc0 = ex2f(m0 - mn0), sc1 = ex2f(m1 - mn1);
        m0 = mn0; m1 = mn1;
        float s0 = 0.f, s1 = 0.f;
        #pragma unroll
        for (int n = 0; n < 14; n++) {
            c[n][0] = ex2f(c[n][0] - mn0);
            c[n][1] = ex2f(c[n][1] - mn0);
            c[n][2] = ex2f(c[n][2] - mn1);
            c[n][3] = ex2f(c[n][3] - mn1);
            s0 += c[n][0] + c[n][1];
            s1 += c[n][2] + c[n][3];
        }
        s0 += __shfl_xor_sync(0xffffffffu, s0, 1);
        s0 += __shfl_xor_sync(0xffffffffu, s0, 2);
        s1 += __shfl_xor_sync(0xffffffffu, s1, 1);
        s1 += __shfl_xor_sync(0xffffffffu, s1, 2);
        l0 = l0 * sc0 + s0;
        l1 = l1 * sc1 + s1;
        #pragma unroll
        for (int i = 0; i < 16; i++) {
            o[i][0] *= sc0; o[i][1] *= sc0;
            o[i][2] *= sc1; o[i][3] *= sc1;
        }

        // ---- O += P @ V ----
        #pragma unroll
        for (int kk = 0; kk < 7; kk++) {
            uint32_t a[4];
            a[0] = packbf(c[2 * kk][0], c[2 * kk][1]);
            a[1] = packbf(c[2 * kk][2], c[2 * kk][3]);
            a[2] = packbf(c[2 * kk + 1][0], c[2 * kk + 1][1]);
            a[3] = packbf(c[2 * kk + 1][2], c[2 * kk + 1][3]);
            #pragma unroll
            for (int h = 0; h < 8; h++) {
                uint32_t b[4];
                uint32_t bd = bV + (uint32_t)(((kk * 16 + (lane & 7) + (((lane >> 3) & 1) << 3)) * FA_ST
                                              + h * 16 + ((lane >> 4) << 3)) * 2);
                ldsm4t(b[0], b[1], b[2], b[3], bd);
                mma16816(o[2 * h], a, b);
                mma16816(o[2 * h + 1], a, b + 2);
            }
        }
        __syncthreads();
    }

    float il0 = 1.f / l0, il1 = 1.f / l1;
    int q0 = mtile * 128 + wp * 16 + g;
    #pragma unroll
    for (int h = 0; h < 16; h++) {
        int col = hoff + h * 8 + 2 * t;
        if (q0 < 360) {
            bf162 v = __floats2bfloat162_rn(o[h][0] * il0, o[h][1] * il0);
            *(bf162*)(Og + ((long long)win * 360 + q0) * 512 + col) = v;
        }
        if (q0 + 8 < 360) {
            bf162 v = __floats2bfloat162_rn(o[h][2] * il1, o[h][3] * il1);
            *(bf162*)(Og + ((long long)win * 360 + q0 + 8) * 512 + col) = v;
        }
    }
}

// ---------------- bf16 GEMM: BM=128, BN=128, BK=32, 3-stage, optional row-scatter epilogue ----
constexpr int GBM = 128, GBN = 128, GBK = 32;
constexpr int GAST = GBK + 8;    // 40
constexpr int GBST = GBN + 8;    // 136
constexpr int GASZ = GBM * GAST;
constexpr int GBSZ = GBK * GBST;

template <typename OutT>
__global__ __launch_bounds__(256, 2) void tgemm_k(
    const bf16* __restrict__ A, const bf16* __restrict__ Bm,
    const float* __restrict__ bias, const float* __restrict__ res,
    OutT* __restrict__ Cm, int M, int N, int K,
    const int* __restrict__ scat) {
    extern __shared__ bf16 smem[];
    bf16* As = smem;
    bf16* Bs = smem + 3 * GASZ;

    int tid = threadIdx.x;
    int row0 = blockIdx.y * GBM, col0 = blockIdx.x * GBN;
    int wid = tid >> 5, lane = tid & 31;
    int wm = wid & 3, wn = wid >> 2;
    int g = lane >> 2, t = lane & 3;

    uint32_t sA0 = (uint32_t)__cvta_generic_to_shared(As);
    uint32_t sB0 = (uint32_t)__cvta_generic_to_shared(Bs);
    int ktiles = (K + GBK - 1) / GBK;

    auto load_tile = [&](int stage, int k0) {
        #pragma unroll
        for (int i = 0; i < 2; i++) {
            int idx = tid + i * 256;
            int r = idx >> 2, kc = (idx & 3) << 3;
            bool ok = (k0 + kc) < K;
            cpasync16(sA0 + (uint32_t)((stage * GASZ + r * GAST + kc) * 2),
                      A + (long long)(row0 + r) * K + k0 + kc, ok);
        }
        #pragma unroll
        for (int i = 0; i < 2; i++) {
            int idx = tid + i * 256;
            int kk = idx >> 4, nc = (idx & 15) << 3;
            int gn = col0 + nc;
            bool ok = ((k0 + kk) < K) && (gn < N);
            cpasync16(sB0 + (uint32_t)((stage * GBSZ + kk * GBST + nc) * 2),
                      Bm + (long long)(k0 + kk) * N + gn, ok);
        }
    };

    float acc[2][8][4];
    #pragma unroll
    for (int mi = 0; mi < 2; mi++)
        #pragma unroll
        for (int ni = 0; ni < 8; ni++)
            #pragma unroll
            for (int q = 0; q < 4; q++) acc[mi][ni][q] = 0.f;

    load_tile(0, 0);
    asm volatile("cp.async.commit_group;\n");
    load_tile(1, GBK);
    asm volatile("cp.async.commit_group;\n");

    for (int kt = 0; kt < ktiles; kt++) {
        asm volatile("cp.async.wait_group %0;\n" :: "n"(1));
        __syncthreads();
        if (kt + 2 < ktiles) load_tile((kt + 2) % 3, (kt + 2) * GBK);
        asm volatile("cp.async.commit_group;\n");

        uint32_t sAb = sA0 + (uint32_t)((kt % 3) * GASZ * 2);
        uint32_t sBb = sB0 + (uint32_t)((kt % 3) * GBSZ * 2);

        #pragma unroll
        for (int ks = 0; ks < 2; ks++) {
            uint32_t a[2][4], b[8][2];
            #pragma unroll
            for (int mi = 0; mi < 2; mi++) {
                int row = wm * 32 + mi * 16 + (lane & 15);
                uint32_t ad = sAb + (uint32_t)((row * GAST + ks * 16 + ((lane >> 4) << 3)) * 2);
                ldsm4(a[mi][0], a[mi][1], a[mi][2], a[mi][3], ad);
            }
            #pragma unroll
            for (int h = 0; h < 4; h++) {
                int rowk = ks * 16 + (lane & 7) + (((lane >> 3) & 1) << 3);
                int coln = wn * 64 + h * 16 + ((lane >> 4) << 3);
                uint32_t bd = sBb + (uint32_t)((rowk * GBST + coln) * 2);
                ldsm4t(b[2 * h][0], b[2 * h][1], b[2 * h + 1][0], b[2 * h + 1][1], bd);
            }
            #pragma unroll
            for (int mi = 0; mi < 2; mi++)
                #pragma unroll
                for (int ni = 0; ni < 8; ni++)
                    mma16816(acc[mi][ni], a[mi], b[ni]);
        }
    }

    #pragma unroll
    for (int mi = 0; mi < 2; mi++) {
        int r = row0 + wm * 32 + mi * 16 + g;
        int ra = scat ? __ldg(scat + r) : r;
        int rb = scat ? __ldg(scat + r + 8) : r + 8;
        #pragma unroll
        for (int ni = 0; ni < 8; ni++) {
            int cidx = col0 + wn * 64 + ni * 8 + 2 * t;
            if (cidx < N) {
                float b0 = bias ? bias[cidx] : 0.f;
                float b1 = bias ? bias[cidx + 1] : 0.f;
                float x0 = acc[mi][ni][0] + b0, x1 = acc[mi][ni][1] + b1;
                float x2 = acc[mi][ni][2] + b0, x3 = acc[mi][ni][3] + b1;
                long long i0 = (long long)ra * N + cidx;
                long long i1 = (long long)rb * N + cidx;
                if (res) {
                    float2 r0 = *(const float2*)(res + i0);
                    float2 r1 = *(const float2*)(res + i1);
                    x0 += r0.x; x1 += r0.y; x2 += r1.x; x3 += r1.y;
                }
                store2(Cm + i0, x0, x1);
                store2(Cm + i1, x2, x3);
            }
        }
    }
}

// ---------------- T2T fold (gather form, bf16 in) + normalize ----------------
__global__ __launch_bounds__(256) void t2tfold_k(const bf16* __restrict__ h1,
                                                 float* __restrict__ I) {
    int idx = blockIdx.x * 256 + threadIdx.x;
    if (idx >= 16 * 40 * 60 * 108) return;
    int x = idx % 108;
    int y = (idx / 108) % 60;
    int c40 = (idx / (108 * 60)) % 40;
    int g = idx / (108 * 60 * 40);
    int pys[3], kis[3], pxs[3], kjs[3];
    int cy = 0, cx = 0;
    #pragma unroll
    for (int dp = 0; dp < 3; dp++) {
        int py = (y + 3) / 3 - dp;
        int ki = y + 3 - 3 * py;
        if (py >= 0 && py < 20 && ki < 7) { pys[cy] = py; kis[cy] = ki; cy++; }
        int px = (x + 3) / 3 - dp;
        int kj = x + 3 - 3 * px;
        if (px >= 0 && px < 36 && kj < 7) { pxs[cx] = px; kjs[cx] = kj; cx++; }
    }
    float s = 0.f;
    for (int a = 0; a < cy; a++)
        for (int bb = 0; bb < cx; bb++) {
            long long r = (long long)g * 720 + pys[a] * 36 + pxs[bb];
            s += __bfloat162float(h1[r * 1960 + c40 * 49 + kis[a] * 7 + kjs[bb]]);
        }
    I[idx] = s / (float)(cy * cx);
}

// ---------------- T2T unfold + exact GELU (bf16 out) ----------------
__global__ __launch_bounds__(256) void t2tunf_k(const float* __restrict__ I,
                                                bf16* __restrict__ h2) {
    int idx = blockIdx.x * 256 + threadIdx.x;
    if (idx >= TOK * FFN) return;
    int c = idx % 1960;
    int r = idx / 1960;
    int g = r / 720;
    int p = r - g * 720;
    int py = p / 36, px = p - py * 36;
    int c40 = c / 49;
    int kk = c - c40 * 49;
    int ki = kk / 7, kj = kk - ki * 7;
    int y = py * 3 + ki - 3, x = px * 3 + kj - 3;
    float v = 0.f;
    if (y >= 0 && y < 60 && x >= 0 && x < 108)
        v = I[(((long long)g * 40 + c40) * 60 + y) * 108 + x];
    h2[idx] = __float2bfloat16(0.5f * v * (1.f + erff(v * 0.7071067811865475f)));
}

// ---------------- host launch ----------------
#define SYM(T, p, s) T* p; do { void* _t = nullptr; cudaGetSymbolAddress(&_t, s); (p) = (T*)_t; } while (0)

template <typename OutT>
static void run_tgemm(const bf16* A, const bf16* Bm, const float* bias,
                      const float* res, OutT* C, int M, int N, int K,
                      const int* scat = nullptr) {
    dim3 grid((N + GBN - 1) / GBN, M / GBM);
    size_t sm = (size_t)3 * (GASZ + GBSZ) * sizeof(bf16);
    cudaFuncSetAttribute(tgemm_k<OutT>, cudaFuncAttributeMaxDynamicSharedMemorySize, (int)sm);
    tgemm_k<OutT><<<grid, 256, sm>>>(A, Bm, bias, res, C, M, N, K, scat);
}

extern "C" void kernel_launch(void* const* d_in, const int* in_sizes, int n_in,
                              void* d_out, int out_size) {
    const float* x     = (const float*)d_in[0];
    const float* g1    = (const float*)d_in[1];
    const float* be1   = (const float*)d_in[2];
    const float* wqkv  = (const float*)d_in[3];
    const float* bqkv  = (const float*)d_in[4];
    const float* wproj = (const float*)d_in[5];
    const float* bproj = (const float*)d_in[6];
    const float* wpool = (const float*)d_in[7];
    const float* bpool = (const float*)d_in[8];
    const float* g2    = (const float*)d_in[9];
    const float* be2   = (const float*)d_in[10];
    const float* w1    = (const float*)d_in[11];
    const float* bf1   = (const float*)d_in[12];
    const float* w2    = (const float*)d_in[13];
    const float* bf2   = (const float*)d_in[14];
    float* out = (float*)d_out;

    SYM(bf16, xn, g_xn); SYM(bf16, qkv, g_qkv); SYM(bf16, pooled, g_pooled);
    SYM(bf16, qkvp, g_qkvp); SYM(bf16, Aw, g_Aw);
    SYM(float, xres, g_xres); SYM(bf16, hb, g_hb); SYM(float, I, g_I);
    SYM(int, qidx, g_qidx); SYM(int, kidx, g_kidx);
    SYM(bf16, wb, g_wb);
    bf16* wqkvb  = wb;
    bf16* wprojb = wb + WO_PROJ;
    bf16* w1b    = wb + WO_W1;
    bf16* w2b    = wb + WO_W2;

    initvalid_k<<<1, 32>>>();
    idx_k<<<(NWIN * NKP + 255) / 256, 256>>>(qidx, kidx);
    convw_all<<<(WTOT + 255) / 256, 256>>>(wqkv, wproj, w1, w2, wb);

    ln_k<<<TOK, 128>>>(x, g1, be1, xn);
    run_tgemm<bf16>(xn, wqkvb, bqkv, nullptr, qkv, TOK, 1536, 512);
    pool_k<<<1024, 128>>>(xn, wpool, bpool, pooled);
    run_tgemm<bf16>(pooled, wqkvb, bqkv, nullptr, qkvp, 256, 1536, 512);

    {
        size_t smfa = (size_t)4 * FA_KT * FA_ST * sizeof(bf16);
        cudaFuncSetAttribute(fattn_k, cudaFuncAttributeMaxDynamicSharedMemorySize, (int)smfa);
        fattn_k<<<dim3(3, 128), 256, smfa>>>(qkv, qkvp, qidx, kidx, Aw);
    }

    // proj GEMM with fused scatter + residual: xres[tok] = x[tok] + proj(Aw)[row]
    run_tgemm<float>(Aw, wprojb, bproj, x, xres, TOK, 512, 512, qidx);
    ln_k<<<TOK, 128>>>(xres, g2, be2, xn);
    run_tgemm<bf16>(xn, w1b, bf1, nullptr, hb, TOK, FFN, 512);
    t2tfold_k<<<(16 * 40 * 60 * 108 + 255) / 256, 256>>>(hb, I);
    t2tunf_k<<<(TOK * FFN + 255) / 256, 256>>>(I, hb);
    run_tgemm<float>(hb, w2b, bf2, xres, out, TOK, 512, FFN);
}

// round 9
// speedup vs baseline: 9.3648x; 1.0409x over previous
#include <cuda_runtime.h>
#include <cuda_bf16.h>
#include <math.h>
#include <stdint.h>

// ---------------- constants ----------------
constexpr int NWIN = 32;
constexpr int NQ = 360;
constexpr int NKP = 1456;          // compacted+padded keys = 13 * 112
constexpr int NKT = 13;            // key tiles
constexpr int TOK = 11520;
constexpr int FFN = 1960;
constexpr int Cch = 512;
constexpr float SC2 = 0.08838834764831845f * 1.4426950408889634f; // qscale * log2(e)

typedef __nv_bfloat16 bf16;
typedef __nv_bfloat162 bf162;

// ---------------- scratch ----------------
__device__ bf16  g_xn[TOK * Cch];
__device__ bf16  g_qkv[TOK * 3 * Cch];
__device__ bf16  g_pooled[256 * Cch];
__device__ bf16  g_qkvp[256 * 3 * Cch];
__device__ bf16  g_Aw[TOK * Cch];
__device__ float g_xres[TOK * Cch];
__device__ bf16  g_hb[TOK * FFN];          // h1 (pre-fold) then h2 (post-GELU)
__device__ float g_I[16 * 40 * 60 * 108];
__device__ int   g_valid[120];
__device__ int   g_qidx[NWIN * NQ];
__device__ int   g_kidx[NWIN * NKP];
__device__ bf16  g_wb[3055616];            // qkv | proj | w1 | w2 (bf16)
constexpr int WO_PROJ = 786432;
constexpr int WO_W1   = 1048576;
constexpr int WO_W2   = 2052096;
constexpr int WTOT    = 3055616;

// ---------------- init valid-rolled table ----------------
__global__ void initvalid_k() {
    if (threadIdx.x == 0 && blockIdx.x == 0) {
        int n = 0;
        for (int s = 0; s < 4; s++)
            for (int ih = 0; ih < 5; ih++)
                for (int iw = 0; iw < 9; iw++) {
                    bool zero;
                    if (s == 0) zero = (ih < 3 && iw < 5);
                    else if (s == 1) zero = (ih < 3 && iw >= 4);
                    else if (s == 2) zero = (ih >= 2 && iw < 5);
                    else zero = (ih >= 2 && iw >= 4);
                    if (!zero) g_valid[n++] = s * 45 + ih * 9 + iw;
                }
    }
}

// ---------------- build gather index tables (compacted pooled keys) ----------------
__global__ __launch_bounds__(256) void idx_k(int* __restrict__ qidx,
                                             int* __restrict__ kidx) {
    int i = blockIdx.x * 256 + threadIdx.x;
    if (i < NWIN * NQ) {
        int win = i / NQ, q = i - win * NQ;
        int b = win >> 4, wh = (win >> 2) & 3, ww = win & 3;
        int t = q / 45, a = q - t * 45, ih = a / 9, iw = a % 9;
        qidx[i] = ((b * 8 + t) * 20 + wh * 5 + ih) * 36 + ww * 9 + iw;
    }
    if (i < NWIN * NKP) {
        int win = i / NKP, j = i - win * NKP;
        int b = win >> 4, wh = (win >> 2) & 3, ww = win & 3;
        int e = -1;
        if (j < 360) {
            int t = j / 45, a = j - t * 45, ih = a / 9, iw = a % 9;
            e = ((b * 8 + t) * 20 + wh * 5 + ih) * 36 + ww * 9 + iw;
        } else if (j < 1320) {
            int jj = j - 360;
            int t = jj / 120, vi = jj - t * 120;
            int f = g_valid[vi];
            int s = f / 45, a = f - s * 45, ih = a / 9, iw = a % 9;
            int sh = (s < 2) ? -2 : 2;
            int sw = (s & 1) ? 4 : -4;
            int hh = wh * 5 + ih - sh; hh %= 20; if (hh < 0) hh += 20;
            int wp = ww * 9 + iw - sw; wp %= 36; if (wp < 0) wp += 36;
            e = ((b * 8 + t) * 20 + hh) * 36 + wp;
        } else {
            int pos = j - 1320;
            int i0 = (2 - wh) > 0 ? (2 - wh) : 0;
            int iend = (6 - wh) < 5 ? (6 - wh) : 5;
            int rows = iend - i0;
            int nv = rows * 4;
            if (pos < nv * 8) {
                int t = pos / nv, r = pos - t * nv;
                int di = r >> 2, dj = r & 3;
                int gi = wh + (i0 + di) - 2;
                int gj = dj;
                e = TOK + (b * 8 + t) * 16 + gi * 4 + gj;
            }
        }
        kidx[i] = e;
    }
}

// ---------------- all weights fp32 -> bf16 (single launch) ----------------
__global__ __launch_bounds__(256) void convw_all(const float* __restrict__ a,
                                                 const float* __restrict__ b,
                                                 const float* __restrict__ c,
                                                 const float* __restrict__ d,
                                                 bf16* __restrict__ o) {
    int i = blockIdx.x * 256 + threadIdx.x;
    if (i >= WTOT) return;
    float v;
    if (i < WO_PROJ) v = a[i];
    else if (i < WO_W1) v = b[i - WO_PROJ];
    else if (i < WO_W2) v = c[i - WO_W1];
    else v = d[i - WO_W2];
    o[i] = __float2bfloat16(v);
}

// ---------------- LayerNorm: warp per row, 8 rows/block ----------------
__global__ __launch_bounds__(256) void ln_k(const float* __restrict__ in,
                                            const float* __restrict__ g,
                                            const float* __restrict__ b,
                                            bf16* __restrict__ out) {
    int row = blockIdx.x * 8 + (threadIdx.x >> 5);
    int lane = threadIdx.x & 31;
    const float4* xp = (const float4*)(in + (long long)row * 512);
    float4 v[4];
    float s = 0.f;
    #pragma unroll
    for (int i = 0; i < 4; i++) {
        v[i] = xp[lane + 32 * i];
        s += v[i].x + v[i].y + v[i].z + v[i].w;
    }
    #pragma unroll
    for (int o = 16; o; o >>= 1) s += __shfl_xor_sync(0xffffffffu, s, o);
    float mu = s * (1.f / 512.f);
    float sq = 0.f;
    #pragma unroll
    for (int i = 0; i < 4; i++) {
        float dx = v[i].x - mu, dy = v[i].y - mu, dz = v[i].z - mu, dw = v[i].w - mu;
        sq += dx * dx + dy * dy + dz * dz + dw * dw;
    }
    #pragma unroll
    for (int o = 16; o; o >>= 1) sq += __shfl_xor_sync(0xffffffffu, sq, o);
    float inv = rsqrtf(sq * (1.f / 512.f) + 1e-5f);
    bf162* op = (bf162*)(out + (long long)row * 512);
    #pragma unroll
    for (int i = 0; i < 4; i++) {
        float4 gg = ((const float4*)g)[lane + 32 * i];
        float4 bb = ((const float4*)b)[lane + 32 * i];
        bf162 o0 = __floats2bfloat162_rn((v[i].x - mu) * inv * gg.x + bb.x,
                                         (v[i].y - mu) * inv * gg.y + bb.y);
        bf162 o1 = __floats2bfloat162_rn((v[i].z - mu) * inv * gg.z + bb.z,
                                         (v[i].w - mu) * inv * gg.w + bb.w);
        op[2 * (lane + 32 * i)] = o0;
        op[2 * (lane + 32 * i) + 1] = o1;
    }
}

// ---------------- window pooling (coalesced uint2 channel groups) ----------------
__global__ __launch_bounds__(128) void pool_k(const bf16* __restrict__ xn,
                                              const float* __restrict__ wpool,
                                              const float* __restrict__ bpool,
                                              bf16* __restrict__ pooled) {
    int widx = blockIdx.x;                 // 256 windows
    int ww = widx & 3, wh = (widx >> 2) & 3, bt = widx >> 4;
    int tid = threadIdx.x;                 // 4 channels each
    float a0 = 0.f, a1 = 0.f, a2 = 0.f, a3 = 0.f;
    #pragma unroll
    for (int a = 0; a < 45; a++) {
        int ih = a / 9, iw = a % 9;
        long long tok = ((long long)bt * 20 + wh * 5 + ih) * 36 + ww * 9 + iw;
        uint2 u = *(const uint2*)(xn + tok * 512 + tid * 4);
        float2 f0 = __bfloat1622float2(*(bf162*)&u.x);
        float2 f1 = __bfloat1622float2(*(bf162*)&u.y);
        float w = wpool[a];
        a0 += f0.x * w; a1 += f0.y * w; a2 += f1.x * w; a3 += f1.y * w;
    }
    float bp = bpool[0];
    bf162* dst = (bf162*)(pooled + (long long)widx * 512 + tid * 4);
    dst[0] = __floats2bfloat162_rn(a0 + bp, a1 + bp);
    dst[1] = __floats2bfloat162_rn(a2 + bp, a3 + bp);
}

// ---------------- common PTX helpers ----------------
__device__ __forceinline__ void cpasync16(uint32_t saddr, const void* gaddr, bool pred) {
    int sz = pred ? 16 : 0;
    asm volatile("cp.async.cg.shared.global [%0], [%1], 16, %2;\n"
                 :: "r"(saddr), "l"(gaddr), "r"(sz));
}
__device__ __forceinline__ void ldsm4(uint32_t& r0, uint32_t& r1, uint32_t& r2, uint32_t& r3,
                                      uint32_t a) {
    asm volatile("ldmatrix.sync.aligned.m8n8.x4.shared.b16 {%0,%1,%2,%3}, [%4];\n"
                 : "=r"(r0), "=r"(r1), "=r"(r2), "=r"(r3) : "r"(a));
}
__device__ __forceinline__ void ldsm4t(uint32_t& r0, uint32_t& r1, uint32_t& r2, uint32_t& r3,
                                       uint32_t a) {
    asm volatile("ldmatrix.sync.aligned.m8n8.x4.trans.shared.b16 {%0,%1,%2,%3}, [%4];\n"
                 : "=r"(r0), "=r"(r1), "=r"(r2), "=r"(r3) : "r"(a));
}
__device__ __forceinline__ void mma16816(float* c, const uint32_t* a, const uint32_t* b) {
    asm volatile(
        "mma.sync.aligned.m16n8k16.row.col.f32.bf16.bf16.f32 "
        "{%0,%1,%2,%3}, {%4,%5,%6,%7}, {%8,%9}, {%0,%1,%2,%3};\n"
        : "+f"(c[0]), "+f"(c[1]), "+f"(c[2]), "+f"(c[3])
        : "r"(a[0]), "r"(a[1]), "r"(a[2]), "r"(a[3]), "r"(b[0]), "r"(b[1]));
}
__device__ __forceinline__ uint32_t packbf(float x, float y) {
    bf162 h = __floats2bfloat162_rn(x, y);
    return *(uint32_t*)&h;
}
__device__ __forceinline__ float ex2f(float x) {
    float r;
    asm("ex2.approx.f32 %0, %1;" : "=f"(r) : "f"(x));
    return r;
}
__device__ __forceinline__ void store2(float* p, float x, float y) {
    *(float2*)p = make_float2(x, y);
}
__device__ __forceinline__ void store2(bf16* p, float x, float y) {
    *(bf162*)p = __floats2bfloat162_rn(x, y);
}

// ---------------- fused flash attention (compacted keys, log2-domain softmax) ----------------
constexpr int FA_KT = 112;
constexpr int FA_ST = 136;

__global__ __launch_bounds__(256, 1) void fattn_k(const bf16* __restrict__ qkv,
                                                  const bf16* __restrict__ qkvp,
                                                  const int* __restrict__ qidx,
                                                  const int* __restrict__ kidx,
                                                  bf16* __restrict__ Og) {
    int mtile = blockIdx.x;
    int zy = blockIdx.y;
    int win = zy >> 2, head = zy & 3;
    int wl = win & 15;
    int mwh = wl >> 2;
    int nk = 1320 + (((mwh == 0) || (mwh == 3)) ? 12 : 16) * 8;

    extern __shared__ bf16 sm[];
    bf16* Ks = sm;
    bf16* Vs = sm + 2 * FA_KT * FA_ST;
    uint32_t sK = (uint32_t)__cvta_generic_to_shared(Ks);
    uint32_t sV = (uint32_t)__cvta_generic_to_shared(Vs);

    int tid = threadIdx.x, wp = tid >> 5, lane = tid & 31;
    int g = lane >> 2, t = lane & 3;
    int hoff = head * 128;

    // ---- load Q tile ----
    #pragma unroll
    for (int i = 0; i < 8; i++) {
        int idx = tid + i * 256;
        int r = idx >> 4, c = (idx & 15) << 3;
        int q = mtile * 128 + r;
        bool ok = q < 360;
        int e = ok ? __ldg(qidx + win * 360 + q) : 0;
        cpasync16(sK + (uint32_t)((r * FA_ST + c) * 2),
                  qkv + (long long)e * 1536 + hoff + c, ok);
    }
    asm volatile("cp.async.commit_group;\n");
    asm volatile("cp.async.wait_group 0;\n");
    __syncthreads();
    uint32_t qa[8][4];
    #pragma unroll
    for (int ks = 0; ks < 8; ks++) {
        uint32_t ad = sK + (uint32_t)((((wp << 4) + (lane & 15)) * FA_ST
                                       + ks * 16 + ((lane >> 4) << 3)) * 2);
        ldsm4(qa[ks][0], qa[ks][1], qa[ks][2], qa[ks][3], ad);
    }
    __syncthreads();

    auto loadKV = [&](int stage, int kt) {
        #pragma unroll
        for (int i = 0; i < 7; i++) {
            int idx = tid + i * 256;
            int r = idx >> 4, c = (idx & 15) << 3;
            int e = __ldg(kidx + win * NKP + kt * FA_KT + r);
            bool ok = e >= 0;
            const bf16* p = qkv;
            if (ok) p = (e < TOK) ? qkv + (long long)e * 1536
                                  : qkvp + (long long)(e - TOK) * 1536;
            uint32_t off = (uint32_t)((stage * FA_KT * FA_ST + r * FA_ST + c) * 2);
            cpasync16(sK + off, p + 512 + hoff + c, ok);
            cpasync16(sV + off, p + 1024 + hoff + c, ok);
        }
    };

    float m0 = -1e30f, m1 = -1e30f, l0 = 0.f, l1 = 0.f;
    float o[16][4];
    #pragma unroll
    for (int i = 0; i < 16; i++)
        #pragma unroll
        for (int q = 0; q < 4; q++) o[i][q] = 0.f;

    loadKV(0, 0);
    asm volatile("cp.async.commit_group;\n");

    for (int kt = 0; kt < NKT; kt++) {
        if (kt + 1 < NKT) loadKV((kt + 1) & 1, kt + 1);
        asm volatile("cp.async.commit_group;\n");
        asm volatile("cp.async.wait_group %0;\n" :: "n"(1));
        __syncthreads();

        uint32_t bK = sK + (uint32_t)((kt & 1) * FA_KT * FA_ST * 2);
        uint32_t bV = sV + (uint32_t)((kt & 1) * FA_KT * FA_ST * 2);

        float c[14][4];
        #pragma unroll
        for (int n = 0; n < 14; n++)
            #pragma unroll
            for (int q = 0; q < 4; q++) c[n][q] = 0.f;

        #pragma unroll
        for (int ks = 0; ks < 8; ks++) {
            #pragma unroll
            for (int h = 0; h < 7; h++) {
                uint32_t b[4];
                uint32_t bd = bK + (uint32_t)(((h * 16 + (lane & 7) + ((lane >> 4) << 3)) * FA_ST
                                              + ks * 16 + (((lane >> 3) & 1) << 3)) * 2);
                ldsm4(b[0], b[1], b[2], b[3], bd);
                mma16816(c[2 * h], qa[ks], b);
                mma16816(c[2 * h + 1], qa[ks], b + 2);
            }
        }

        #pragma unroll
        for (int n = 0; n < 14; n++)
            #pragma unroll
            for (int q = 0; q < 4; q++) c[n][q] *= SC2;

        if (kt == NKT - 1) {
            #pragma unroll
            for (int n = 0; n < 14; n++) {
                #pragma unroll
                for (int e = 0; e < 2; e++) {
                    int j = (NKT - 1) * FA_KT + n * 8 + 2 * t + e;
                    if (j >= nk) { c[n][e] = -1e30f; c[n][e + 2] = -1e30f; }
                }
            }
        }

        float r0 = -1e30f, r1 = -1e30f;
        #pragma unroll
        for (int n = 0; n < 14; n++) {
            r0 = fmaxf(r0, fmaxf(c[n][0], c[n][1]));
            r1 = fmaxf(r1, fmaxf(c[n][2], c[n][3]));
        }
        r0 = fmaxf(r0, __shfl_xor_sync(0xffffffffu, r0, 1));
        r0 = fmaxf(r0, __shfl_xor_sync(0xffffffffu, r0, 2));
        r1 = fmaxf(r1, __shfl_xor_sync(0xffffffffu, r1, 1));
        r1 = fmaxf(r1, __shfl_xor_sync(0xffffffffu, r1, 2));
        float mn0 = fmaxf(m0, r0), mn1 = fmaxf(m1, r1);
        float sc0 = ex2f(m0 - mn0), sc1 = ex2f(m1 - mn1);
        m0 = mn0; m1 = mn1;
        float s0 = 0.f, s1 = 0.f;
        #pragma unroll
        for (int n = 0; n < 14; n++) {
            c[n][0] = ex2f(c[n][0] - mn0);
            c[n][1] = ex2f(c[n][1] - mn0);
            c[n][2] = ex2f(c[n][2] - mn1);
            c[n][3] = ex2f(c[n][3] - mn1);
            s0 += c[n][0] + c[n][1];
            s1 += c[n][2] + c[n][3];
        }
        s0 += __shfl_xor_sync(0xffffffffu, s0, 1);
        s0 += __shfl_xor_sync(0xffffffffu, s0, 2);
        s1 += __shfl_xor_sync(0xffffffffu, s1, 1);
        s1 += __shfl_xor_sync(0xffffffffu, s1, 2);
        l0 = l0 * sc0 + s0;
        l1 = l1 * sc1 + s1;
        #pragma unroll
        for (int i = 0; i < 16; i++) {
            o[i][0] *= sc0; o[i][1] *= sc0;
            o[i][2] *= sc1; o[i][3] *= sc1;
        }

        #pragma unroll
        for (int kk = 0; kk < 7; kk++) {
            uint32_t a[4];
            a[0] = packbf(c[2 * kk][0], c[2 * kk][1]);
            a[1] = packbf(c[2 * kk][2], c[2 * kk][3]);
            a[2] = packbf(c[2 * kk + 1][0], c[2 * kk + 1][1]);
            a[3] = packbf(c[2 * kk + 1][2], c[2 * kk + 1][3]);
            #pragma unroll
            for (int h = 0; h < 8; h++) {
                uint32_t b[4];
                uint32_t bd = bV + (uint32_t)(((kk * 16 + (lane & 7) + (((lane >> 3) & 1) << 3)) * FA_ST
                                              + h * 16 + ((lane >> 4) << 3)) * 2);
                ldsm4t(b[0], b[1], b[2], b[3], bd);
                mma16816(o[2 * h], a, b);
                mma16816(o[2 * h + 1], a, b + 2);
            }
        }
        __syncthreads();
    }

    float il0 = 1.f / l0, il1 = 1.f / l1;
    int q0 = mtile * 128 + wp * 16 + g;
    #pragma unroll
    for (int h = 0; h < 16; h++) {
        int col = hoff + h * 8 + 2 * t;
        if (q0 < 360) {
            bf162 v = __floats2bfloat162_rn(o[h][0] * il0, o[h][1] * il0);
            *(bf162*)(Og + ((long long)win * 360 + q0) * 512 + col) = v;
        }
        if (q0 + 8 < 360) {
            bf162 v = __floats2bfloat162_rn(o[h][2] * il1, o[h][3] * il1);
            *(bf162*)(Og + ((long long)win * 360 + q0 + 8) * 512 + col) = v;
        }
    }
}

// ---------------- bf16 GEMM: BM=128, BN=128, BK=64, 3-stage, optional row-scatter ----------
constexpr int GBM = 128, GBN = 128, GBK = 64;
constexpr int GAST = GBK + 8;    // 72
constexpr int GBST = GBN + 8;    // 136
constexpr int GASZ = GBM * GAST; // 9216
constexpr int GBSZ = GBK * GBST; // 8704

template <typename OutT>
__global__ __launch_bounds__(256, 2) void tgemm_k(
    const bf16* __restrict__ A, const bf16* __restrict__ Bm,
    const float* __restrict__ bias, const float* __restrict__ res,
    OutT* __restrict__ Cm, int M, int N, int K,
    const int* __restrict__ scat) {
    extern __shared__ bf16 smem[];
    bf16* As = smem;
    bf16* Bs = smem + 3 * GASZ;

    int tid = threadIdx.x;
    int row0 = blockIdx.y * GBM, col0 = blockIdx.x * GBN;
    int wid = tid >> 5, lane = tid & 31;
    int wm = wid & 3, wn = wid >> 2;
    int g = lane >> 2, t = lane & 3;

    uint32_t sA0 = (uint32_t)__cvta_generic_to_shared(As);
    uint32_t sB0 = (uint32_t)__cvta_generic_to_shared(Bs);
    int ktiles = (K + GBK - 1) / GBK;

    auto load_tile = [&](int stage, int k0) {
        #pragma unroll
        for (int i = 0; i < 4; i++) {
            int idx = tid + i * 256;
            int r = idx >> 3, kc = (idx & 7) << 3;
            bool ok = (k0 + kc) < K;
            cpasync16(sA0 + (uint32_t)((stage * GASZ + r * GAST + kc) * 2),
                      A + (long long)(row0 + r) * K + k0 + kc, ok);
        }
        #pragma unroll
        for (int i = 0; i < 4; i++) {
            int idx = tid + i * 256;
            int kk = idx >> 4, nc = (idx & 15) << 3;
            int gn = col0 + nc;
            bool ok = ((k0 + kk) < K) && (gn < N);
            cpasync16(sB0 + (uint32_t)((stage * GBSZ + kk * GBST + nc) * 2),
                      Bm + (long long)(k0 + kk) * N + gn, ok);
        }
    };

    float acc[2][8][4];
    #pragma unroll
    for (int mi = 0; mi < 2; mi++)
        #pragma unroll
        for (int ni = 0; ni < 8; ni++)
            #pragma unroll
            for (int q = 0; q < 4; q++) acc[mi][ni][q] = 0.f;

    load_tile(0, 0);
    asm volatile("cp.async.commit_group;\n");
    load_tile(1, GBK);
    asm volatile("cp.async.commit_group;\n");

    for (int kt = 0; kt < ktiles; kt++) {
        asm volatile("cp.async.wait_group %0;\n" :: "n"(1));
        __syncthreads();
        if (kt + 2 < ktiles) load_tile((kt + 2) % 3, (kt + 2) * GBK);
        asm volatile("cp.async.commit_group;\n");

        uint32_t sAb = sA0 + (uint32_t)((kt % 3) * GASZ * 2);
        uint32_t sBb = sB0 + (uint32_t)((kt % 3) * GBSZ * 2);

        #pragma unroll
        for (int ks = 0; ks < 4; ks++) {
            uint32_t a[2][4], b[8][2];
            #pragma unroll
            for (int mi = 0; mi < 2; mi++) {
                int row = wm * 32 + mi * 16 + (lane & 15);
                uint32_t ad = sAb + (uint32_t)((row * GAST + ks * 16 + ((lane >> 4) << 3)) * 2);
                ldsm4(a[mi][0], a[mi][1], a[mi][2], a[mi][3], ad);
            }
            #pragma unroll
            for (int h = 0; h < 4; h++) {
                int rowk = ks * 16 + (lane & 7) + (((lane >> 3) & 1) << 3);
                int coln = wn * 64 + h * 16 + ((lane >> 4) << 3);
                uint32_t bd = sBb + (uint32_t)((rowk * GBST + coln) * 2);
                ldsm4t(b[2 * h][0], b[2 * h][1], b[2 * h + 1][0], b[2 * h + 1][1], bd);
            }
            #pragma unroll
            for (int mi = 0; mi < 2; mi++)
                #pragma unroll
                for (int ni = 0; ni < 8; ni++)
                    mma16816(acc[mi][ni], a[mi], b[ni]);
        }
    }

    #pragma unroll
    for (int mi = 0; mi < 2; mi++) {
        int r = row0 + wm * 32 + mi * 16 + g;
        int ra = scat ? __ldg(scat + r) : r;
        int rb = scat ? __ldg(scat + r + 8) : r + 8;
        #pragma unroll
        for (int ni = 0; ni < 8; ni++) {
            int cidx = col0 + wn * 64 + ni * 8 + 2 * t;
            if (cidx < N) {
                float b0 = bias ? bias[cidx] : 0.f;
                float b1 = bias ? bias[cidx + 1] : 0.f;
                float x0 = acc[mi][ni][0] + b0, x1 = acc[mi][ni][1] + b1;
                float x2 = acc[mi][ni][2] + b0, x3 = acc[mi][ni][3] + b1;
                long long i0 = (long long)ra * N + cidx;
                long long i1 = (long long)rb * N + cidx;
                if (res) {
                    float2 r0 = *(const float2*)(res + i0);
                    float2 r1 = *(const float2*)(res + i1);
                    x0 += r0.x; x1 += r0.y; x2 += r1.x; x3 += r1.y;
                }
                store2(Cm + i0, x0, x1);
                store2(Cm + i1, x2, x3);
            }
        }
    }
}

// ---------------- T2T fold (gather form, bf16 in) + normalize ----------------
__global__ __launch_bounds__(256) void t2tfold_k(const bf16* __restrict__ h1,
                                                 float* __restrict__ I) {
    int idx = blockIdx.x * 256 + threadIdx.x;
    if (idx >= 16 * 40 * 60 * 108) return;
    int x = idx % 108;
    int y = (idx / 108) % 60;
    int c40 = (idx / (108 * 60)) % 40;
    int g = idx / (108 * 60 * 40);
    int pys[3], kis[3], pxs[3], kjs[3];
    int cy = 0, cx = 0;
    #pragma unroll
    for (int dp = 0; dp < 3; dp++) {
        int py = (y + 3) / 3 - dp;
        int ki = y + 3 - 3 * py;
        if (py >= 0 && py < 20 && ki < 7) { pys[cy] = py; kis[cy] = ki; cy++; }
        int px = (x + 3) / 3 - dp;
        int kj = x + 3 - 3 * px;
        if (px >= 0 && px < 36 && kj < 7) { pxs[cx] = px; kjs[cx] = kj; cx++; }
    }
    float s = 0.f;
    for (int a = 0; a < cy; a++)
        for (int bb = 0; bb < cx; bb++) {
            long long r = (long long)g * 720 + pys[a] * 36 + pxs[bb];
            s += __bfloat162float(h1[r * 1960 + c40 * 49 + kis[a] * 7 + kjs[bb]]);
        }
    I[idx] = s / (float)(cy * cx);
}

// ---------------- T2T unfold + exact GELU (paired bf162 out) ----------------
__global__ __launch_bounds__(256) void t2tunf_k(const float* __restrict__ I,
                                                bf16* __restrict__ h2) {
    int idx2 = blockIdx.x * 256 + threadIdx.x;
    if (idx2 >= TOK * FFN / 2) return;
    float vv[2];
    #pragma unroll
    for (int e = 0; e < 2; e++) {
        int idx = 2 * idx2 + e;
        int c = idx % 1960;
        int r = idx / 1960;
        int g = r / 720;
        int p = r - g * 720;
        int py = p / 36, px = p - py * 36;
        int c40 = c / 49;
        int kk = c - c40 * 49;
        int ki = kk / 7, kj = kk - ki * 7;
        int y = py * 3 + ki - 3, x = px * 3 + kj - 3;
        float v = 0.f;
        if (y >= 0 && y < 60 && x >= 0 && x < 108)
            v = I[(((long long)g * 40 + c40) * 60 + y) * 108 + x];
        vv[e] = 0.5f * v * (1.f + erff(v * 0.7071067811865475f));
    }
    ((bf162*)h2)[idx2] = __floats2bfloat162_rn(vv[0], vv[1]);
}

// ---------------- host launch ----------------
#define SYM(T, p, s) T* p; do { void* _t = nullptr; cudaGetSymbolAddress(&_t, s); (p) = (T*)_t; } while (0)

template <typename OutT>
static void run_tgemm(const bf16* A, const bf16* Bm, const float* bias,
                      const float* res, OutT* C, int M, int N, int K,
                      const int* scat = nullptr) {
    dim3 grid((N + GBN - 1) / GBN, M / GBM);
    size_t sm = (size_t)3 * (GASZ + GBSZ) * sizeof(bf16);
    cudaFuncSetAttribute(tgemm_k<OutT>, cudaFuncAttributeMaxDynamicSharedMemorySize, (int)sm);
    tgemm_k<OutT><<<grid, 256, sm>>>(A, Bm, bias, res, C, M, N, K, scat);
}

extern "C" void kernel_launch(void* const* d_in, const int* in_sizes, int n_in,
                              void* d_out, int out_size) {
    const float* x     = (const float*)d_in[0];
    const float* g1    = (const float*)d_in[1];
    const float* be1   = (const float*)d_in[2];
    const float* wqkv  = (const float*)d_in[3];
    const float* bqkv  = (const float*)d_in[4];
    const float* wproj = (const float*)d_in[5];
    const float* bproj = (const float*)d_in[6];
    const float* wpool = (const float*)d_in[7];
    const float* bpool = (const float*)d_in[8];
    const float* g2    = (const float*)d_in[9];
    const float* be2   = (const float*)d_in[10];
    const float* w1    = (const float*)d_in[11];
    const float* bf1   = (const float*)d_in[12];
    const float* w2    = (const float*)d_in[13];
    const float* bf2   = (const float*)d_in[14];
    float* out = (float*)d_out;

    SYM(bf16, xn, g_xn); SYM(bf16, qkv, g_qkv); SYM(bf16, pooled, g_pooled);
    SYM(bf16, qkvp, g_qkvp); SYM(bf16, Aw, g_Aw);
    SYM(float, xres, g_xres); SYM(bf16, hb, g_hb); SYM(float, I, g_I);
    SYM(int, qidx, g_qidx); SYM(int, kidx, g_kidx);
    SYM(bf16, wb, g_wb);
    bf16* wqkvb  = wb;
    bf16* wprojb = wb + WO_PROJ;
    bf16* w1b    = wb + WO_W1;
    bf16* w2b    = wb + WO_W2;

    initvalid_k<<<1, 32>>>();
    idx_k<<<(NWIN * NKP + 255) / 256, 256>>>(qidx, kidx);
    convw_all<<<(WTOT + 255) / 256, 256>>>(wqkv, wproj, w1, w2, wb);

    ln_k<<<TOK / 8, 256>>>(x, g1, be1, xn);
    run_tgemm<bf16>(xn, wqkvb, bqkv, nullptr, qkv, TOK, 1536, 512);
    pool_k<<<256, 128>>>(xn, wpool, bpool, pooled);
    run_tgemm<bf16>(pooled, wqkvb, bqkv, nullptr, qkvp, 256, 1536, 512);

    {
        size_t smfa = (size_t)4 * FA_KT * FA_ST * sizeof(bf16);
        cudaFuncSetAttribute(fattn_k, cudaFuncAttributeMaxDynamicSharedMemorySize, (int)smfa);
        fattn_k<<<dim3(3, 128), 256, smfa>>>(qkv, qkvp, qidx, kidx, Aw);
    }

    // proj GEMM with fused scatter + residual: xres[tok] = x[tok] + proj(Aw)[row]
    run_tgemm<float>(Aw, wprojb, bproj, x, xres, TOK, 512, 512, qidx);
    ln_k<<<TOK / 8, 256>>>(xres, g2, be2, xn);
    run_tgemm<bf16>(xn, w1b, bf1, nullptr, hb, TOK, FFN, 512);
    t2tfold_k<<<(16 * 40 * 60 * 108 + 255) / 256, 256>>>(hb, I);
    t2tunf_k<<<(TOK * FFN / 2 + 255) / 256, 256>>>(I, hb);
    run_tgemm<float>(hb, w2b, bf2, xres, out, TOK, 512, FFN);
}

// round 10
// speedup vs baseline: 9.5697x; 1.0219x over previous
#include <cuda_runtime.h>
#include <cuda_bf16.h>
#include <math.h>
#include <stdint.h>

// ---------------- constants ----------------
constexpr int NWIN = 32;
constexpr int NQ = 360;
constexpr int NKP = 1456;          // compacted+padded keys = 13 * 112
constexpr int NKT = 13;            // key tiles
constexpr int TOK = 11520;
constexpr int MTOT = TOK + 256;    // tokens + pooled rows (11776 = 92*128)
constexpr int FFN = 1960;
constexpr int Cch = 512;
constexpr float SC2 = 0.08838834764831845f * 1.4426950408889634f; // qscale * log2(e)

typedef __nv_bfloat16 bf16;
typedef __nv_bfloat162 bf162;

// ---------------- scratch ----------------
__device__ bf16  g_xn[MTOT * Cch];          // LN out rows 0..TOK-1, pooled rows TOK..
__device__ bf16  g_qkv[MTOT * 3 * Cch];     // merged qkv (incl pooled rows)
__device__ bf16  g_Aw[TOK * Cch];
__device__ float g_xres[TOK * Cch];
__device__ bf16  g_hb[TOK * FFN];           // h1 (pre-fold) then h2 (post-GELU)
__device__ float g_I[16 * 40 * 60 * 108];
__device__ int   g_valid[120];
__device__ int   g_qidx[NWIN * NQ];
__device__ int   g_kidx[NWIN * NKP];
__device__ bf16  g_wb[3055616];             // qkv | proj | w1 | w2 (bf16)
constexpr int WO_PROJ = 786432;
constexpr int WO_W1   = 1048576;
constexpr int WO_W2   = 2052096;
constexpr int WTOT    = 3055616;

// ---------------- init valid-rolled table ----------------
__global__ void initvalid_k() {
    if (threadIdx.x == 0 && blockIdx.x == 0) {
        int n = 0;
        for (int s = 0; s < 4; s++)
            for (int ih = 0; ih < 5; ih++)
                for (int iw = 0; iw < 9; iw++) {
                    bool zero;
                    if (s == 0) zero = (ih < 3 && iw < 5);
                    else if (s == 1) zero = (ih < 3 && iw >= 4);
                    else if (s == 2) zero = (ih >= 2 && iw < 5);
                    else zero = (ih >= 2 && iw >= 4);
                    if (!zero) g_valid[n++] = s * 45 + ih * 9 + iw;
                }
    }
}

// ---------------- build gather index tables (compacted pooled keys) ----------------
__global__ __launch_bounds__(256) void idx_k(int* __restrict__ qidx,
                                             int* __restrict__ kidx) {
    int i = blockIdx.x * 256 + threadIdx.x;
    if (i < NWIN * NQ) {
        int win = i / NQ, q = i - win * NQ;
        int b = win >> 4, wh = (win >> 2) & 3, ww = win & 3;
        int t = q / 45, a = q - t * 45, ih = a / 9, iw = a % 9;
        qidx[i] = ((b * 8 + t) * 20 + wh * 5 + ih) * 36 + ww * 9 + iw;
    }
    if (i < NWIN * NKP) {
        int win = i / NKP, j = i - win * NKP;
        int b = win >> 4, wh = (win >> 2) & 3, ww = win & 3;
        int e = -1;
        if (j < 360) {
            int t = j / 45, a = j - t * 45, ih = a / 9, iw = a % 9;
            e = ((b * 8 + t) * 20 + wh * 5 + ih) * 36 + ww * 9 + iw;
        } else if (j < 1320) {
            int jj = j - 360;
            int t = jj / 120, vi = jj - t * 120;
            int f = g_valid[vi];
            int s = f / 45, a = f - s * 45, ih = a / 9, iw = a % 9;
            int sh = (s < 2) ? -2 : 2;
            int sw = (s & 1) ? 4 : -4;
            int hh = wh * 5 + ih - sh; hh %= 20; if (hh < 0) hh += 20;
            int wp = ww * 9 + iw - sw; wp %= 36; if (wp < 0) wp += 36;
            e = ((b * 8 + t) * 20 + hh) * 36 + wp;
        } else {
            int pos = j - 1320;
            int i0 = (2 - wh) > 0 ? (2 - wh) : 0;
            int iend = (6 - wh) < 5 ? (6 - wh) : 5;
            int rows = iend - i0;
            int nv = rows * 4;
            if (pos < nv * 8) {
                int t = pos / nv, r = pos - t * nv;
                int di = r >> 2, dj = r & 3;
                int gi = wh + (i0 + di) - 2;
                int gj = dj;
                e = TOK + (b * 8 + t) * 16 + gi * 4 + gj;
            }
        }
        kidx[i] = e;
    }
}

// ---------------- all weights fp32 -> bf16 (vectorized, single launch) ----------------
__global__ __launch_bounds__(256) void convw_all(const float* __restrict__ a,
                                                 const float* __restrict__ b,
                                                 const float* __restrict__ c,
                                                 const float* __restrict__ d,
                                                 bf16* __restrict__ o) {
    int i4 = (blockIdx.x * 256 + threadIdx.x) * 4;
    if (i4 >= WTOT) return;
    const float* src;
    int off;
    if (i4 < WO_PROJ)      { src = a; off = i4; }
    else if (i4 < WO_W1)   { src = b; off = i4 - WO_PROJ; }
    else if (i4 < WO_W2)   { src = c; off = i4 - WO_W1; }
    else                   { src = d; off = i4 - WO_W2; }
    float4 v = *(const float4*)(src + off);
    *(bf162*)(o + i4)     = __floats2bfloat162_rn(v.x, v.y);
    *(bf162*)(o + i4 + 2) = __floats2bfloat162_rn(v.z, v.w);
}

// ---------------- LayerNorm: 2 rows per warp (independent chains) ----------------
__global__ __launch_bounds__(256) void ln_k(const float* __restrict__ in,
                                            const float* __restrict__ g,
                                            const float* __restrict__ b,
                                            bf16* __restrict__ out) {
    int warp = threadIdx.x >> 5, lane = threadIdx.x & 31;
    int row0 = blockIdx.x * 16 + warp * 2;
    const float4* x0 = (const float4*)(in + (long long)row0 * 512);
    const float4* x1 = (const float4*)(in + (long long)(row0 + 1) * 512);
    float4 v0[4], v1[4];
    float s0 = 0.f, s1 = 0.f;
    #pragma unroll
    for (int i = 0; i < 4; i++) {
        v0[i] = x0[lane + 32 * i];
        v1[i] = x1[lane + 32 * i];
        s0 += v0[i].x + v0[i].y + v0[i].z + v0[i].w;
        s1 += v1[i].x + v1[i].y + v1[i].z + v1[i].w;
    }
    #pragma unroll
    for (int o = 16; o; o >>= 1) {
        s0 += __shfl_xor_sync(0xffffffffu, s0, o);
        s1 += __shfl_xor_sync(0xffffffffu, s1, o);
    }
    float mu0 = s0 * (1.f / 512.f), mu1 = s1 * (1.f / 512.f);
    float q0 = 0.f, q1 = 0.f;
    #pragma unroll
    for (int i = 0; i < 4; i++) {
        float a0 = v0[i].x - mu0, b0 = v0[i].y - mu0, c0 = v0[i].z - mu0, d0 = v0[i].w - mu0;
        float a1 = v1[i].x - mu1, b1 = v1[i].y - mu1, c1 = v1[i].z - mu1, d1 = v1[i].w - mu1;
        q0 += a0 * a0 + b0 * b0 + c0 * c0 + d0 * d0;
        q1 += a1 * a1 + b1 * b1 + c1 * c1 + d1 * d1;
    }
    #pragma unroll
    for (int o = 16; o; o >>= 1) {
        q0 += __shfl_xor_sync(0xffffffffu, q0, o);
        q1 += __shfl_xor_sync(0xffffffffu, q1, o);
    }
    float inv0 = rsqrtf(q0 * (1.f / 512.f) + 1e-5f);
    float inv1 = rsqrtf(q1 * (1.f / 512.f) + 1e-5f);
    bf162* o0p = (bf162*)(out + (long long)row0 * 512);
    bf162* o1p = (bf162*)(out + (long long)(row0 + 1) * 512);
    #pragma unroll
    for (int i = 0; i < 4; i++) {
        float4 gg = ((const float4*)g)[lane + 32 * i];
        float4 bb = ((const float4*)b)[lane + 32 * i];
        o0p[2 * (lane + 32 * i)] =
            __floats2bfloat162_rn((v0[i].x - mu0) * inv0 * gg.x + bb.x,
                                  (v0[i].y - mu0) * inv0 * gg.y + bb.y);
        o0p[2 * (lane + 32 * i) + 1] =
            __floats2bfloat162_rn((v0[i].z - mu0) * inv0 * gg.z + bb.z,
                                  (v0[i].w - mu0) * inv0 * gg.w + bb.w);
        o1p[2 * (lane + 32 * i)] =
            __floats2bfloat162_rn((v1[i].x - mu1) * inv1 * gg.x + bb.x,
                                  (v1[i].y - mu1) * inv1 * gg.y + bb.y);
        o1p[2 * (lane + 32 * i) + 1] =
            __floats2bfloat162_rn((v1[i].z - mu1) * inv1 * gg.z + bb.z,
                                  (v1[i].w - mu1) * inv1 * gg.w + bb.w);
    }
}

// ---------------- window pooling -> rows TOK.. of xn buffer ----------------
__global__ __launch_bounds__(128) void pool_k(const bf16* __restrict__ xn,
                                              const float* __restrict__ wpool,
                                              const float* __restrict__ bpool,
                                              bf16* __restrict__ pooled) {
    int widx = blockIdx.x;                 // 256 windows
    int ww = widx & 3, wh = (widx >> 2) & 3, bt = widx >> 4;
    int tid = threadIdx.x;
    float a0 = 0.f, a1 = 0.f, a2 = 0.f, a3 = 0.f;
    #pragma unroll
    for (int a = 0; a < 45; a++) {
        int ih = a / 9, iw = a % 9;
        long long tok = ((long long)bt * 20 + wh * 5 + ih) * 36 + ww * 9 + iw;
        uint2 u = *(const uint2*)(xn + tok * 512 + tid * 4);
        float2 f0 = __bfloat1622float2(*(bf162*)&u.x);
        float2 f1 = __bfloat1622float2(*(bf162*)&u.y);
        float w = wpool[a];
        a0 += f0.x * w; a1 += f0.y * w; a2 += f1.x * w; a3 += f1.y * w;
    }
    float bp = bpool[0];
    bf162* dst = (bf162*)(pooled + (long long)widx * 512 + tid * 4);
    dst[0] = __floats2bfloat162_rn(a0 + bp, a1 + bp);
    dst[1] = __floats2bfloat162_rn(a2 + bp, a3 + bp);
}

// ---------------- common PTX helpers ----------------
__device__ __forceinline__ void cpasync16(uint32_t saddr, const void* gaddr, bool pred) {
    int sz = pred ? 16 : 0;
    asm volatile("cp.async.cg.shared.global [%0], [%1], 16, %2;\n"
                 :: "r"(saddr), "l"(gaddr), "r"(sz));
}
__device__ __forceinline__ void ldsm4(uint32_t& r0, uint32_t& r1, uint32_t& r2, uint32_t& r3,
                                      uint32_t a) {
    asm volatile("ldmatrix.sync.aligned.m8n8.x4.shared.b16 {%0,%1,%2,%3}, [%4];\n"
                 : "=r"(r0), "=r"(r1), "=r"(r2), "=r"(r3) : "r"(a));
}
__device__ __forceinline__ void ldsm4t(uint32_t& r0, uint32_t& r1, uint32_t& r2, uint32_t& r3,
                                       uint32_t a) {
    asm volatile("ldmatrix.sync.aligned.m8n8.x4.trans.shared.b16 {%0,%1,%2,%3}, [%4];\n"
                 : "=r"(r0), "=r"(r1), "=r"(r2), "=r"(r3) : "r"(a));
}
__device__ __forceinline__ void mma16816(float* c, const uint32_t* a, const uint32_t* b) {
    asm volatile(
        "mma.sync.aligned.m16n8k16.row.col.f32.bf16.bf16.f32 "
        "{%0,%1,%2,%3}, {%4,%5,%6,%7}, {%8,%9}, {%0,%1,%2,%3};\n"
        : "+f"(c[0]), "+f"(c[1]), "+f"(c[2]), "+f"(c[3])
        : "r"(a[0]), "r"(a[1]), "r"(a[2]), "r"(a[3]), "r"(b[0]), "r"(b[1]));
}
__device__ __forceinline__ uint32_t packbf(float x, float y) {
    bf162 h = __floats2bfloat162_rn(x, y);
    return *(uint32_t*)&h;
}
__device__ __forceinline__ float ex2f(float x) {
    float r;
    asm("ex2.approx.f32 %0, %1;" : "=f"(r) : "f"(x));
    return r;
}
__device__ __forceinline__ void store2(float* p, float x, float y) {
    *(float2*)p = make_float2(x, y);
}
__device__ __forceinline__ void store2(bf16* p, float x, float y) {
    *(bf162*)p = __floats2bfloat162_rn(x, y);
}

// ---------------- fused flash attention (single merged qkv buffer) ----------------
constexpr int FA_KT = 112;
constexpr int FA_ST = 136;

__global__ __launch_bounds__(256, 1) void fattn_k(const bf16* __restrict__ qkv,
                                                  const int* __restrict__ qidx,
                                                  const int* __restrict__ kidx,
                                                  bf16* __restrict__ Og) {
    int mtile = blockIdx.x;
    int zy = blockIdx.y;
    int win = zy >> 2, head = zy & 3;
    int wl = win & 15;
    int mwh = wl >> 2;
    int nk = 1320 + (((mwh == 0) || (mwh == 3)) ? 12 : 16) * 8;

    extern __shared__ bf16 sm[];
    bf16* Ks = sm;
    bf16* Vs = sm + 2 * FA_KT * FA_ST;
    uint32_t sK = (uint32_t)__cvta_generic_to_shared(Ks);
    uint32_t sV = (uint32_t)__cvta_generic_to_shared(Vs);

    int tid = threadIdx.x, wp = tid >> 5, lane = tid & 31;
    int g = lane >> 2, t = lane & 3;
    int hoff = head * 128;

    // ---- load Q tile ----
    #pragma unroll
    for (int i = 0; i < 8; i++) {
        int idx = tid + i * 256;
        int r = idx >> 4, c = (idx & 15) << 3;
        int q = mtile * 128 + r;
        bool ok = q < 360;
        int e = ok ? __ldg(qidx + win * 360 + q) : 0;
        cpasync16(sK + (uint32_t)((r * FA_ST + c) * 2),
                  qkv + (long long)e * 1536 + hoff + c, ok);
    }
    asm volatile("cp.async.commit_group;\n");
    asm volatile("cp.async.wait_group 0;\n");
    __syncthreads();
    uint32_t qa[8][4];
    #pragma unroll
    for (int ks = 0; ks < 8; ks++) {
        uint32_t ad = sK + (uint32_t)((((wp << 4) + (lane & 15)) * FA_ST
                                       + ks * 16 + ((lane >> 4) << 3)) * 2);
        ldsm4(qa[ks][0], qa[ks][1], qa[ks][2], qa[ks][3], ad);
    }
    __syncthreads();

    auto loadKV = [&](int stage, int kt) {
        #pragma unroll
        for (int i = 0; i < 7; i++) {
            int idx = tid + i * 256;
            int r = idx >> 4, c = (idx & 15) << 3;
            int e = __ldg(kidx + win * NKP + kt * FA_KT + r);
            bool ok = e >= 0;
            const bf16* p = qkv + (long long)(ok ? e : 0) * 1536;
            uint32_t off = (uint32_t)((stage * FA_KT * FA_ST + r * FA_ST + c) * 2);
            cpasync16(sK + off, p + 512 + hoff + c, ok);
            cpasync16(sV + off, p + 1024 + hoff + c, ok);
        }
    };

    float m0 = -1e30f, m1 = -1e30f, l0 = 0.f, l1 = 0.f;
    float o[16][4];
    #pragma unroll
    for (int i = 0; i < 16; i++)
        #pragma unroll
        for (int q = 0; q < 4; q++) o[i][q] = 0.f;

    loadKV(0, 0);
    asm volatile("cp.async.commit_group;\n");

    for (int kt = 0; kt < NKT; kt++) {
        if (kt + 1 < NKT) loadKV((kt + 1) & 1, kt + 1);
        asm volatile("cp.async.commit_group;\n");
        asm volatile("cp.async.wait_group %0;\n" :: "n"(1));
        __syncthreads();

        uint32_t bK = sK + (uint32_t)((kt & 1) * FA_KT * FA_ST * 2);
        uint32_t bV = sV + (uint32_t)((kt & 1) * FA_KT * FA_ST * 2);

        float c[14][4];
        #pragma unroll
        for (int n = 0; n < 14; n++)
            #pragma unroll
            for (int q = 0; q < 4; q++) c[n][q] = 0.f;

        #pragma unroll
        for (int ks = 0; ks < 8; ks++) {
            #pragma unroll
            for (int h = 0; h < 7; h++) {
                uint32_t b[4];
                uint32_t bd = bK + (uint32_t)(((h * 16 + (lane & 7) + ((lane >> 4) << 3)) * FA_ST
                                              + ks * 16 + (((lane >> 3) & 1) << 3)) * 2);
                ldsm4(b[0], b[1], b[2], b[3], bd);
                mma16816(c[2 * h], qa[ks], b);
                mma16816(c[2 * h + 1], qa[ks], b + 2);
            }
        }

        #pragma unroll
        for (int n = 0; n < 14; n++)
            #pragma unroll
            for (int q = 0; q < 4; q++) c[n][q] *= SC2;

        if (kt == NKT - 1) {
            #pragma unroll
            for (int n = 0; n < 14; n++) {
                #pragma unroll
                for (int e = 0; e < 2; e++) {
                    int j = (NKT - 1) * FA_KT + n * 8 + 2 * t + e;
                    if (j >= nk) { c[n][e] = -1e30f; c[n][e + 2] = -1e30f; }
                }
            }
        }

        float r0 = -1e30f, r1 = -1e30f;
        #pragma unroll
        for (int n = 0; n < 14; n++) {
            r0 = fmaxf(r0, fmaxf(c[n][0], c[n][1]));
            r1 = fmaxf(r1, fmaxf(c[n][2], c[n][3]));
        }
        r0 = fmaxf(r0, __shfl_xor_sync(0xffffffffu, r0, 1));
        r0 = fmaxf(r0, __shfl_xor_sync(0xffffffffu, r0, 2));
        r1 = fmaxf(r1, __shfl_xor_sync(0xffffffffu, r1, 1));
        r1 = fmaxf(r1, __shfl_xor_sync(0xffffffffu, r1, 2));
        float mn0 = fmaxf(m0, r0), mn1 = fmaxf(m1, r1);
        float sc0 = ex2f(m0 - mn0), sc1 = ex2f(m1 - mn1);
        m0 = mn0; m1 = mn1;
        float s0 = 0.f, s1 = 0.f;
        #pragma unroll
        for (int n = 0; n < 14; n++) {
            c[n][0] = ex2f(c[n][0] - mn0);
            c[n][1] = ex2f(c[n][1] - mn0);
            c[n][2] = ex2f(c[n][2] - mn1);
            c[n][3] = ex2f(c[n][3] - mn1);
            s0 += c[n][0] + c[n][1];
            s1 += c[n][2] + c[n][3];
        }
        s0 += __shfl_xor_sync(0xffffffffu, s0, 1);
        s0 += __shfl_xor_sync(0xffffffffu, s0, 2);
        s1 += __shfl_xor_sync(0xffffffffu, s1, 1);
        s1 += __shfl_xor_sync(0xffffffffu, s1, 2);
        l0 = l0 * sc0 + s0;
        l1 = l1 * sc1 + s1;
        #pragma unroll
        for (int i = 0; i < 16; i++) {
            o[i][0] *= sc0; o[i][1] *= sc0;
            o[i][2] *= sc1; o[i][3] *= sc1;
        }

        #pragma unroll
        for (int kk = 0; kk < 7; kk++) {
            uint32_t a[4];
            a[0] = packbf(c[2 * kk][0], c[2 * kk][1]);
            a[1] = packbf(c[2 * kk][2], c[2 * kk][3]);
            a[2] = packbf(c[2 * kk + 1][0], c[2 * kk + 1][1]);
            a[3] = packbf(c[2 * kk + 1][2], c[2 * kk + 1][3]);
            #pragma unroll
            for (int h = 0; h < 8; h++) {
                uint32_t b[4];
                uint32_t bd = bV + (uint32_t)(((kk * 16 + (lane & 7) + (((lane >> 3) & 1) << 3)) * FA_ST
                                              + h * 16 + ((lane >> 4) << 3)) * 2);
                ldsm4t(b[0], b[1], b[2], b[3], bd);
                mma16816(o[2 * h], a, b);
                mma16816(o[2 * h + 1], a, b + 2);
            }
        }
        __syncthreads();
    }

    float il0 = 1.f / l0, il1 = 1.f / l1;
    int q0 = mtile * 128 + wp * 16 + g;
    #pragma unroll
    for (int h = 0; h < 16; h++) {
        int col = hoff + h * 8 + 2 * t;
        if (q0 < 360) {
            bf162 v = __floats2bfloat162_rn(o[h][0] * il0, o[h][1] * il0);
            *(bf162*)(Og + ((long long)win * 360 + q0) * 512 + col) = v;
        }
        if (q0 + 8 < 360) {
            bf162 v = __floats2bfloat162_rn(o[h][2] * il1, o[h][3] * il1);
            *(bf162*)(Og + ((long long)win * 360 + q0 + 8) * 512 + col) = v;
        }
    }
}

// ---------------- bf16 GEMM: BM template (128/64), BN=128, BK=64, 3-stage ----------
constexpr int GBN = 128, GBK = 64;
constexpr int GAST = GBK + 8;    // 72
constexpr int GBST = GBN + 8;    // 136
constexpr int GBSZ = GBK * GBST; // 8704

template <typename OutT, int BMT>
__global__ __launch_bounds__(256, 2) void tgemm_k(
    const bf16* __restrict__ A, const bf16* __restrict__ Bm,
    const float* __restrict__ bias, const float* __restrict__ res,
    OutT* __restrict__ Cm, int M, int N, int K,
    const int* __restrict__ scat) {
    constexpr int GASZ = BMT * GAST;
    constexpr int MI = BMT / 64;          // 2 or 1
    constexpr int ALOAD = BMT / 32;       // 4 or 2
    extern __shared__ bf16 smem[];
    bf16* As = smem;
    bf16* Bs = smem + 3 * GASZ;

    int tid = threadIdx.x;
    int row0 = blockIdx.y * BMT, col0 = blockIdx.x * GBN;
    int wid = tid >> 5, lane = tid & 31;
    int wm = wid & 3, wn = wid >> 2;
    int g = lane >> 2, t = lane & 3;

    uint32_t sA0 = (uint32_t)__cvta_generic_to_shared(As);
    uint32_t sB0 = (uint32_t)__cvta_generic_to_shared(Bs);
    int ktiles = (K + GBK - 1) / GBK;

    auto load_tile = [&](int stage, int k0) {
        #pragma unroll
        for (int i = 0; i < ALOAD; i++) {
            int idx = tid + i * 256;
            int r = idx >> 3, kc = (idx & 7) << 3;
            bool ok = (k0 + kc) < K;
            cpasync16(sA0 + (uint32_t)((stage * GASZ + r * GAST + kc) * 2),
                      A + (long long)(row0 + r) * K + k0 + kc, ok);
        }
        #pragma unroll
        for (int i = 0; i < 4; i++) {
            int idx = tid + i * 256;
            int kk = idx >> 4, nc = (idx & 15) << 3;
            int gn = col0 + nc;
            bool ok = ((k0 + kk) < K) && (gn < N);
            cpasync16(sB0 + (uint32_t)((stage * GBSZ + kk * GBST + nc) * 2),
                      Bm + (long long)(k0 + kk) * N + gn, ok);
        }
    };

    float acc[MI][8][4];
    #pragma unroll
    for (int mi = 0; mi < MI; mi++)
        #pragma unroll
        for (int ni = 0; ni < 8; ni++)
            #pragma unroll
            for (int q = 0; q < 4; q++) acc[mi][ni][q] = 0.f;

    load_tile(0, 0);
    asm volatile("cp.async.commit_group;\n");
    load_tile(1, GBK);
    asm volatile("cp.async.commit_group;\n");

    for (int kt = 0; kt < ktiles; kt++) {
        asm volatile("cp.async.wait_group %0;\n" :: "n"(1));
        __syncthreads();
        if (kt + 2 < ktiles) load_tile((kt + 2) % 3, (kt + 2) * GBK);
        asm volatile("cp.async.commit_group;\n");

        uint32_t sAb = sA0 + (uint32_t)((kt % 3) * GASZ * 2);
        uint32_t sBb = sB0 + (uint32_t)((kt % 3) * GBSZ * 2);

        #pragma unroll
        for (int ks = 0; ks < 4; ks++) {
            uint32_t a[MI][4], b[8][2];
            #pragma unroll
            for (int mi = 0; mi < MI; mi++) {
                int row = wm * (BMT / 4) + mi * 16 + (lane & 15);
                uint32_t ad = sAb + (uint32_t)((row * GAST + ks * 16 + ((lane >> 4) << 3)) * 2);
                ldsm4(a[mi][0], a[mi][1], a[mi][2], a[mi][3], ad);
            }
            #pragma unroll
            for (int h = 0; h < 4; h++) {
                int rowk = ks * 16 + (lane & 7) + (((lane >> 3) & 1) << 3);
                int coln = wn * 64 + h * 16 + ((lane >> 4) << 3);
                uint32_t bd = sBb + (uint32_t)((rowk * GBST + coln) * 2);
                ldsm4t(b[2 * h][0], b[2 * h][1], b[2 * h + 1][0], b[2 * h + 1][1], bd);
            }
            #pragma unroll
            for (int mi = 0; mi < MI; mi++)
                #pragma unroll
                for (int ni = 0; ni < 8; ni++)
                    mma16816(acc[mi][ni], a[mi], b[ni]);
        }
    }

    #pragma unroll
    for (int mi = 0; mi < MI; mi++) {
        int r = row0 + wm * (BMT / 4) + mi * 16 + g;
        int ra = scat ? __ldg(scat + r) : r;
        int rb = scat ? __ldg(scat + r + 8) : r + 8;
        #pragma unroll
        for (int ni = 0; ni < 8; ni++) {
            int cidx = col0 + wn * 64 + ni * 8 + 2 * t;
            if (cidx < N) {
                float b0 = bias ? bias[cidx] : 0.f;
                float b1 = bias ? bias[cidx + 1] : 0.f;
                float x0 = acc[mi][ni][0] + b0, x1 = acc[mi][ni][1] + b1;
                float x2 = acc[mi][ni][2] + b0, x3 = acc[mi][ni][3] + b1;
                long long i0 = (long long)ra * N + cidx;
                long long i1 = (long long)rb * N + cidx;
                if (res) {
                    float2 r0 = *(const float2*)(res + i0);
                    float2 r1 = *(const float2*)(res + i1);
                    x0 += r0.x; x1 += r0.y; x2 += r1.x; x3 += r1.y;
                }
                store2(Cm + i0, x0, x1);
                store2(Cm + i1, x2, x3);
            }
        }
    }
}

// ---------------- T2T fold (gather form, bf16 in) + normalize ----------------
__global__ __launch_bounds__(256) void t2tfold_k(const bf16* __restrict__ h1,
                                                 float* __restrict__ I) {
    int idx = blockIdx.x * 256 + threadIdx.x;
    if (idx >= 16 * 40 * 60 * 108) return;
    int x = idx % 108;
    int y = (idx / 108) % 60;
    int c40 = (idx / (108 * 60)) % 40;
    int g = idx / (108 * 60 * 40);
    int pys[3], kis[3], pxs[3], kjs[3];
    int cy = 0, cx = 0;
    #pragma unroll
    for (int dp = 0; dp < 3; dp++) {
        int py = (y + 3) / 3 - dp;
        int ki = y + 3 - 3 * py;
        if (py >= 0 && py < 20 && ki < 7) { pys[cy] = py; kis[cy] = ki; cy++; }
        int px = (x + 3) / 3 - dp;
        int kj = x + 3 - 3 * px;
        if (px >= 0 && px < 36 && kj < 7) { pxs[cx] = px; kjs[cx] = kj; cx++; }
    }
    float s = 0.f;
    for (int a = 0; a < cy; a++)
        for (int bb = 0; bb < cx; bb++) {
            long long r = (long long)g * 720 + pys[a] * 36 + pxs[bb];
            s += __bfloat162float(h1[r * 1960 + c40 * 49 + kis[a] * 7 + kjs[bb]]);
        }
    I[idx] = s / (float)(cy * cx);
}

// ---------------- T2T unfold + exact GELU (paired bf162 out) ----------------
__global__ __launch_bounds__(256) void t2tunf_k(const float* __restrict__ I,
                                                bf16* __restrict__ h2) {
    int idx2 = blockIdx.x * 256 + threadIdx.x;
    if (idx2 >= TOK * FFN / 2) return;
    float vv[2];
    #pragma unroll
    for (int e = 0; e < 2; e++) {
        int idx = 2 * idx2 + e;
        int c = idx % 1960;
        int r = idx / 1960;
        int g = r / 720;
        int p = r - g * 720;
        int py = p / 36, px = p - py * 36;
        int c40 = c / 49;
        int kk = c - c40 * 49;
        int ki = kk / 7, kj = kk - ki * 7;
        int y = py * 3 + ki - 3, x = px * 3 + kj - 3;
        float v = 0.f;
        if (y >= 0 && y < 60 && x >= 0 && x < 108)
            v = I[(((long long)g * 40 + c40) * 60 + y) * 108 + x];
        vv[e] = 0.5f * v * (1.f + erff(v * 0.7071067811865475f));
    }
    ((bf162*)h2)[idx2] = __floats2bfloat162_rn(vv[0], vv[1]);
}

// ---------------- host launch ----------------
#define SYM(T, p, s) T* p; do { void* _t = nullptr; cudaGetSymbolAddress(&_t, s); (p) = (T*)_t; } while (0)

template <typename OutT, int BMT>
static void run_tgemm(const bf16* A, const bf16* Bm, const float* bias,
                      const float* res, OutT* C, int M, int N, int K,
                      const int* scat = nullptr) {
    dim3 grid((N + GBN - 1) / GBN, M / BMT);
    size_t sm = (size_t)3 * (BMT * GAST + GBSZ) * sizeof(bf16);
    cudaFuncSetAttribute(tgemm_k<OutT, BMT>, cudaFuncAttributeMaxDynamicSharedMemorySize, (int)sm);
    tgemm_k<OutT, BMT><<<grid, 256, sm>>>(A, Bm, bias, res, C, M, N, K, scat);
}

extern "C" void kernel_launch(void* const* d_in, const int* in_sizes, int n_in,
                              void* d_out, int out_size) {
    const float* x     = (const float*)d_in[0];
    const float* g1    = (const float*)d_in[1];
    const float* be1   = (const float*)d_in[2];
    const float* wqkv  = (const float*)d_in[3];
    const float* bqkv  = (const float*)d_in[4];
    const float* wproj = (const float*)d_in[5];
    const float* bproj = (const float*)d_in[6];
    const float* wpool = (const float*)d_in[7];
    const float* bpool = (const float*)d_in[8];
    const float* g2    = (const float*)d_in[9];
    const float* be2   = (const float*)d_in[10];
    const float* w1    = (const float*)d_in[11];
    const float* bf1   = (const float*)d_in[12];
    const float* w2    = (const float*)d_in[13];
    const float* bf2   = (const float*)d_in[14];
    float* out = (float*)d_out;

    SYM(bf16, xn, g_xn); SYM(bf16, qkv, g_qkv); SYM(bf16, Aw, g_Aw);
    SYM(float, xres, g_xres); SYM(bf16, hb, g_hb); SYM(float, I, g_I);
    SYM(int, qidx, g_qidx); SYM(int, kidx, g_kidx);
    SYM(bf16, wb, g_wb);
    bf16* wqkvb  = wb;
    bf16* wprojb = wb + WO_PROJ;
    bf16* w1b    = wb + WO_W1;
    bf16* w2b    = wb + WO_W2;

    initvalid_k<<<1, 32>>>();
    idx_k<<<(NWIN * NKP + 255) / 256, 256>>>(qidx, kidx);
    convw_all<<<(WTOT / 4 + 255) / 256, 256>>>(wqkv, wproj, w1, w2, wb);

    ln_k<<<TOK / 16, 256>>>(x, g1, be1, xn);
    pool_k<<<256, 128>>>(xn, wpool, bpool, xn + (long long)TOK * 512);
    // merged QKV GEMM over tokens + pooled rows
    run_tgemm<bf16, 128>(xn, wqkvb, bqkv, nullptr, qkv, MTOT, 1536, 512);

    {
        size_t smfa = (size_t)4 * FA_KT * FA_ST * sizeof(bf16);
        cudaFuncSetAttribute(fattn_k, cudaFuncAttributeMaxDynamicSharedMemorySize, (int)smfa);
        fattn_k<<<dim3(3, 128), 256, smfa>>>(qkv, qidx, kidx, Aw);
    }

    // proj GEMM with fused scatter + residual (BM=64 for wave balance)
    run_tgemm<float, 64>(Aw, wprojb, bproj, x, xres, TOK, 512, 512, qidx);
    ln_k<<<TOK / 16, 256>>>(xres, g2, be2, xn);
    run_tgemm<bf16, 128>(xn, w1b, bf1, nullptr, hb, TOK, FFN, 512);
    t2tfold_k<<<(16 * 40 * 60 * 108 + 255) / 256, 256>>>(hb, I);
    t2tunf_k<<<(TOK * FFN / 2 + 255) / 256, 256>>>(I, hb);
    run_tgemm<float, 64>(hb, w2b, bf2, xres, out, TOK, 512, FFN);
}